// round 1
// baseline (speedup 1.0000x reference)
#include <cuda_runtime.h>
#include <math.h>

#define Bb   2
#define Tt   2048
#define Cc   1024
#define Hh   8
#define KVh  4
#define Dd   128
#define WINs 512
#define HIDm 4096
#define Mrows (Bb*Tt)   // 4096

// ---------------- scratch (static device globals; no allocation) ----------------
__device__ float g_h   [Mrows*Cc];        // rmsnorm output, reused
__device__ float g_q   [Mrows*Hh*Dd];     // 4096 x 1024
__device__ float g_k   [Mrows*KVh*Dd];    // 4096 x 512
__device__ float g_v   [Mrows*KVh*Dd];    // 4096 x 512
__device__ float g_attn[Mrows*Hh*Dd];     // 4096 x 1024
__device__ float g_x2  [Mrows*Cc];        // residual after attention
__device__ float g_gate[Mrows*HIDm];      // 4096 x 4096 (also holds swiglu act)
__device__ float g_up  [Mrows*HIDm];      // 4096 x 4096

// ---------------- rmsnorm: one block per row (C=1024, 256 thr, float4) ----------
__global__ void rmsnorm_kernel(const float* __restrict__ x,
                               const float* __restrict__ scale,
                               float* __restrict__ y)
{
    int row = blockIdx.x;
    const float4* xr = (const float4*)(x + (size_t)row * Cc);
    float4 v = xr[threadIdx.x];
    float ss = v.x*v.x + v.y*v.y + v.z*v.z + v.w*v.w;
    #pragma unroll
    for (int o = 16; o; o >>= 1) ss += __shfl_xor_sync(0xffffffffu, ss, o);
    __shared__ float wsum[8];
    if ((threadIdx.x & 31) == 0) wsum[threadIdx.x >> 5] = ss;
    __syncthreads();
    if (threadIdx.x < 8) {
        float t = wsum[threadIdx.x];
        #pragma unroll
        for (int o = 4; o; o >>= 1) t += __shfl_xor_sync(0xffu, t, o);
        if (threadIdx.x == 0) wsum[0] = t;
    }
    __syncthreads();
    float inv = rsqrtf(wsum[0] * (1.0f / Cc) + 1e-6f);
    float4 sc = ((const float4*)scale)[threadIdx.x];
    float4 o;
    o.x = v.x * inv * (1.f + sc.x);
    o.y = v.y * inv * (1.f + sc.y);
    o.z = v.z * inv * (1.f + sc.z);
    o.w = v.w * inv * (1.f + sc.w);
    ((float4*)(y + (size_t)row * Cc))[threadIdx.x] = o;
}

// ---------------- SGEMM: C[M,N] = A[M,K] @ B[K,N] (+ Res) -----------------------
// 128x128 tile, BK=8, 256 threads, 8x8 per thread, interleaved thread tiling.
__global__ __launch_bounds__(256) void sgemm_kernel(
    const float* __restrict__ A, const float* __restrict__ B,
    const float* __restrict__ Res, float* __restrict__ C,
    int M, int N, int K)
{
    __shared__ float As[128 * 8];     // [m][k] natural
    __shared__ float Bs[8 * 132];     // [k][n] natural, pad 132

    int tid = threadIdx.x;
    int tx = tid & 15, ty = tid >> 4;
    int m0 = blockIdx.y * 128, n0 = blockIdx.x * 128;

    int am = tid >> 1, ac = (tid & 1) * 4;       // A tile loader coords
    int bk = tid >> 5, bn = (tid & 31) * 4;      // B tile loader coords
    const float* Aptr = A + (size_t)(m0 + am) * K + ac;
    const float* Bptr = B + (size_t)bk * N + n0 + bn;

    float acc[8][8];
    #pragma unroll
    for (int i = 0; i < 8; i++)
        #pragma unroll
        for (int j = 0; j < 8; j++) acc[i][j] = 0.f;

    for (int kt = 0; kt < K; kt += 8) {
        float4 a4 = *(const float4*)(Aptr + kt);
        float4 b4 = *(const float4*)(Bptr + (size_t)kt * N);
        *(float4*)(As + am * 8 + ac) = a4;
        *(float4*)(Bs + bk * 132 + bn) = b4;
        __syncthreads();
        #pragma unroll
        for (int k = 0; k < 8; k++) {
            float a[8], b[8];
            #pragma unroll
            for (int i = 0; i < 8; i++) a[i] = As[(ty + 16 * i) * 8 + k];
            #pragma unroll
            for (int j = 0; j < 8; j++) b[j] = Bs[k * 132 + tx + 16 * j];
            #pragma unroll
            for (int i = 0; i < 8; i++)
                #pragma unroll
                for (int j = 0; j < 8; j++) acc[i][j] += a[i] * b[j];
        }
        __syncthreads();
    }

    #pragma unroll
    for (int i = 0; i < 8; i++) {
        int m = m0 + ty + 16 * i;
        #pragma unroll
        for (int j = 0; j < 8; j++) {
            int n = n0 + tx + 16 * j;
            float v = acc[i][j];
            if (Res) v += Res[(size_t)m * N + n];
            C[(size_t)m * N + n] = v;
        }
    }
}

// ---------------- RoPE on q (8 heads) and k (4 heads), in place -----------------
__global__ void rope_kernel(float* __restrict__ q, float* __restrict__ k)
{
    int row = blockIdx.x;           // b*T + t
    int t = row & (Tt - 1);
    __shared__ float s_sin[64], s_cos[64];
    if (threadIdx.x < 64) {
        float inv = expf(-logf(10000.0f) * (2.0f * threadIdx.x) / 128.0f);
        float ang = (float)t * inv;
        s_sin[threadIdx.x] = sinf(ang);
        s_cos[threadIdx.x] = cosf(ang);
    }
    __syncthreads();
    // q: 8 heads * 64 pairs = 512
    for (int p = threadIdx.x; p < 512; p += 256) {
        int head = p >> 6, i = p & 63;
        float* base = q + (size_t)row * 1024 + head * 128;
        float x1 = base[i], x2 = base[i + 64];
        float s = s_sin[i], c = s_cos[i];
        base[i]      = x1 * c - x2 * s;
        base[i + 64] = x2 * c + x1 * s;
    }
    // k: 4 heads * 64 pairs = 256
    for (int p = threadIdx.x; p < 256; p += 256) {
        int head = p >> 6, i = p & 63;
        float* base = k + (size_t)row * 512 + head * 128;
        float x1 = base[i], x2 = base[i + 64];
        float s = s_sin[i], c = s_cos[i];
        base[i]      = x1 * c - x2 * s;
        base[i + 64] = x2 * c + x1 * s;
    }
}

// ---------------- attention: flash-style, 64-query tile, window 512 -------------
#define PADQ 129
#define PADP 65
__global__ __launch_bounds__(256) void attn_kernel(
    const float* __restrict__ Q, const float* __restrict__ K,
    const float* __restrict__ V, float* __restrict__ O)
{
    extern __shared__ float sm[];
    float* Qs = sm;                    // [64][129]
    float* Ks = Qs + 64 * PADQ;        // [64][129]
    float* Vs = Ks + 64 * PADQ;        // [64][129]
    float* Ps = Vs + 64 * PADQ;        // [64][65]
    float* mrow = Ps + 64 * PADP;      // [64]
    float* lrow = mrow + 64;           // [64]
    float* arow = lrow + 64;           // [64]

    int qb = blockIdx.x, h = blockIdx.y, b = blockIdx.z;
    int q0 = qb * 64;
    int tid = threadIdx.x;
    int tx = tid & 15, ty = tid >> 4;
    const float qscale = 0.08838834764831845f;   // 1/sqrt(128)

    // load + prescale Q tile
    const float* Qg = Q + (size_t)(b * Tt + q0) * 1024 + h * 128;
    for (int i = tid; i < 64 * 32; i += 256) {
        int m = i >> 5, d4 = (i & 31) * 4;
        float4 v = *(const float4*)(Qg + (size_t)m * 1024 + d4);
        float* dst = Qs + m * PADQ + d4;
        dst[0] = v.x * qscale; dst[1] = v.y * qscale;
        dst[2] = v.z * qscale; dst[3] = v.w * qscale;
    }
    if (tid < 64) { mrow[tid] = -INFINITY; lrow[tid] = 0.f; }

    float Oacc[4][8];
    #pragma unroll
    for (int i = 0; i < 4; i++)
        #pragma unroll
        for (int j = 0; j < 8; j++) Oacc[i][j] = 0.f;

    int kvh = h & 3;
    const float* Kg = K + (size_t)b * Tt * 512 + kvh * 128;
    const float* Vg = V + (size_t)b * Tt * 512 + kvh * 128;

    int jlo = (qb >= 8) ? qb - 8 : 0;
    for (int jt = jlo; jt <= qb; jt++) {
        __syncthreads();   // previous PV done before overwriting K/V/P
        int k0row = jt * 64;
        for (int i = tid; i < 64 * 32; i += 256) {
            int m = i >> 5, d4 = (i & 31) * 4;
            float4 kv4 = *(const float4*)(Kg + (size_t)(k0row + m) * 512 + d4);
            float* kd = Ks + m * PADQ + d4;
            kd[0] = kv4.x; kd[1] = kv4.y; kd[2] = kv4.z; kd[3] = kv4.w;
            float4 vv4 = *(const float4*)(Vg + (size_t)(k0row + m) * 512 + d4);
            float* vd = Vs + m * PADQ + d4;
            vd[0] = vv4.x; vd[1] = vv4.y; vd[2] = vv4.z; vd[3] = vv4.w;
        }
        __syncthreads();

        // S = Qs @ Ks^T  (64x64, over d=128)
        float s[4][4];
        #pragma unroll
        for (int i = 0; i < 4; i++)
            #pragma unroll
            for (int j = 0; j < 4; j++) s[i][j] = 0.f;
        #pragma unroll 4
        for (int d = 0; d < 128; d++) {
            float a[4], bb[4];
            #pragma unroll
            for (int i = 0; i < 4; i++) a[i] = Qs[(ty + 16 * i) * PADQ + d];
            #pragma unroll
            for (int j = 0; j < 4; j++) bb[j] = Ks[(tx + 16 * j) * PADQ + d];
            #pragma unroll
            for (int i = 0; i < 4; i++)
                #pragma unroll
                for (int j = 0; j < 4; j++) s[i][j] += a[i] * bb[j];
        }
        // softcap + mask + stage scores
        #pragma unroll
        for (int i = 0; i < 4; i++) {
            int r = ty + 16 * i, qt = q0 + r;
            #pragma unroll
            for (int j = 0; j < 4; j++) {
                int cl = tx + 16 * j, kt = k0row + cl;
                float sv = 50.0f * tanhf(s[i][j] * 0.02f);
                if (!((kt <= qt) && (qt - kt < WINs))) sv = -INFINITY;
                Ps[r * PADP + cl] = sv;
            }
        }
        __syncthreads();

        // online softmax: 4 threads per row
        {
            int r = tid >> 2, part = tid & 3;
            float vals[16];
            float tmax = -INFINITY;
            #pragma unroll
            for (int c = 0; c < 16; c++) {
                float pv = Ps[r * PADP + part * 16 + c];
                vals[c] = pv;
                tmax = fmaxf(tmax, pv);
            }
            tmax = fmaxf(tmax, __shfl_xor_sync(0xffffffffu, tmax, 1));
            tmax = fmaxf(tmax, __shfl_xor_sync(0xffffffffu, tmax, 2));
            float mold = mrow[r];
            float mnew = fmaxf(mold, tmax);
            float alpha, psum = 0.f;
            if (mnew == -INFINITY) {
                alpha = 1.0f;
                #pragma unroll
                for (int c = 0; c < 16; c++) Ps[r * PADP + part * 16 + c] = 0.f;
            } else {
                alpha = expf(mold - mnew);   // exp(-inf)=0 on first tile
                #pragma unroll
                for (int c = 0; c < 16; c++) {
                    float p = expf(vals[c] - mnew);
                    Ps[r * PADP + part * 16 + c] = p;
                    psum += p;
                }
            }
            psum += __shfl_xor_sync(0xffffffffu, psum, 1);
            psum += __shfl_xor_sync(0xffffffffu, psum, 2);
            if (part == 0) {
                mrow[r] = mnew;
                lrow[r] = lrow[r] * alpha + psum;
                arow[r] = alpha;
            }
        }
        __syncthreads();

        // O = O*alpha + P @ V  (64x128, over 64 keys)
        float al[4];
        #pragma unroll
        for (int i = 0; i < 4; i++) al[i] = arow[ty + 16 * i];
        #pragma unroll
        for (int i = 0; i < 4; i++)
            #pragma unroll
            for (int j = 0; j < 8; j++) Oacc[i][j] *= al[i];
        #pragma unroll 2
        for (int kk = 0; kk < 64; kk++) {
            float p[4], vv[8];
            #pragma unroll
            for (int i = 0; i < 4; i++) p[i] = Ps[(ty + 16 * i) * PADP + kk];
            #pragma unroll
            for (int j = 0; j < 8; j++) vv[j] = Vs[kk * PADQ + tx + 16 * j];
            #pragma unroll
            for (int i = 0; i < 4; i++)
                #pragma unroll
                for (int j = 0; j < 8; j++) Oacc[i][j] += p[i] * vv[j];
        }
    }

    // normalize + store
    float* Og = O + (size_t)(b * Tt + q0) * 1024 + h * 128;
    #pragma unroll
    for (int i = 0; i < 4; i++) {
        int r = ty + 16 * i;
        float linv = 1.0f / lrow[r];
        #pragma unroll
        for (int j = 0; j < 8; j++) {
            Og[(size_t)r * 1024 + tx + 16 * j] = Oacc[i][j] * linv;
        }
    }
}

// ---------------- swiglu: act = silu(gate) * up (in place into gate) ------------
__global__ void swiglu_kernel(const float* __restrict__ g,
                              const float* __restrict__ u,
                              float* __restrict__ a)
{
    int i = blockIdx.x * blockDim.x + threadIdx.x;
    float4 gv = ((const float4*)g)[i];
    float4 uv = ((const float4*)u)[i];
    float4 o;
    o.x = gv.x / (1.f + expf(-gv.x)) * uv.x;
    o.y = gv.y / (1.f + expf(-gv.y)) * uv.y;
    o.z = gv.z / (1.f + expf(-gv.z)) * uv.z;
    o.w = gv.w / (1.f + expf(-gv.w)) * uv.w;
    ((float4*)a)[i] = o;
}

// ---------------- launch ---------------------------------------------------------
extern "C" void kernel_launch(void* const* d_in, const int* in_sizes, int n_in,
                              void* d_out, int out_size)
{
    const float* x        = (const float*)d_in[0];
    const float* q_kernel = (const float*)d_in[1];
    const float* k_kernel = (const float*)d_in[2];
    const float* v_kernel = (const float*)d_in[3];
    const float* out_kern = (const float*)d_in[4];
    const float* attn_sc  = (const float*)d_in[5];
    const float* mlp_sc   = (const float*)d_in[6];
    const float* gate_k   = (const float*)d_in[7];
    const float* up_k     = (const float*)d_in[8];
    const float* down_k   = (const float*)d_in[9];
    float* out = (float*)d_out;

    float *p_h, *p_q, *p_k, *p_v, *p_attn, *p_x2, *p_gate, *p_up;
    cudaGetSymbolAddress((void**)&p_h,    g_h);
    cudaGetSymbolAddress((void**)&p_q,    g_q);
    cudaGetSymbolAddress((void**)&p_k,    g_k);
    cudaGetSymbolAddress((void**)&p_v,    g_v);
    cudaGetSymbolAddress((void**)&p_attn, g_attn);
    cudaGetSymbolAddress((void**)&p_x2,   g_x2);
    cudaGetSymbolAddress((void**)&p_gate, g_gate);
    cudaGetSymbolAddress((void**)&p_up,   g_up);

    const int ATTN_SMEM = (3 * 64 * PADQ + 64 * PADP + 3 * 64) * 4;  // 116480 B
    cudaFuncSetAttribute(attn_kernel, cudaFuncAttributeMaxDynamicSharedMemorySize,
                         ATTN_SMEM);

    // 1) h = rmsnorm(x, attn_scale)
    rmsnorm_kernel<<<Mrows, 256>>>(x, attn_sc, p_h);
    // 2) q/k/v projections
    sgemm_kernel<<<dim3(8, 32), 256>>>(p_h, q_kernel, nullptr, p_q, Mrows, 1024, 1024);
    sgemm_kernel<<<dim3(4, 32), 256>>>(p_h, k_kernel, nullptr, p_k, Mrows,  512, 1024);
    sgemm_kernel<<<dim3(4, 32), 256>>>(p_h, v_kernel, nullptr, p_v, Mrows,  512, 1024);
    // 3) rope
    rope_kernel<<<Mrows, 256>>>(p_q, p_k);
    // 4) attention
    attn_kernel<<<dim3(Tt / 64, Hh, Bb), 256, ATTN_SMEM>>>(p_q, p_k, p_v, p_attn);
    // 5) out projection + residual
    sgemm_kernel<<<dim3(8, 32), 256>>>(p_attn, out_kern, x, p_x2, Mrows, 1024, 1024);
    // 6) h = rmsnorm(x2, mlp_scale)
    rmsnorm_kernel<<<Mrows, 256>>>(p_x2, mlp_sc, p_h);
    // 7) gate / up
    sgemm_kernel<<<dim3(32, 32), 256>>>(p_h, gate_k, nullptr, p_gate, Mrows, HIDm, 1024);
    sgemm_kernel<<<dim3(32, 32), 256>>>(p_h, up_k,   nullptr, p_up,   Mrows, HIDm, 1024);
    // 8) act = silu(gate)*up
    swiglu_kernel<<<(Mrows * HIDm / 4) / 256, 256>>>(p_gate, p_up, p_gate);
    // 9) down + residual -> out
    sgemm_kernel<<<dim3(8, 32), 256>>>(p_gate, down_k, p_x2, out, Mrows, 1024, HIDm);
}

// round 3
// speedup vs baseline: 2.0571x; 2.0571x over previous
#include <cuda_runtime.h>
#include <stdint.h>
#include <math.h>

#define Bb   2
#define Tt   2048
#define Cc   1024
#define Hh   8
#define KVh  4
#define Dd   128
#define WINs 512
#define HIDm 4096
#define Mrows (Bb*Tt)   // 4096

// ---------------- scratch ----------------
__device__ float g_h   [Mrows*Cc];
__device__ float g_q   [Mrows*Hh*Dd];
__device__ float g_k   [Mrows*KVh*Dd];
__device__ float g_v   [Mrows*KVh*Dd];
__device__ float g_attn[Mrows*Hh*Dd];
__device__ float g_x2  [Mrows*Cc];
__device__ float g_gate[Mrows*HIDm];

// ---------------- helpers ----------------
__device__ __forceinline__ uint32_t f2tf32(float x) {
    uint32_t r; asm("cvt.rna.tf32.f32 %0, %1;" : "=r"(r) : "f"(x)); return r;
}

__device__ __forceinline__ void mma_tf32(float* d, const uint32_t* a, const uint32_t* b) {
    asm volatile(
        "mma.sync.aligned.m16n8k8.row.col.f32.tf32.tf32.f32 "
        "{%0,%1,%2,%3},{%4,%5,%6,%7},{%8,%9},{%0,%1,%2,%3};"
        : "+f"(d[0]), "+f"(d[1]), "+f"(d[2]), "+f"(d[3])
        : "r"(a[0]), "r"(a[1]), "r"(a[2]), "r"(a[3]),
          "r"(b[0]), "r"(b[1]));
}

// ---------------- rmsnorm ----------------
__global__ void rmsnorm_kernel(const float* __restrict__ x,
                               const float* __restrict__ scale,
                               float* __restrict__ y)
{
    int row = blockIdx.x;
    const float4* xr = (const float4*)(x + (size_t)row * Cc);
    float4 v = xr[threadIdx.x];
    float ss = v.x*v.x + v.y*v.y + v.z*v.z + v.w*v.w;
    #pragma unroll
    for (int o = 16; o; o >>= 1) ss += __shfl_xor_sync(0xffffffffu, ss, o);
    __shared__ float wsum[8];
    if ((threadIdx.x & 31) == 0) wsum[threadIdx.x >> 5] = ss;
    __syncthreads();
    if (threadIdx.x < 8) {
        float t = wsum[threadIdx.x];
        #pragma unroll
        for (int o = 4; o; o >>= 1) t += __shfl_xor_sync(0xffu, t, o);
        if (threadIdx.x == 0) wsum[0] = t;
    }
    __syncthreads();
    float inv = rsqrtf(wsum[0] * (1.0f / Cc) + 1e-6f);
    float4 sc = ((const float4*)scale)[threadIdx.x];
    float4 o;
    o.x = v.x * inv * (1.f + sc.x);
    o.y = v.y * inv * (1.f + sc.y);
    o.z = v.z * inv * (1.f + sc.z);
    o.w = v.w * inv * (1.f + sc.w);
    ((float4*)(y + (size_t)row * Cc))[threadIdx.x] = o;
}

// ---------------- TF32 tensor-core GEMM ------------------------------------
// C[M,N] = A[M,K] @ B[K,N]  (+ epilogue)
// MODE 0: plain   MODE 1: += Res   MODE 2: C = silu(Res) * acc  (SwiGLU fuse)
// 128x128x16 tile, 256 thr, 8 warps (2m x 4n), warp tile 64x32, m16n8k8 tf32.
#define PA 136
template<int MODE>
__global__ __launch_bounds__(256) void tf32gemm_kernel(
    const float* __restrict__ A, const float* __restrict__ B,
    const float* __restrict__ Res, float* __restrict__ C,
    int M, int N, int K)
{
    __shared__ uint32_t As[2][16 * PA];   // [k][m], pitch 136
    __shared__ uint32_t Bs[2][16 * PA];   // [k][n], pitch 136

    int tid  = threadIdx.x;
    int lane = tid & 31, warp = tid >> 5;
    int wm = (warp & 1) * 64;
    int wn = (warp >> 1) * 32;
    int g = lane >> 2, c = lane & 3;

    int m0 = blockIdx.y * 128, n0 = blockIdx.x * 128;

    // A loader: thread owns k = tid&15, m-quad = (tid>>4)*4 (and +64)
    int ak = tid & 15;
    int am = (tid >> 4) * 4;
    const float* Ag = A + (size_t)(m0 + am) * K + ak;
    // B loader: row = tid>>5 (and +8), 4 cols at (tid&31)*4
    int brow = tid >> 5;
    int bcol = (tid & 31) * 4;
    const float* Bg = B + (size_t)brow * N + n0 + bcol;

    float acc[4][4][4];
    #pragma unroll
    for (int i = 0; i < 4; i++)
        #pragma unroll
        for (int j = 0; j < 4; j++)
            #pragma unroll
            for (int r = 0; r < 4; r++) acc[i][j][r] = 0.f;

    int ntiles = K >> 4;

    // prologue: tile 0 -> buf 0
    {
        float a[8];
        #pragma unroll
        for (int i = 0; i < 4; i++) {
            a[i]     = Ag[(size_t)i * K];
            a[i + 4] = Ag[(size_t)(i + 64) * K];
        }
        float4 b0 = *(const float4*)Bg;
        float4 b1 = *(const float4*)(Bg + (size_t)8 * N);
        #pragma unroll
        for (int i = 0; i < 4; i++) {
            As[0][ak * PA + am + i]      = f2tf32(a[i]);
            As[0][ak * PA + am + 64 + i] = f2tf32(a[i + 4]);
        }
        uint32_t* bd0 = &Bs[0][brow * PA + bcol];
        bd0[0] = f2tf32(b0.x); bd0[1] = f2tf32(b0.y); bd0[2] = f2tf32(b0.z); bd0[3] = f2tf32(b0.w);
        uint32_t* bd1 = &Bs[0][(brow + 8) * PA + bcol];
        bd1[0] = f2tf32(b1.x); bd1[1] = f2tf32(b1.y); bd1[2] = f2tf32(b1.z); bd1[3] = f2tf32(b1.w);
    }
    __syncthreads();

    int buf = 0;
    for (int kt = 0; kt < ntiles; kt++) {
        // prefetch next tile into regs
        float na[8]; float4 nb0, nb1;
        bool more = (kt + 1 < ntiles);
        if (more) {
            const float* Ap = Ag + (kt + 1) * 16;
            #pragma unroll
            for (int i = 0; i < 4; i++) {
                na[i]     = Ap[(size_t)i * K];
                na[i + 4] = Ap[(size_t)(i + 64) * K];
            }
            const float* Bp = Bg + (size_t)(kt + 1) * 16 * N;
            nb0 = *(const float4*)Bp;
            nb1 = *(const float4*)(Bp + (size_t)8 * N);
        }

        // compute on buf
        #pragma unroll
        for (int ks = 0; ks < 2; ks++) {
            uint32_t bf[4][2];
            #pragma unroll
            for (int nt = 0; nt < 4; nt++) {
                int col = wn + nt * 8 + g;
                bf[nt][0] = Bs[buf][(ks * 8 + c) * PA + col];
                bf[nt][1] = Bs[buf][(ks * 8 + c + 4) * PA + col];
            }
            #pragma unroll
            for (int mt = 0; mt < 4; mt++) {
                int row = wm + mt * 16 + g;
                uint32_t af[4];
                af[0] = As[buf][(ks * 8 + c) * PA + row];
                af[1] = As[buf][(ks * 8 + c) * PA + row + 8];
                af[2] = As[buf][(ks * 8 + c + 4) * PA + row];
                af[3] = As[buf][(ks * 8 + c + 4) * PA + row + 8];
                #pragma unroll
                for (int nt = 0; nt < 4; nt++)
                    mma_tf32(acc[mt][nt], af, bf[nt]);
            }
        }

        if (more) {
            int nb = buf ^ 1;
            #pragma unroll
            for (int i = 0; i < 4; i++) {
                As[nb][ak * PA + am + i]      = f2tf32(na[i]);
                As[nb][ak * PA + am + 64 + i] = f2tf32(na[i + 4]);
            }
            uint32_t* bd0 = &Bs[nb][brow * PA + bcol];
            bd0[0] = f2tf32(nb0.x); bd0[1] = f2tf32(nb0.y); bd0[2] = f2tf32(nb0.z); bd0[3] = f2tf32(nb0.w);
            uint32_t* bd1 = &Bs[nb][(brow + 8) * PA + bcol];
            bd1[0] = f2tf32(nb1.x); bd1[1] = f2tf32(nb1.y); bd1[2] = f2tf32(nb1.z); bd1[3] = f2tf32(nb1.w);
            __syncthreads();
            buf = nb;
        }
    }

    // epilogue
    #pragma unroll
    for (int mt = 0; mt < 4; mt++) {
        int r0 = m0 + wm + mt * 16 + g;
        #pragma unroll
        for (int nt = 0; nt < 4; nt++) {
            int cl = n0 + wn + nt * 8 + 2 * c;
            #pragma unroll
            for (int half = 0; half < 2; half++) {
                int rr = r0 + half * 8;
                float v0 = acc[mt][nt][half * 2 + 0];
                float v1 = acc[mt][nt][half * 2 + 1];
                size_t idx = (size_t)rr * N + cl;
                if (MODE == 1) {
                    v0 += Res[idx];
                    v1 += Res[idx + 1];
                } else if (MODE == 2) {
                    float gt0 = Res[idx], gt1 = Res[idx + 1];
                    v0 *= gt0 / (1.f + expf(-gt0));
                    v1 *= gt1 / (1.f + expf(-gt1));
                }
                float2 o = make_float2(v0, v1);
                *(float2*)(C + idx) = o;
            }
        }
    }
}

// ---------------- RoPE ----------------
__global__ void rope_kernel(float* __restrict__ q, float* __restrict__ k)
{
    int row = blockIdx.x;
    int t = row & (Tt - 1);
    __shared__ float s_sin[64], s_cos[64];
    if (threadIdx.x < 64) {
        float inv = expf(-logf(10000.0f) * (2.0f * threadIdx.x) / 128.0f);
        float ang = (float)t * inv;
        s_sin[threadIdx.x] = sinf(ang);
        s_cos[threadIdx.x] = cosf(ang);
    }
    __syncthreads();
    for (int p = threadIdx.x; p < 512; p += 256) {
        int head = p >> 6, i = p & 63;
        float* base = q + (size_t)row * 1024 + head * 128;
        float x1 = base[i], x2 = base[i + 64];
        float s = s_sin[i], c = s_cos[i];
        base[i]      = x1 * c - x2 * s;
        base[i + 64] = x2 * c + x1 * s;
    }
    for (int p = threadIdx.x; p < 256; p += 256) {
        int head = p >> 6, i = p & 63;
        float* base = k + (size_t)row * 512 + head * 128;
        float x1 = base[i], x2 = base[i + 64];
        float s = s_sin[i], c = s_cos[i];
        base[i]      = x1 * c - x2 * s;
        base[i + 64] = x2 * c + x1 * s;
    }
}

// ---------------- attention (fp32 flash) ----------------
#define PADQ 129
#define PADP 65
__global__ __launch_bounds__(256) void attn_kernel(
    const float* __restrict__ Q, const float* __restrict__ K,
    const float* __restrict__ V, float* __restrict__ O)
{
    extern __shared__ float sm[];
    float* Qs = sm;
    float* Ks = Qs + 64 * PADQ;
    float* Vs = Ks + 64 * PADQ;
    float* Ps = Vs + 64 * PADQ;
    float* mrow = Ps + 64 * PADP;
    float* lrow = mrow + 64;
    float* arow = lrow + 64;

    int qb = blockIdx.x, h = blockIdx.y, b = blockIdx.z;
    int q0 = qb * 64;
    int tid = threadIdx.x;
    int tx = tid & 15, ty = tid >> 4;
    const float qscale = 0.08838834764831845f;

    const float* Qg = Q + (size_t)(b * Tt + q0) * 1024 + h * 128;
    for (int i = tid; i < 64 * 32; i += 256) {
        int m = i >> 5, d4 = (i & 31) * 4;
        float4 v = *(const float4*)(Qg + (size_t)m * 1024 + d4);
        float* dst = Qs + m * PADQ + d4;
        dst[0] = v.x * qscale; dst[1] = v.y * qscale;
        dst[2] = v.z * qscale; dst[3] = v.w * qscale;
    }
    if (tid < 64) { mrow[tid] = -INFINITY; lrow[tid] = 0.f; }

    float Oacc[4][8];
    #pragma unroll
    for (int i = 0; i < 4; i++)
        #pragma unroll
        for (int j = 0; j < 8; j++) Oacc[i][j] = 0.f;

    int kvh = h & 3;
    const float* Kg = K + (size_t)b * Tt * 512 + kvh * 128;
    const float* Vg = V + (size_t)b * Tt * 512 + kvh * 128;

    int jlo = (qb >= 8) ? qb - 8 : 0;
    for (int jt = jlo; jt <= qb; jt++) {
        __syncthreads();
        int k0row = jt * 64;
        for (int i = tid; i < 64 * 32; i += 256) {
            int m = i >> 5, d4 = (i & 31) * 4;
            float4 kv4 = *(const float4*)(Kg + (size_t)(k0row + m) * 512 + d4);
            float* kd = Ks + m * PADQ + d4;
            kd[0] = kv4.x; kd[1] = kv4.y; kd[2] = kv4.z; kd[3] = kv4.w;
            float4 vv4 = *(const float4*)(Vg + (size_t)(k0row + m) * 512 + d4);
            float* vd = Vs + m * PADQ + d4;
            vd[0] = vv4.x; vd[1] = vv4.y; vd[2] = vv4.z; vd[3] = vv4.w;
        }
        __syncthreads();

        float s[4][4];
        #pragma unroll
        for (int i = 0; i < 4; i++)
            #pragma unroll
            for (int j = 0; j < 4; j++) s[i][j] = 0.f;
        #pragma unroll 4
        for (int d = 0; d < 128; d++) {
            float a[4], bb[4];
            #pragma unroll
            for (int i = 0; i < 4; i++) a[i] = Qs[(ty + 16 * i) * PADQ + d];
            #pragma unroll
            for (int j = 0; j < 4; j++) bb[j] = Ks[(tx + 16 * j) * PADQ + d];
            #pragma unroll
            for (int i = 0; i < 4; i++)
                #pragma unroll
                for (int j = 0; j < 4; j++) s[i][j] += a[i] * bb[j];
        }
        #pragma unroll
        for (int i = 0; i < 4; i++) {
            int r = ty + 16 * i, qt = q0 + r;
            #pragma unroll
            for (int j = 0; j < 4; j++) {
                int cl = tx + 16 * j, kt = k0row + cl;
                float sv = 50.0f * tanhf(s[i][j] * 0.02f);
                if (!((kt <= qt) && (qt - kt < WINs))) sv = -INFINITY;
                Ps[r * PADP + cl] = sv;
            }
        }
        __syncthreads();

        {
            int r = tid >> 2, part = tid & 3;
            float vals[16];
            float tmax = -INFINITY;
            #pragma unroll
            for (int cc = 0; cc < 16; cc++) {
                float pv = Ps[r * PADP + part * 16 + cc];
                vals[cc] = pv;
                tmax = fmaxf(tmax, pv);
            }
            tmax = fmaxf(tmax, __shfl_xor_sync(0xffffffffu, tmax, 1));
            tmax = fmaxf(tmax, __shfl_xor_sync(0xffffffffu, tmax, 2));
            float mold = mrow[r];
            float mnew = fmaxf(mold, tmax);
            float alpha, psum = 0.f;
            if (mnew == -INFINITY) {
                alpha = 1.0f;
                #pragma unroll
                for (int cc = 0; cc < 16; cc++) Ps[r * PADP + part * 16 + cc] = 0.f;
            } else {
                alpha = expf(mold - mnew);
                #pragma unroll
                for (int cc = 0; cc < 16; cc++) {
                    float p = expf(vals[cc] - mnew);
                    Ps[r * PADP + part * 16 + cc] = p;
                    psum += p;
                }
            }
            psum += __shfl_xor_sync(0xffffffffu, psum, 1);
            psum += __shfl_xor_sync(0xffffffffu, psum, 2);
            if (part == 0) {
                mrow[r] = mnew;
                lrow[r] = lrow[r] * alpha + psum;
                arow[r] = alpha;
            }
        }
        __syncthreads();

        float al[4];
        #pragma unroll
        for (int i = 0; i < 4; i++) al[i] = arow[ty + 16 * i];
        #pragma unroll
        for (int i = 0; i < 4; i++)
            #pragma unroll
            for (int j = 0; j < 8; j++) Oacc[i][j] *= al[i];
        #pragma unroll 2
        for (int kk = 0; kk < 64; kk++) {
            float p[4], vv[8];
            #pragma unroll
            for (int i = 0; i < 4; i++) p[i] = Ps[(ty + 16 * i) * PADP + kk];
            #pragma unroll
            for (int j = 0; j < 8; j++) vv[j] = Vs[kk * PADQ + tx + 16 * j];
            #pragma unroll
            for (int i = 0; i < 4; i++)
                #pragma unroll
                for (int j = 0; j < 8; j++) Oacc[i][j] += p[i] * vv[j];
        }
    }

    float* Og = O + (size_t)(b * Tt + q0) * 1024 + h * 128;
    #pragma unroll
    for (int i = 0; i < 4; i++) {
        int r = ty + 16 * i;
        float linv = 1.0f / lrow[r];
        #pragma unroll
        for (int j = 0; j < 8; j++) {
            Og[(size_t)r * 1024 + tx + 16 * j] = Oacc[i][j] * linv;
        }
    }
}

// ---------------- launch ----------------
extern "C" void kernel_launch(void* const* d_in, const int* in_sizes, int n_in,
                              void* d_out, int out_size)
{
    const float* x        = (const float*)d_in[0];
    const float* q_kernel = (const float*)d_in[1];
    const float* k_kernel = (const float*)d_in[2];
    const float* v_kernel = (const float*)d_in[3];
    const float* out_kern = (const float*)d_in[4];
    const float* attn_sc  = (const float*)d_in[5];
    const float* mlp_sc   = (const float*)d_in[6];
    const float* gate_k   = (const float*)d_in[7];
    const float* up_k     = (const float*)d_in[8];
    const float* down_k   = (const float*)d_in[9];
    float* out = (float*)d_out;

    float *p_h, *p_q, *p_k, *p_v, *p_attn, *p_x2, *p_gate;
    cudaGetSymbolAddress((void**)&p_h,    g_h);
    cudaGetSymbolAddress((void**)&p_q,    g_q);
    cudaGetSymbolAddress((void**)&p_k,    g_k);
    cudaGetSymbolAddress((void**)&p_v,    g_v);
    cudaGetSymbolAddress((void**)&p_attn, g_attn);
    cudaGetSymbolAddress((void**)&p_x2,   g_x2);
    cudaGetSymbolAddress((void**)&p_gate, g_gate);

    const int ATTN_SMEM = (3 * 64 * PADQ + 64 * PADP + 3 * 64) * 4;
    cudaFuncSetAttribute(attn_kernel, cudaFuncAttributeMaxDynamicSharedMemorySize,
                         ATTN_SMEM);

    // 1) h = rmsnorm(x, attn_scale)
    rmsnorm_kernel<<<Mrows, 256>>>(x, attn_sc, p_h);
    // 2) q/k/v projections (tf32 TC)
    tf32gemm_kernel<0><<<dim3(8, 32), 256>>>(p_h, q_kernel, nullptr, p_q, Mrows, 1024, 1024);
    tf32gemm_kernel<0><<<dim3(4, 32), 256>>>(p_h, k_kernel, nullptr, p_k, Mrows,  512, 1024);
    tf32gemm_kernel<0><<<dim3(4, 32), 256>>>(p_h, v_kernel, nullptr, p_v, Mrows,  512, 1024);
    // 3) rope
    rope_kernel<<<Mrows, 256>>>(p_q, p_k);
    // 4) attention
    attn_kernel<<<dim3(Tt / 64, Hh, Bb), 256, ATTN_SMEM>>>(p_q, p_k, p_v, p_attn);
    // 5) out projection + residual
    tf32gemm_kernel<1><<<dim3(8, 32), 256>>>(p_attn, out_kern, x, p_x2, Mrows, 1024, 1024);
    // 6) h = rmsnorm(x2, mlp_scale)
    rmsnorm_kernel<<<Mrows, 256>>>(p_x2, mlp_sc, p_h);
    // 7) gate, then up with fused SwiGLU epilogue -> act in p_gate
    tf32gemm_kernel<0><<<dim3(32, 32), 256>>>(p_h, gate_k, nullptr, p_gate, Mrows, HIDm, 1024);
    tf32gemm_kernel<2><<<dim3(32, 32), 256>>>(p_h, up_k, p_gate, p_gate, Mrows, HIDm, 1024);
    // 8) down + residual -> out
    tf32gemm_kernel<1><<<dim3(8, 32), 256>>>(p_gate, down_k, p_x2, out, Mrows, 1024, HIDm);
}

// round 4
// speedup vs baseline: 2.6680x; 1.2970x over previous
#include <cuda_runtime.h>
#include <stdint.h>
#include <math.h>

#define Bb   2
#define Tt   2048
#define Cc   1024
#define Hh   8
#define KVh  4
#define Dd   128
#define WINs 512
#define HIDm 4096
#define Mrows (Bb*Tt)   // 4096

// ---------------- scratch ----------------
__device__ float g_h   [Mrows*Cc];
__device__ float g_q   [Mrows*Hh*Dd];
__device__ float g_k   [Mrows*KVh*Dd];
__device__ float g_v   [Mrows*KVh*Dd];
__device__ float g_attn[Mrows*Hh*Dd];
__device__ float g_x2  [Mrows*Cc];
__device__ float g_gate[Mrows*HIDm];

// ---------------- mma helper ----------------
__device__ __forceinline__ void mma_tf32(float* d, const uint32_t* a, const uint32_t* b) {
    asm volatile(
        "mma.sync.aligned.m16n8k8.row.col.f32.tf32.tf32.f32 "
        "{%0,%1,%2,%3},{%4,%5,%6,%7},{%8,%9},{%0,%1,%2,%3};"
        : "+f"(d[0]), "+f"(d[1]), "+f"(d[2]), "+f"(d[3])
        : "r"(a[0]), "r"(a[1]), "r"(a[2]), "r"(a[3]),
          "r"(b[0]), "r"(b[1]));
}

#define CP16(dst, src) \
    asm volatile("cp.async.cg.shared.global [%0], [%1], 16;" :: "r"(dst), "l"(src))
#define CP_COMMIT() asm volatile("cp.async.commit_group;")
#define CP_WAIT1()  asm volatile("cp.async.wait_group 1;")

// ---------------- rmsnorm ----------------
__global__ void rmsnorm_kernel(const float* __restrict__ x,
                               const float* __restrict__ scale,
                               float* __restrict__ y)
{
    int row = blockIdx.x;
    const float4* xr = (const float4*)(x + (size_t)row * Cc);
    float4 v = xr[threadIdx.x];
    float ss = v.x*v.x + v.y*v.y + v.z*v.z + v.w*v.w;
    #pragma unroll
    for (int o = 16; o; o >>= 1) ss += __shfl_xor_sync(0xffffffffu, ss, o);
    __shared__ float wsum[8];
    if ((threadIdx.x & 31) == 0) wsum[threadIdx.x >> 5] = ss;
    __syncthreads();
    if (threadIdx.x < 8) {
        float t = wsum[threadIdx.x];
        #pragma unroll
        for (int o = 4; o; o >>= 1) t += __shfl_xor_sync(0xffu, t, o);
        if (threadIdx.x == 0) wsum[0] = t;
    }
    __syncthreads();
    float inv = rsqrtf(wsum[0] * (1.0f / Cc) + 1e-6f);
    float4 sc = ((const float4*)scale)[threadIdx.x];
    float4 o;
    o.x = v.x * inv * (1.f + sc.x);
    o.y = v.y * inv * (1.f + sc.y);
    o.z = v.z * inv * (1.f + sc.z);
    o.w = v.w * inv * (1.f + sc.w);
    ((float4*)(y + (size_t)row * Cc))[threadIdx.x] = o;
}

// ---------------- TF32 GEMM core (cp.async 3-stage) --------------------------
// A [M,K] row-major, B [K,NB] row-major. Computes 128x128 tile at (m0, n0B),
// writes C (stride NC) at column n0C. MODE 0: plain, 1: +=Res, 2: silu(Res)*acc.
#define PA_A 20          // A smem pitch (floats): [128][20]
#define PB_B 136         // B smem pitch (floats): [16][136]
#define A_STG (128*PA_A) // 2560
#define B_STG (16*PB_B)  // 2176
#define STG   (A_STG + B_STG)   // 4736 floats
#define GEMM_STAGES 3
#define GEMM_SMEM (GEMM_STAGES*STG*4)   // 56832 bytes

template<int MODE>
__device__ __forceinline__ void gemm_tile(
    const float* __restrict__ A, const float* __restrict__ B,
    const float* __restrict__ Res, float* __restrict__ C,
    int NB, int NC, int K, int m0, int n0B, int n0C, float* sm)
{
    int tid  = threadIdx.x;
    int lane = tid & 31, warp = tid >> 5;
    int wm = (warp & 1) * 64;
    int wn = (warp >> 1) * 32;
    int g = lane >> 2, c = lane & 3;

    // loader coords
    int la_m  = tid >> 1;
    int la_c0 = (tid & 1) * 2;            // A chunk pair: c4 in {la_c0, la_c0+1}
    int lb_k  = tid >> 4;
    int lb_j0 = (tid & 15) * 2;           // B chunk pair

    const float* Abase = A + (size_t)(m0 + la_m) * K + la_c0 * 4;
    const float* Bbase = B + (size_t)lb_k * NB + n0B + lb_j0 * 4;

    uint32_t smu = (uint32_t)__cvta_generic_to_shared(sm);
    uint32_t dA = smu + (uint32_t)(la_m * PA_A + la_c0 * 4) * 4u;
    uint32_t dB = smu + (uint32_t)(A_STG + lb_k * PB_B + lb_j0 * 4) * 4u;

    float acc[4][4][4];
    #pragma unroll
    for (int i = 0; i < 4; i++)
        #pragma unroll
        for (int j = 0; j < 4; j++)
            #pragma unroll
            for (int r = 0; r < 4; r++) acc[i][j][r] = 0.f;

    int ntiles = K >> 4;

    // prologue: stages 0,1
    #pragma unroll
    for (int s = 0; s < GEMM_STAGES - 1; s++) {
        uint32_t off = (uint32_t)(s * STG) * 4u;
        const float* as = Abase + s * 16;
        CP16(dA + off, as);
        CP16(dA + off + 16, as + 4);
        const float* bs = Bbase + (size_t)s * 16 * NB;
        CP16(dB + off, bs);
        CP16(dB + off + 16, bs + 4);
        CP_COMMIT();
    }

    for (int kt = 0; kt < ntiles; kt++) {
        CP_WAIT1();
        __syncthreads();

        int pf = kt + GEMM_STAGES - 1;
        if (pf < ntiles) {
            int s = pf % GEMM_STAGES;
            uint32_t off = (uint32_t)(s * STG) * 4u;
            const float* as = Abase + pf * 16;
            CP16(dA + off, as);
            CP16(dA + off + 16, as + 4);
            const float* bs = Bbase + (size_t)pf * 16 * NB;
            CP16(dB + off, bs);
            CP16(dB + off + 16, bs + 4);
        }
        CP_COMMIT();

        const float* sA = sm + (kt % GEMM_STAGES) * STG;
        const float* sB = sA + A_STG;
        #pragma unroll
        for (int ks = 0; ks < 2; ks++) {
            uint32_t bf[4][2];
            #pragma unroll
            for (int nt = 0; nt < 4; nt++) {
                int col = wn + nt * 8 + g;
                bf[nt][0] = __float_as_uint(sB[(ks * 8 + c) * PB_B + col]);
                bf[nt][1] = __float_as_uint(sB[(ks * 8 + c + 4) * PB_B + col]);
            }
            #pragma unroll
            for (int mt = 0; mt < 4; mt++) {
                int row = wm + mt * 16 + g;
                uint32_t af[4];
                af[0] = __float_as_uint(sA[row * PA_A + ks * 8 + c]);
                af[1] = __float_as_uint(sA[(row + 8) * PA_A + ks * 8 + c]);
                af[2] = __float_as_uint(sA[row * PA_A + ks * 8 + c + 4]);
                af[3] = __float_as_uint(sA[(row + 8) * PA_A + ks * 8 + c + 4]);
                #pragma unroll
                for (int nt = 0; nt < 4; nt++)
                    mma_tf32(acc[mt][nt], af, bf[nt]);
            }
        }
    }

    // epilogue
    #pragma unroll
    for (int mt = 0; mt < 4; mt++) {
        int r0 = m0 + wm + mt * 16 + g;
        #pragma unroll
        for (int nt = 0; nt < 4; nt++) {
            int cl = n0C + wn + nt * 8 + 2 * c;
            #pragma unroll
            for (int half = 0; half < 2; half++) {
                int rr = r0 + half * 8;
                float v0 = acc[mt][nt][half * 2 + 0];
                float v1 = acc[mt][nt][half * 2 + 1];
                size_t idx = (size_t)rr * NC + cl;
                if (MODE == 1) {
                    v0 += Res[idx];
                    v1 += Res[idx + 1];
                } else if (MODE == 2) {
                    float gt0 = Res[idx], gt1 = Res[idx + 1];
                    v0 *= gt0 / (1.f + expf(-gt0));
                    v1 *= gt1 / (1.f + expf(-gt1));
                }
                *(float2*)(C + idx) = make_float2(v0, v1);
            }
        }
    }
}

template<int MODE>
__global__ __launch_bounds__(256, 2) void tf32gemm_kernel(
    const float* __restrict__ A, const float* __restrict__ B,
    const float* __restrict__ Res, float* __restrict__ C, int N, int K)
{
    extern __shared__ float sm[];
    gemm_tile<MODE>(A, B, Res, C, N, N, K,
                    blockIdx.y * 128, blockIdx.x * 128, blockIdx.x * 128, sm);
}

// fused QKV: grid.x = 16 (8 q blocks, 4 k blocks, 4 v blocks)
__global__ __launch_bounds__(256, 2) void qkv_gemm_kernel(
    const float* __restrict__ A,
    const float* __restrict__ Bq, const float* __restrict__ Bk,
    const float* __restrict__ Bv,
    float* __restrict__ Cq, float* __restrict__ Ck, float* __restrict__ Cv,
    int K)
{
    extern __shared__ float sm[];
    int nb = blockIdx.x;
    int m0 = blockIdx.y * 128;
    if (nb < 8)
        gemm_tile<0>(A, Bq, nullptr, Cq, 1024, 1024, K, m0, nb * 128, nb * 128, sm);
    else if (nb < 12)
        gemm_tile<0>(A, Bk, nullptr, Ck, 512, 512, K, m0, (nb - 8) * 128, (nb - 8) * 128, sm);
    else
        gemm_tile<0>(A, Bv, nullptr, Cv, 512, 512, K, m0, (nb - 12) * 128, (nb - 12) * 128, sm);
}

// ---------------- RoPE ----------------
__global__ void rope_kernel(float* __restrict__ q, float* __restrict__ k)
{
    int row = blockIdx.x;
    int t = row & (Tt - 1);
    __shared__ float s_sin[64], s_cos[64];
    if (threadIdx.x < 64) {
        float inv = expf(-logf(10000.0f) * (2.0f * threadIdx.x) / 128.0f);
        float ang = (float)t * inv;
        s_sin[threadIdx.x] = sinf(ang);
        s_cos[threadIdx.x] = cosf(ang);
    }
    __syncthreads();
    for (int p = threadIdx.x; p < 512; p += 256) {
        int head = p >> 6, i = p & 63;
        float* base = q + (size_t)row * 1024 + head * 128;
        float x1 = base[i], x2 = base[i + 64];
        float s = s_sin[i], c = s_cos[i];
        base[i]      = x1 * c - x2 * s;
        base[i + 64] = x2 * c + x1 * s;
    }
    for (int p = threadIdx.x; p < 256; p += 256) {
        int head = p >> 6, i = p & 63;
        float* base = k + (size_t)row * 512 + head * 128;
        float x1 = base[i], x2 = base[i + 64];
        float s = s_sin[i], c = s_cos[i];
        base[i]      = x1 * c - x2 * s;
        base[i + 64] = x2 * c + x1 * s;
    }
}

// ---------------- attention (fp32 flash) ----------------
#define PADQ 129
#define PADP 65
__global__ __launch_bounds__(256) void attn_kernel(
    const float* __restrict__ Q, const float* __restrict__ K,
    const float* __restrict__ V, float* __restrict__ O)
{
    extern __shared__ float sm[];
    float* Qs = sm;
    float* Ks = Qs + 64 * PADQ;
    float* Vs = Ks + 64 * PADQ;
    float* Ps = Vs + 64 * PADQ;
    float* mrow = Ps + 64 * PADP;
    float* lrow = mrow + 64;
    float* arow = lrow + 64;

    int qb = blockIdx.x, h = blockIdx.y, b = blockIdx.z;
    int q0 = qb * 64;
    int tid = threadIdx.x;
    int tx = tid & 15, ty = tid >> 4;
    const float qscale = 0.08838834764831845f;

    const float* Qg = Q + (size_t)(b * Tt + q0) * 1024 + h * 128;
    for (int i = tid; i < 64 * 32; i += 256) {
        int m = i >> 5, d4 = (i & 31) * 4;
        float4 v = *(const float4*)(Qg + (size_t)m * 1024 + d4);
        float* dst = Qs + m * PADQ + d4;
        dst[0] = v.x * qscale; dst[1] = v.y * qscale;
        dst[2] = v.z * qscale; dst[3] = v.w * qscale;
    }
    if (tid < 64) { mrow[tid] = -INFINITY; lrow[tid] = 0.f; }

    float Oacc[4][8];
    #pragma unroll
    for (int i = 0; i < 4; i++)
        #pragma unroll
        for (int j = 0; j < 8; j++) Oacc[i][j] = 0.f;

    int kvh = h & 3;
    const float* Kg = K + (size_t)b * Tt * 512 + kvh * 128;
    const float* Vg = V + (size_t)b * Tt * 512 + kvh * 128;

    int jlo = (qb >= 8) ? qb - 8 : 0;
    for (int jt = jlo; jt <= qb; jt++) {
        __syncthreads();
        int k0row = jt * 64;
        for (int i = tid; i < 64 * 32; i += 256) {
            int m = i >> 5, d4 = (i & 31) * 4;
            float4 kv4 = *(const float4*)(Kg + (size_t)(k0row + m) * 512 + d4);
            float* kd = Ks + m * PADQ + d4;
            kd[0] = kv4.x; kd[1] = kv4.y; kd[2] = kv4.z; kd[3] = kv4.w;
            float4 vv4 = *(const float4*)(Vg + (size_t)(k0row + m) * 512 + d4);
            float* vd = Vs + m * PADQ + d4;
            vd[0] = vv4.x; vd[1] = vv4.y; vd[2] = vv4.z; vd[3] = vv4.w;
        }
        __syncthreads();

        float s[4][4];
        #pragma unroll
        for (int i = 0; i < 4; i++)
            #pragma unroll
            for (int j = 0; j < 4; j++) s[i][j] = 0.f;
        #pragma unroll 4
        for (int d = 0; d < 128; d++) {
            float a[4], bb[4];
            #pragma unroll
            for (int i = 0; i < 4; i++) a[i] = Qs[(ty + 16 * i) * PADQ + d];
            #pragma unroll
            for (int j = 0; j < 4; j++) bb[j] = Ks[(tx + 16 * j) * PADQ + d];
            #pragma unroll
            for (int i = 0; i < 4; i++)
                #pragma unroll
                for (int j = 0; j < 4; j++) s[i][j] += a[i] * bb[j];
        }
        #pragma unroll
        for (int i = 0; i < 4; i++) {
            int r = ty + 16 * i, qt = q0 + r;
            #pragma unroll
            for (int j = 0; j < 4; j++) {
                int cl = tx + 16 * j, kt = k0row + cl;
                float sv = 50.0f * tanhf(s[i][j] * 0.02f);
                if (!((kt <= qt) && (qt - kt < WINs))) sv = -INFINITY;
                Ps[r * PADP + cl] = sv;
            }
        }
        __syncthreads();

        {
            int r = tid >> 2, part = tid & 3;
            float vals[16];
            float tmax = -INFINITY;
            #pragma unroll
            for (int cc = 0; cc < 16; cc++) {
                float pv = Ps[r * PADP + part * 16 + cc];
                vals[cc] = pv;
                tmax = fmaxf(tmax, pv);
            }
            tmax = fmaxf(tmax, __shfl_xor_sync(0xffffffffu, tmax, 1));
            tmax = fmaxf(tmax, __shfl_xor_sync(0xffffffffu, tmax, 2));
            float mold = mrow[r];
            float mnew = fmaxf(mold, tmax);
            float alpha, psum = 0.f;
            if (mnew == -INFINITY) {
                alpha = 1.0f;
                #pragma unroll
                for (int cc = 0; cc < 16; cc++) Ps[r * PADP + part * 16 + cc] = 0.f;
            } else {
                alpha = expf(mold - mnew);
                #pragma unroll
                for (int cc = 0; cc < 16; cc++) {
                    float p = expf(vals[cc] - mnew);
                    Ps[r * PADP + part * 16 + cc] = p;
                    psum += p;
                }
            }
            psum += __shfl_xor_sync(0xffffffffu, psum, 1);
            psum += __shfl_xor_sync(0xffffffffu, psum, 2);
            if (part == 0) {
                mrow[r] = mnew;
                lrow[r] = lrow[r] * alpha + psum;
                arow[r] = alpha;
            }
        }
        __syncthreads();

        float al[4];
        #pragma unroll
        for (int i = 0; i < 4; i++) al[i] = arow[ty + 16 * i];
        #pragma unroll
        for (int i = 0; i < 4; i++)
            #pragma unroll
            for (int j = 0; j < 8; j++) Oacc[i][j] *= al[i];
        #pragma unroll 2
        for (int kk = 0; kk < 64; kk++) {
            float p[4], vv[8];
            #pragma unroll
            for (int i = 0; i < 4; i++) p[i] = Ps[(ty + 16 * i) * PADP + kk];
            #pragma unroll
            for (int j = 0; j < 8; j++) vv[j] = Vs[kk * PADQ + tx + 16 * j];
            #pragma unroll
            for (int i = 0; i < 4; i++)
                #pragma unroll
                for (int j = 0; j < 8; j++) Oacc[i][j] += p[i] * vv[j];
        }
    }

    float* Og = O + (size_t)(b * Tt + q0) * 1024 + h * 128;
    #pragma unroll
    for (int i = 0; i < 4; i++) {
        int r = ty + 16 * i;
        float linv = 1.0f / lrow[r];
        #pragma unroll
        for (int j = 0; j < 8; j++) {
            Og[(size_t)r * 1024 + tx + 16 * j] = Oacc[i][j] * linv;
        }
    }
}

// ---------------- launch ----------------
extern "C" void kernel_launch(void* const* d_in, const int* in_sizes, int n_in,
                              void* d_out, int out_size)
{
    const float* x        = (const float*)d_in[0];
    const float* q_kernel = (const float*)d_in[1];
    const float* k_kernel = (const float*)d_in[2];
    const float* v_kernel = (const float*)d_in[3];
    const float* out_kern = (const float*)d_in[4];
    const float* attn_sc  = (const float*)d_in[5];
    const float* mlp_sc   = (const float*)d_in[6];
    const float* gate_k   = (const float*)d_in[7];
    const float* up_k     = (const float*)d_in[8];
    const float* down_k   = (const float*)d_in[9];
    float* out = (float*)d_out;

    float *p_h, *p_q, *p_k, *p_v, *p_attn, *p_x2, *p_gate;
    cudaGetSymbolAddress((void**)&p_h,    g_h);
    cudaGetSymbolAddress((void**)&p_q,    g_q);
    cudaGetSymbolAddress((void**)&p_k,    g_k);
    cudaGetSymbolAddress((void**)&p_v,    g_v);
    cudaGetSymbolAddress((void**)&p_attn, g_attn);
    cudaGetSymbolAddress((void**)&p_x2,   g_x2);
    cudaGetSymbolAddress((void**)&p_gate, g_gate);

    const int ATTN_SMEM = (3 * 64 * PADQ + 64 * PADP + 3 * 64) * 4;
    cudaFuncSetAttribute(attn_kernel, cudaFuncAttributeMaxDynamicSharedMemorySize, ATTN_SMEM);
    cudaFuncSetAttribute(qkv_gemm_kernel, cudaFuncAttributeMaxDynamicSharedMemorySize, GEMM_SMEM);
    cudaFuncSetAttribute(tf32gemm_kernel<0>, cudaFuncAttributeMaxDynamicSharedMemorySize, GEMM_SMEM);
    cudaFuncSetAttribute(tf32gemm_kernel<1>, cudaFuncAttributeMaxDynamicSharedMemorySize, GEMM_SMEM);
    cudaFuncSetAttribute(tf32gemm_kernel<2>, cudaFuncAttributeMaxDynamicSharedMemorySize, GEMM_SMEM);

    // 1) h = rmsnorm(x, attn_scale)
    rmsnorm_kernel<<<Mrows, 256>>>(x, attn_sc, p_h);
    // 2) fused q/k/v projections
    qkv_gemm_kernel<<<dim3(16, 32), 256, GEMM_SMEM>>>(
        p_h, q_kernel, k_kernel, v_kernel, p_q, p_k, p_v, 1024);
    // 3) rope
    rope_kernel<<<Mrows, 256>>>(p_q, p_k);
    // 4) attention
    attn_kernel<<<dim3(Tt / 64, Hh, Bb), 256, ATTN_SMEM>>>(p_q, p_k, p_v, p_attn);
    // 5) out projection + residual
    tf32gemm_kernel<1><<<dim3(8, 32), 256, GEMM_SMEM>>>(p_attn, out_kern, x, p_x2, 1024, 1024);
    // 6) h = rmsnorm(x2, mlp_scale)
    rmsnorm_kernel<<<Mrows, 256>>>(p_x2, mlp_sc, p_h);
    // 7) gate, then up with fused SwiGLU epilogue
    tf32gemm_kernel<0><<<dim3(32, 32), 256, GEMM_SMEM>>>(p_h, gate_k, nullptr, p_gate, HIDm, 1024);
    tf32gemm_kernel<2><<<dim3(32, 32), 256, GEMM_SMEM>>>(p_h, up_k, p_gate, p_gate, HIDm, 1024);
    // 8) down + residual -> out
    tf32gemm_kernel<1><<<dim3(8, 32), 256, GEMM_SMEM>>>(p_gate, down_k, p_x2, out, 1024, HIDm);
}

// round 5
// speedup vs baseline: 3.1535x; 1.1820x over previous
#include <cuda_runtime.h>
#include <stdint.h>
#include <math.h>

#define Bb   2
#define Tt   2048
#define Cc   1024
#define Hh   8
#define KVh  4
#define Dd   128
#define WINs 512
#define HIDm 4096
#define Mrows (Bb*Tt)   // 4096

// ---------------- scratch ----------------
__device__ float g_h   [Mrows*Cc];
__device__ float g_q   [Mrows*Hh*Dd];
__device__ float g_k   [Mrows*KVh*Dd];
__device__ float g_v   [Mrows*KVh*Dd];
__device__ float g_attn[Mrows*Hh*Dd];
__device__ float g_x2  [Mrows*Cc];
__device__ float g_gate[Mrows*HIDm];
// rounded weights
__device__ float g_wq[1048576];
__device__ float g_wk[524288];
__device__ float g_wv[524288];
__device__ float g_wo[1048576];
__device__ float g_wg[4194304];
__device__ float g_wu[4194304];
__device__ float g_wd[4194304];

// ---------------- helpers ----------------
__device__ __forceinline__ float rnd32(float x) {
    uint32_t r; asm("cvt.rna.tf32.f32 %0, %1;" : "=r"(r) : "f"(x));
    return __uint_as_float(r);
}

__device__ __forceinline__ void mma_tf32(float* d, const uint32_t* a, const uint32_t* b) {
    asm volatile(
        "mma.sync.aligned.m16n8k8.row.col.f32.tf32.tf32.f32 "
        "{%0,%1,%2,%3},{%4,%5,%6,%7},{%8,%9},{%0,%1,%2,%3};"
        : "+f"(d[0]), "+f"(d[1]), "+f"(d[2]), "+f"(d[3])
        : "r"(a[0]), "r"(a[1]), "r"(a[2]), "r"(a[3]),
          "r"(b[0]), "r"(b[1]));
}

#define CP16(dst, src) \
    asm volatile("cp.async.cg.shared.global [%0], [%1], 16;" :: "r"(dst), "l"(src))
#define CP_COMMIT() asm volatile("cp.async.commit_group;")
#define CP_WAIT1()  asm volatile("cp.async.wait_group 1;")

// softcap: 50*tanh(s/50); poly path on FMA pipe for the (always-taken) small range
__device__ __forceinline__ float softcap50(float s) {
    float x = s * 0.02f;
    float x2 = x * x;
    float t;
    if (x2 <= 0.09f) {
        t = x * (1.0f + x2 * (-0.333333333f + x2 * (0.133333333f + x2 * (-0.053968254f))));
    } else {
        t = tanhf(x);
    }
    return 50.0f * t;
}

// ---------------- weight rounding ----------------
__global__ void roundcpy_kernel(const float4* __restrict__ s, float4* __restrict__ d, int n4)
{
    int i = blockIdx.x * blockDim.x + threadIdx.x;
    if (i < n4) {
        float4 v = s[i];
        v.x = rnd32(v.x); v.y = rnd32(v.y); v.z = rnd32(v.z); v.w = rnd32(v.w);
        d[i] = v;
    }
}

// ---------------- rmsnorm (output rounded to tf32) ----------------
__global__ void rmsnorm_kernel(const float* __restrict__ x,
                               const float* __restrict__ scale,
                               float* __restrict__ y)
{
    int row = blockIdx.x;
    const float4* xr = (const float4*)(x + (size_t)row * Cc);
    float4 v = xr[threadIdx.x];
    float ss = v.x*v.x + v.y*v.y + v.z*v.z + v.w*v.w;
    #pragma unroll
    for (int o = 16; o; o >>= 1) ss += __shfl_xor_sync(0xffffffffu, ss, o);
    __shared__ float wsum[8];
    if ((threadIdx.x & 31) == 0) wsum[threadIdx.x >> 5] = ss;
    __syncthreads();
    if (threadIdx.x < 8) {
        float t = wsum[threadIdx.x];
        #pragma unroll
        for (int o = 4; o; o >>= 1) t += __shfl_xor_sync(0xffu, t, o);
        if (threadIdx.x == 0) wsum[0] = t;
    }
    __syncthreads();
    float inv = rsqrtf(wsum[0] * (1.0f / Cc) + 1e-6f);
    float4 sc = ((const float4*)scale)[threadIdx.x];
    float4 o;
    o.x = rnd32(v.x * inv * (1.f + sc.x));
    o.y = rnd32(v.y * inv * (1.f + sc.y));
    o.z = rnd32(v.z * inv * (1.f + sc.z));
    o.w = rnd32(v.w * inv * (1.f + sc.w));
    ((float4*)(y + (size_t)row * Cc))[threadIdx.x] = o;
}

// ---------------- TF32 GEMM core (cp.async 3-stage) --------------------------
#define PA_A 20
#define PB_B 136
#define A_STG (128*PA_A)
#define B_STG (16*PB_B)
#define STG   (A_STG + B_STG)
#define GEMM_STAGES 3
#define GEMM_SMEM (GEMM_STAGES*STG*4)

template<int MODE>
__device__ __forceinline__ void gemm_tile(
    const float* __restrict__ A, const float* __restrict__ B,
    const float* __restrict__ Res, float* __restrict__ C,
    int NB, int NC, int K, int m0, int n0B, int n0C, float* sm)
{
    int tid  = threadIdx.x;
    int lane = tid & 31, warp = tid >> 5;
    int wm = (warp & 1) * 64;
    int wn = (warp >> 1) * 32;
    int g = lane >> 2, c = lane & 3;

    int la_m  = tid >> 1;
    int la_c0 = (tid & 1) * 2;
    int lb_k  = tid >> 4;
    int lb_j0 = (tid & 15) * 2;

    const float* Abase = A + (size_t)(m0 + la_m) * K + la_c0 * 4;
    const float* Bbase = B + (size_t)lb_k * NB + n0B + lb_j0 * 4;

    uint32_t smu = (uint32_t)__cvta_generic_to_shared(sm);
    uint32_t dA = smu + (uint32_t)(la_m * PA_A + la_c0 * 4) * 4u;
    uint32_t dB = smu + (uint32_t)(A_STG + lb_k * PB_B + lb_j0 * 4) * 4u;

    float acc[4][4][4];
    #pragma unroll
    for (int i = 0; i < 4; i++)
        #pragma unroll
        for (int j = 0; j < 4; j++)
            #pragma unroll
            for (int r = 0; r < 4; r++) acc[i][j][r] = 0.f;

    int ntiles = K >> 4;

    #pragma unroll
    for (int s = 0; s < GEMM_STAGES - 1; s++) {
        uint32_t off = (uint32_t)(s * STG) * 4u;
        const float* as = Abase + s * 16;
        CP16(dA + off, as);
        CP16(dA + off + 16, as + 4);
        const float* bs = Bbase + (size_t)s * 16 * NB;
        CP16(dB + off, bs);
        CP16(dB + off + 16, bs + 4);
        CP_COMMIT();
    }

    for (int kt = 0; kt < ntiles; kt++) {
        CP_WAIT1();
        __syncthreads();

        int pf = kt + GEMM_STAGES - 1;
        if (pf < ntiles) {
            int s = pf % GEMM_STAGES;
            uint32_t off = (uint32_t)(s * STG) * 4u;
            const float* as = Abase + pf * 16;
            CP16(dA + off, as);
            CP16(dA + off + 16, as + 4);
            const float* bs = Bbase + (size_t)pf * 16 * NB;
            CP16(dB + off, bs);
            CP16(dB + off + 16, bs + 4);
        }
        CP_COMMIT();

        const float* sA = sm + (kt % GEMM_STAGES) * STG;
        const float* sB = sA + A_STG;
        #pragma unroll
        for (int ks = 0; ks < 2; ks++) {
            uint32_t bf[4][2];
            #pragma unroll
            for (int nt = 0; nt < 4; nt++) {
                int col = wn + nt * 8 + g;
                bf[nt][0] = __float_as_uint(sB[(ks * 8 + c) * PB_B + col]);
                bf[nt][1] = __float_as_uint(sB[(ks * 8 + c + 4) * PB_B + col]);
            }
            #pragma unroll
            for (int mt = 0; mt < 4; mt++) {
                int row = wm + mt * 16 + g;
                uint32_t af[4];
                af[0] = __float_as_uint(sA[row * PA_A + ks * 8 + c]);
                af[1] = __float_as_uint(sA[(row + 8) * PA_A + ks * 8 + c]);
                af[2] = __float_as_uint(sA[row * PA_A + ks * 8 + c + 4]);
                af[3] = __float_as_uint(sA[(row + 8) * PA_A + ks * 8 + c + 4]);
                #pragma unroll
                for (int nt = 0; nt < 4; nt++)
                    mma_tf32(acc[mt][nt], af, bf[nt]);
            }
        }
    }

    #pragma unroll
    for (int mt = 0; mt < 4; mt++) {
        int r0 = m0 + wm + mt * 16 + g;
        #pragma unroll
        for (int nt = 0; nt < 4; nt++) {
            int cl = n0C + wn + nt * 8 + 2 * c;
            #pragma unroll
            for (int half = 0; half < 2; half++) {
                int rr = r0 + half * 8;
                float v0 = acc[mt][nt][half * 2 + 0];
                float v1 = acc[mt][nt][half * 2 + 1];
                size_t idx = (size_t)rr * NC + cl;
                if (MODE == 1) {
                    v0 += Res[idx];
                    v1 += Res[idx + 1];
                } else if (MODE == 2) {
                    float gt0 = Res[idx], gt1 = Res[idx + 1];
                    v0 = rnd32(v0 * gt0 / (1.f + expf(-gt0)));
                    v1 = rnd32(v1 * gt1 / (1.f + expf(-gt1)));
                }
                *(float2*)(C + idx) = make_float2(v0, v1);
            }
        }
    }
}

template<int MODE>
__global__ __launch_bounds__(256, 2) void tf32gemm_kernel(
    const float* __restrict__ A, const float* __restrict__ B,
    const float* __restrict__ Res, float* __restrict__ C, int N, int K)
{
    extern __shared__ float sm[];
    gemm_tile<MODE>(A, B, Res, C, N, N, K,
                    blockIdx.y * 128, blockIdx.x * 128, blockIdx.x * 128, sm);
}

__global__ __launch_bounds__(256, 2) void qkv_gemm_kernel(
    const float* __restrict__ A,
    const float* __restrict__ Bq, const float* __restrict__ Bk,
    const float* __restrict__ Bv,
    float* __restrict__ Cq, float* __restrict__ Ck, float* __restrict__ Cv,
    int K)
{
    extern __shared__ float sm[];
    int nb = blockIdx.x;
    int m0 = blockIdx.y * 128;
    if (nb < 8)
        gemm_tile<0>(A, Bq, nullptr, Cq, 1024, 1024, K, m0, nb * 128, nb * 128, sm);
    else if (nb < 12)
        gemm_tile<0>(A, Bk, nullptr, Ck, 512, 512, K, m0, (nb - 8) * 128, (nb - 8) * 128, sm);
    else
        gemm_tile<0>(A, Bv, nullptr, Cv, 512, 512, K, m0, (nb - 12) * 128, (nb - 12) * 128, sm);
}

// ---------------- RoPE (+ q prescale, tf32 round) ----------------
__global__ void rope_kernel(float* __restrict__ q, float* __restrict__ k)
{
    int row = blockIdx.x;
    int t = row & (Tt - 1);
    const float qscale = 0.08838834764831845f;
    __shared__ float s_sin[64], s_cos[64];
    if (threadIdx.x < 64) {
        float inv = expf(-logf(10000.0f) * (2.0f * threadIdx.x) / 128.0f);
        float ang = (float)t * inv;
        s_sin[threadIdx.x] = sinf(ang);
        s_cos[threadIdx.x] = cosf(ang);
    }
    __syncthreads();
    for (int p = threadIdx.x; p < 512; p += 256) {
        int head = p >> 6, i = p & 63;
        float* base = q + (size_t)row * 1024 + head * 128;
        float x1 = base[i], x2 = base[i + 64];
        float s = s_sin[i], c = s_cos[i];
        base[i]      = rnd32((x1 * c - x2 * s) * qscale);
        base[i + 64] = rnd32((x2 * c + x1 * s) * qscale);
    }
    for (int p = threadIdx.x; p < 256; p += 256) {
        int head = p >> 6, i = p & 63;
        float* base = k + (size_t)row * 512 + head * 128;
        float x1 = base[i], x2 = base[i + 64];
        float s = s_sin[i], c = s_cos[i];
        base[i]      = rnd32(x1 * c - x2 * s);
        base[i + 64] = rnd32(x2 * c + x1 * s);
    }
}

// ---------------- attention: TF32 MMA flash, swizzled smem -------------------
// smem (floats): Qs[64][128] @0, Kt[128][64] @8192, Vs[64][128] @16384,
//                Ps[64][64] @24576, rmax[2][64] @28672, rsum[2][64] @28800
#define ATTN_SMEM (28928 * 4)
__global__ __launch_bounds__(256, 2) void attn_kernel(
    const float* __restrict__ Q, const float* __restrict__ K,
    const float* __restrict__ V, float* __restrict__ O)
{
    extern __shared__ float sm[];
    float* Qs = sm;
    float* Kt = sm + 8192;
    float* Vs = sm + 16384;
    float* Ps = sm + 24576;
    float* rmax = sm + 28672;
    float* rsum = sm + 28800;

    int qb = blockIdx.x, h = blockIdx.y, b = blockIdx.z;
    int q0 = qb * 64;
    int tid = threadIdx.x, lane = tid & 31, warp = tid >> 5;
    int wq = warp >> 1, wn = warp & 1, g = lane >> 2, c = lane & 3;

    // Q tile (pre-scaled + tf32-rounded by rope)
    const float* Qg = Q + (size_t)(b * Tt + q0) * 1024 + h * 128;
    #pragma unroll
    for (int p = 0; p < 8; p++) {
        int idx = tid + p * 256;
        int row = idx >> 5, c4 = (idx & 31) * 4;
        float4 v = *(const float4*)(Qg + (size_t)row * 1024 + c4);
        *(float4*)(Qs + row * 128 + (c4 ^ ((row & 7) * 4))) = v;
    }

    int r0 = 16 * wq + g;
    int r1 = r0 + 8;
    float rm0 = -1e30f, rm1 = -1e30f, rl0 = 0.f, rl1 = 0.f;
    float Oacc[8][4];
    #pragma unroll
    for (int i = 0; i < 8; i++)
        #pragma unroll
        for (int j = 0; j < 4; j++) Oacc[i][j] = 0.f;

    int kvh = h & 3;
    const float* Kg = K + (size_t)b * Tt * 512 + kvh * 128;
    const float* Vg = V + (size_t)b * Tt * 512 + kvh * 128;

    int lkey = tid >> 2;
    int ldq  = (tid & 3) * 4;

    int jlo = (qb >= 8) ? qb - 8 : 0;
    for (int jt = jlo; jt <= qb; jt++) {
        int k0 = jt * 64;
        __syncthreads();
        // K -> Kt (transposed, pre-rounded by rope)
        #pragma unroll
        for (int p = 0; p < 8; p++) {
            int d0 = ldq + p * 16;
            float4 kv = *(const float4*)(Kg + (size_t)(k0 + lkey) * 512 + d0);
            Kt[(d0 + 0) * 64 + (lkey ^ 0)]  = kv.x;
            Kt[(d0 + 1) * 64 + (lkey ^ 8)]  = kv.y;
            Kt[(d0 + 2) * 64 + (lkey ^ 16)] = kv.z;
            Kt[(d0 + 3) * 64 + (lkey ^ 24)] = kv.w;
        }
        // V -> Vs (rounded here)
        #pragma unroll
        for (int p = 0; p < 8; p++) {
            int d0 = ldq + p * 16;
            float4 vv = *(const float4*)(Vg + (size_t)(k0 + lkey) * 512 + d0);
            vv.x = rnd32(vv.x); vv.y = rnd32(vv.y);
            vv.z = rnd32(vv.z); vv.w = rnd32(vv.w);
            *(float4*)(Vs + lkey * 128 + (d0 ^ ((lkey & 3) * 8))) = vv;
        }
        __syncthreads();

        // ---- S = Q @ K^T ----
        float sacc[4][4];
        #pragma unroll
        for (int i = 0; i < 4; i++)
            #pragma unroll
            for (int j = 0; j < 4; j++) sacc[i][j] = 0.f;
        int sa = g * 4;
        #pragma unroll
        for (int ks = 0; ks < 16; ks++) {
            int kk = ks * 8;
            uint32_t af[4];
            af[0] = __float_as_uint(Qs[r0 * 128 + ((kk + c)     ^ sa)]);
            af[1] = __float_as_uint(Qs[r1 * 128 + ((kk + c)     ^ sa)]);
            af[2] = __float_as_uint(Qs[r0 * 128 + ((kk + c + 4) ^ sa)]);
            af[3] = __float_as_uint(Qs[r1 * 128 + ((kk + c + 4) ^ sa)]);
            #pragma unroll
            for (int nt = 0; nt < 4; nt++) {
                int col = wn * 32 + nt * 8 + g;
                uint32_t bf[2];
                bf[0] = __float_as_uint(Kt[(kk + c) * 64     + (col ^ (8 * c))]);
                bf[1] = __float_as_uint(Kt[(kk + c + 4) * 64 + (col ^ (8 * c))]);
                mma_tf32(sacc[nt], af, bf);
            }
        }

        // ---- softcap + mask ----
        float pm0 = -INFINITY, pm1 = -INFINITY;
        int qt0 = q0 + r0, qt1 = q0 + r1;
        #pragma unroll
        for (int nt = 0; nt < 4; nt++) {
            #pragma unroll
            for (int e = 0; e < 4; e++) {
                int col = wn * 32 + nt * 8 + 2 * c + (e & 1);
                int ktg = k0 + col;
                int qt = (e >> 1) ? qt1 : qt0;
                float sv = softcap50(sacc[nt][e]);
                bool ok = (ktg <= qt) && (qt - ktg < WINs);
                sv = ok ? sv : -INFINITY;
                sacc[nt][e] = sv;
                if (e >> 1) pm1 = fmaxf(pm1, sv); else pm0 = fmaxf(pm0, sv);
            }
        }
        pm0 = fmaxf(pm0, __shfl_xor_sync(0xffffffffu, pm0, 1));
        pm0 = fmaxf(pm0, __shfl_xor_sync(0xffffffffu, pm0, 2));
        pm1 = fmaxf(pm1, __shfl_xor_sync(0xffffffffu, pm1, 1));
        pm1 = fmaxf(pm1, __shfl_xor_sync(0xffffffffu, pm1, 2));
        if (c == 0) { rmax[wn * 64 + r0] = pm0; rmax[wn * 64 + r1] = pm1; }
        __syncthreads();

        float mn0 = fmaxf(rm0, fmaxf(rmax[r0], rmax[64 + r0]));
        float mn1 = fmaxf(rm1, fmaxf(rmax[r1], rmax[64 + r1]));
        float al0 = __expf(rm0 - mn0); rm0 = mn0;
        float al1 = __expf(rm1 - mn1); rm1 = mn1;

        float ps0 = 0.f, ps1 = 0.f;
        #pragma unroll
        for (int nt = 0; nt < 4; nt++) {
            float p00 = rnd32(__expf(sacc[nt][0] - mn0));
            float p01 = rnd32(__expf(sacc[nt][1] - mn0));
            float p10 = rnd32(__expf(sacc[nt][2] - mn1));
            float p11 = rnd32(__expf(sacc[nt][3] - mn1));
            ps0 += p00 + p01;
            ps1 += p10 + p11;
            int colb = wn * 32 + nt * 8 + 2 * c;
            *(float2*)(Ps + r0 * 64 + (colb ^ sa)) = make_float2(p00, p01);
            *(float2*)(Ps + r1 * 64 + (colb ^ sa)) = make_float2(p10, p11);
        }
        ps0 += __shfl_xor_sync(0xffffffffu, ps0, 1);
        ps0 += __shfl_xor_sync(0xffffffffu, ps0, 2);
        ps1 += __shfl_xor_sync(0xffffffffu, ps1, 1);
        ps1 += __shfl_xor_sync(0xffffffffu, ps1, 2);
        if (c == 0) { rsum[wn * 64 + r0] = ps0; rsum[wn * 64 + r1] = ps1; }

        // rescale O
        #pragma unroll
        for (int i = 0; i < 8; i++) {
            Oacc[i][0] *= al0; Oacc[i][1] *= al0;
            Oacc[i][2] *= al1; Oacc[i][3] *= al1;
        }
        __syncthreads();
        rl0 = rl0 * al0 + rsum[r0] + rsum[64 + r0];
        rl1 = rl1 * al1 + rsum[r1] + rsum[64 + r1];

        // ---- O += P @ V ----
        #pragma unroll
        for (int ks = 0; ks < 8; ks++) {
            int kk = ks * 8;
            uint32_t af[4];
            af[0] = __float_as_uint(Ps[r0 * 64 + ((kk + c)     ^ sa)]);
            af[1] = __float_as_uint(Ps[r1 * 64 + ((kk + c)     ^ sa)]);
            af[2] = __float_as_uint(Ps[r0 * 64 + ((kk + c + 4) ^ sa)]);
            af[3] = __float_as_uint(Ps[r1 * 64 + ((kk + c + 4) ^ sa)]);
            #pragma unroll
            for (int nt = 0; nt < 8; nt++) {
                int col = wn * 64 + nt * 8 + g;
                uint32_t bf[2];
                bf[0] = __float_as_uint(Vs[(kk + c) * 128     + (col ^ (8 * c))]);
                bf[1] = __float_as_uint(Vs[(kk + c + 4) * 128 + (col ^ (8 * c))]);
                mma_tf32(Oacc[nt], af, bf);
            }
        }
    }

    // write out (rounded: feeds out-proj GEMM)
    float li0 = 1.f / rl0, li1 = 1.f / rl1;
    float* Og = O + (size_t)(b * Tt + q0) * 1024 + h * 128;
    #pragma unroll
    for (int nt = 0; nt < 8; nt++) {
        int col = wn * 64 + nt * 8 + 2 * c;
        *(float2*)(Og + (size_t)r0 * 1024 + col) =
            make_float2(rnd32(Oacc[nt][0] * li0), rnd32(Oacc[nt][1] * li0));
        *(float2*)(Og + (size_t)r1 * 1024 + col) =
            make_float2(rnd32(Oacc[nt][2] * li1), rnd32(Oacc[nt][3] * li1));
    }
}

// ---------------- launch ----------------
extern "C" void kernel_launch(void* const* d_in, const int* in_sizes, int n_in,
                              void* d_out, int out_size)
{
    const float* x        = (const float*)d_in[0];
    const float* q_kernel = (const float*)d_in[1];
    const float* k_kernel = (const float*)d_in[2];
    const float* v_kernel = (const float*)d_in[3];
    const float* out_kern = (const float*)d_in[4];
    const float* attn_sc  = (const float*)d_in[5];
    const float* mlp_sc   = (const float*)d_in[6];
    const float* gate_k   = (const float*)d_in[7];
    const float* up_k     = (const float*)d_in[8];
    const float* down_k   = (const float*)d_in[9];
    float* out = (float*)d_out;

    float *p_h, *p_q, *p_k, *p_v, *p_attn, *p_x2, *p_gate;
    float *w_q, *w_k, *w_v, *w_o, *w_g, *w_u, *w_d;
    cudaGetSymbolAddress((void**)&p_h,    g_h);
    cudaGetSymbolAddress((void**)&p_q,    g_q);
    cudaGetSymbolAddress((void**)&p_k,    g_k);
    cudaGetSymbolAddress((void**)&p_v,    g_v);
    cudaGetSymbolAddress((void**)&p_attn, g_attn);
    cudaGetSymbolAddress((void**)&p_x2,   g_x2);
    cudaGetSymbolAddress((void**)&p_gate, g_gate);
    cudaGetSymbolAddress((void**)&w_q,    g_wq);
    cudaGetSymbolAddress((void**)&w_k,    g_wk);
    cudaGetSymbolAddress((void**)&w_v,    g_wv);
    cudaGetSymbolAddress((void**)&w_o,    g_wo);
    cudaGetSymbolAddress((void**)&w_g,    g_wg);
    cudaGetSymbolAddress((void**)&w_u,    g_wu);
    cudaGetSymbolAddress((void**)&w_d,    g_wd);

    cudaFuncSetAttribute(attn_kernel, cudaFuncAttributeMaxDynamicSharedMemorySize, ATTN_SMEM);
    cudaFuncSetAttribute(qkv_gemm_kernel, cudaFuncAttributeMaxDynamicSharedMemorySize, GEMM_SMEM);
    cudaFuncSetAttribute(tf32gemm_kernel<0>, cudaFuncAttributeMaxDynamicSharedMemorySize, GEMM_SMEM);
    cudaFuncSetAttribute(tf32gemm_kernel<1>, cudaFuncAttributeMaxDynamicSharedMemorySize, GEMM_SMEM);
    cudaFuncSetAttribute(tf32gemm_kernel<2>, cudaFuncAttributeMaxDynamicSharedMemorySize, GEMM_SMEM);

    // 0) round weights to tf32 (removes truncation bias in MMAs)
    roundcpy_kernel<<<1024, 256>>>((const float4*)q_kernel, (float4*)w_q, 262144);
    roundcpy_kernel<<<512,  256>>>((const float4*)k_kernel, (float4*)w_k, 131072);
    roundcpy_kernel<<<512,  256>>>((const float4*)v_kernel, (float4*)w_v, 131072);
    roundcpy_kernel<<<1024, 256>>>((const float4*)out_kern, (float4*)w_o, 262144);
    roundcpy_kernel<<<4096, 256>>>((const float4*)gate_k,   (float4*)w_g, 1048576);
    roundcpy_kernel<<<4096, 256>>>((const float4*)up_k,     (float4*)w_u, 1048576);
    roundcpy_kernel<<<4096, 256>>>((const float4*)down_k,   (float4*)w_d, 1048576);

    // 1) h = rmsnorm(x, attn_scale)
    rmsnorm_kernel<<<Mrows, 256>>>(x, attn_sc, p_h);
    // 2) fused q/k/v projections
    qkv_gemm_kernel<<<dim3(16, 32), 256, GEMM_SMEM>>>(
        p_h, w_q, w_k, w_v, p_q, p_k, p_v, 1024);
    // 3) rope (+ q prescale, tf32 rounding)
    rope_kernel<<<Mrows, 256>>>(p_q, p_k);
    // 4) attention (tf32 MMA flash)
    attn_kernel<<<dim3(Tt / 64, Hh, Bb), 256, ATTN_SMEM>>>(p_q, p_k, p_v, p_attn);
    // 5) out projection + residual
    tf32gemm_kernel<1><<<dim3(8, 32), 256, GEMM_SMEM>>>(p_attn, w_o, x, p_x2, 1024, 1024);
    // 6) h = rmsnorm(x2, mlp_scale)
    rmsnorm_kernel<<<Mrows, 256>>>(p_x2, mlp_sc, p_h);
    // 7) gate, then up with fused SwiGLU epilogue
    tf32gemm_kernel<0><<<dim3(32, 32), 256, GEMM_SMEM>>>(p_h, w_g, nullptr, p_gate, HIDm, 1024);
    tf32gemm_kernel<2><<<dim3(32, 32), 256, GEMM_SMEM>>>(p_h, w_u, p_gate, p_gate, HIDm, 1024);
    // 8) down + residual -> out
    tf32gemm_kernel<1><<<dim3(8, 32), 256, GEMM_SMEM>>>(p_gate, w_d, p_x2, out, 1024, HIDm);
}

// round 7
// speedup vs baseline: 5.5951x; 1.7742x over previous
#include <cuda_runtime.h>
#include <cuda_fp16.h>
#include <stdint.h>
#include <math.h>

#define Bb   2
#define Tt   2048
#define Cc   1024
#define Hh   8
#define KVh  4
#define Dd   128
#define WINs 512
#define HIDm 4096
#define Mrows (Bb*Tt)   // 4096

// ---------------- scratch ----------------
__device__ __half g_h   [Mrows*Cc];        // rmsnorm out (fp16 A operand)
__device__ float  g_q   [Mrows*Hh*Dd];
__device__ float  g_k   [Mrows*KVh*Dd];
__device__ float  g_v   [Mrows*KVh*Dd];
__device__ __half g_attnh[Mrows*Hh*Dd];    // attention out (fp16 A operand)
__device__ float  g_x2  [Mrows*Cc];
__device__ float  g_gate[Mrows*HIDm];      // gate pre-activation (fp32)
__device__ __half g_act [Mrows*HIDm];      // silu(gate)*up (fp16 A operand)
// transposed+converted weights [N][K] fp16
__device__ __half g_wq[1048576];
__device__ __half g_wk[524288];
__device__ __half g_wv[524288];
__device__ __half g_wo[1048576];
__device__ __half g_wg[4194304];
__device__ __half g_wu[4194304];
__device__ __half g_wd[4194304];

// ---------------- helpers ----------------
__device__ __forceinline__ float rnd32(float x) {
    uint32_t r; asm("cvt.rna.tf32.f32 %0, %1;" : "=r"(r) : "f"(x));
    return __uint_as_float(r);
}
__device__ __forceinline__ void mma_tf32(float* d, const uint32_t* a, const uint32_t* b) {
    asm volatile(
        "mma.sync.aligned.m16n8k8.row.col.f32.tf32.tf32.f32 "
        "{%0,%1,%2,%3},{%4,%5,%6,%7},{%8,%9},{%0,%1,%2,%3};"
        : "+f"(d[0]), "+f"(d[1]), "+f"(d[2]), "+f"(d[3])
        : "r"(a[0]), "r"(a[1]), "r"(a[2]), "r"(a[3]),
          "r"(b[0]), "r"(b[1]));
}
__device__ __forceinline__ void mma_f16(float* d, const uint32_t* a, const uint32_t* b) {
    asm volatile(
        "mma.sync.aligned.m16n8k16.row.col.f32.f16.f16.f32 "
        "{%0,%1,%2,%3},{%4,%5,%6,%7},{%8,%9},{%0,%1,%2,%3};"
        : "+f"(d[0]), "+f"(d[1]), "+f"(d[2]), "+f"(d[3])
        : "r"(a[0]), "r"(a[1]), "r"(a[2]), "r"(a[3]),
          "r"(b[0]), "r"(b[1]));
}

#define CP16(dst, src) \
    asm volatile("cp.async.cg.shared.global [%0], [%1], 16;" :: "r"(dst), "l"(src))
#define CP_COMMIT() asm volatile("cp.async.commit_group;")

// softcap: 50*tanh(s/50)
__device__ __forceinline__ float softcap50(float s) {
    float x = s * 0.02f;
    float x2 = x * x;
    float t;
    if (x2 <= 0.09f) {
        t = x * (1.0f + x2 * (-0.333333333f + x2 * (0.133333333f + x2 * (-0.053968254f))));
    } else {
        t = tanhf(x);
    }
    return 50.0f * t;
}

// ---------------- weight transpose + fp16 convert: in[K][N] -> out[N][K] -----
__global__ void transpose_cvt_kernel(const float* __restrict__ in,
                                     __half* __restrict__ out, int K, int N)
{
    __shared__ float t[32][33];
    int n0 = blockIdx.x * 32, k0 = blockIdx.y * 32;
    int tx = threadIdx.x & 31, ty = threadIdx.x >> 5;   // 32 x 8
    #pragma unroll
    for (int i = 0; i < 4; i++) {
        int k = k0 + ty + i * 8;
        t[ty + i * 8][tx] = in[(size_t)k * N + n0 + tx];
    }
    __syncthreads();
    #pragma unroll
    for (int i = 0; i < 4; i++) {
        int n = n0 + ty + i * 8;
        out[(size_t)n * K + k0 + tx] = __float2half_rn(t[tx][ty + i * 8]);
    }
}

// ---------------- rmsnorm -> fp16 ----------------
__global__ void rmsnorm_h_kernel(const float* __restrict__ x,
                                 const float* __restrict__ scale,
                                 __half* __restrict__ y)
{
    int row = blockIdx.x;
    const float4* xr = (const float4*)(x + (size_t)row * Cc);
    float4 v = xr[threadIdx.x];
    float ss = v.x*v.x + v.y*v.y + v.z*v.z + v.w*v.w;
    #pragma unroll
    for (int o = 16; o; o >>= 1) ss += __shfl_xor_sync(0xffffffffu, ss, o);
    __shared__ float wsum[8];
    if ((threadIdx.x & 31) == 0) wsum[threadIdx.x >> 5] = ss;
    __syncthreads();
    if (threadIdx.x < 8) {
        float t = wsum[threadIdx.x];
        #pragma unroll
        for (int o = 4; o; o >>= 1) t += __shfl_xor_sync(0xffu, t, o);
        if (threadIdx.x == 0) wsum[0] = t;
    }
    __syncthreads();
    float inv = rsqrtf(wsum[0] * (1.0f / Cc) + 1e-6f);
    float4 sc = ((const float4*)scale)[threadIdx.x];
    __half2 h0 = __floats2half2_rn(v.x * inv * (1.f + sc.x), v.y * inv * (1.f + sc.y));
    __half2 h1 = __floats2half2_rn(v.z * inv * (1.f + sc.z), v.w * inv * (1.f + sc.w));
    uint2 u = make_uint2(*(uint32_t*)&h0, *(uint32_t*)&h1);
    *(uint2*)(y + (size_t)row * Cc + threadIdx.x * 4) = u;
}

// ---------------- FP16 GEMM (m16n8k16, cp.async 3-stage) ---------------------
// A[M,K] fp16 row-major, Bt[N,K] fp16 (=B^T). 128x128 tile, BK=32.
// MODE 0: C=acc (float), 1: C=acc+Res (float), 2: C=silu(Res)*acc (half)
#define PAH 40                 // smem pitch in halves (80 B)
#define A_HBYTES (128*PAH*2)   // 10240
#define STAGE_HB (2*A_HBYTES)  // 20480
#define H_STAGES 3
#define HGEMM_SMEM (H_STAGES*STAGE_HB)   // 61440

template<int MODE, typename OT>
__device__ __forceinline__ void hgemm_tile(
    const __half* __restrict__ A, const __half* __restrict__ Bt,
    const float* __restrict__ Res, OT* __restrict__ C,
    int NC, int K, int m0, int n0)
{
    extern __shared__ __half smh[];
    uint32_t smb;
    asm("{ .reg .u64 t; cvta.to.shared.u64 t, %1; cvt.u32.u64 %0, t; }"
        : "=r"(smb) : "l"(smh));

    int tid  = threadIdx.x;
    int lane = tid & 31, warp = tid >> 5;
    int wm = (warp & 1) * 64;
    int wn = (warp >> 1) * 32;
    int g = lane >> 2, c = lane & 3;

    const __half* Ag = A  + (size_t)m0 * K;
    const __half* Bg = Bt + (size_t)n0 * K;

    float acc[4][4][4];
    #pragma unroll
    for (int i = 0; i < 4; i++)
        #pragma unroll
        for (int j = 0; j < 4; j++)
            #pragma unroll
            for (int r = 0; r < 4; r++) acc[i][j][r] = 0.f;

    int ntiles = K >> 5;   // BK=32 halves

    int lr = tid >> 2, lc = tid & 3;   // loader: row, 16B-chunk
    auto load_stage = [&](int s, int kc) {
        uint32_t base = smb + s * STAGE_HB;
        // A: rows 0..127 (two halves of 64 rows per thread-pass)
        #pragma unroll
        for (int i = 0; i < 2; i++) {
            int r = lr + i * 64;
            CP16(base + r * 80 + lc * 16, Ag + (size_t)r * K + kc * 32 + lc * 8);
        }
        uint32_t bb = base + A_HBYTES;
        #pragma unroll
        for (int i = 0; i < 2; i++) {
            int r = lr + i * 64;
            CP16(bb + r * 80 + lc * 16, Bg + (size_t)r * K + kc * 32 + lc * 8);
        }
    };

    load_stage(0, 0); CP_COMMIT();
    load_stage(1, 1); CP_COMMIT();

    for (int kt = 0; kt < ntiles; kt++) {
        asm volatile("cp.async.wait_group 1;");
        __syncthreads();

        int pf = kt + H_STAGES - 1;
        if (pf < ntiles) load_stage(pf % H_STAGES, pf);
        CP_COMMIT();

        const __half* sA = smh + (size_t)(kt % H_STAGES) * (STAGE_HB / 2);
        const __half* sB = sA + A_HBYTES / 2;
        #pragma unroll
        for (int ks = 0; ks < 2; ks++) {
            int kb = ks * 16;
            uint32_t bf[4][2];
            #pragma unroll
            for (int nt = 0; nt < 4; nt++) {
                int col = wn + nt * 8 + g;
                bf[nt][0] = *(const uint32_t*)&sB[col * PAH + kb + 2 * c];
                bf[nt][1] = *(const uint32_t*)&sB[col * PAH + kb + 2 * c + 8];
            }
            #pragma unroll
            for (int mt = 0; mt < 4; mt++) {
                int row = wm + mt * 16 + g;
                uint32_t af[4];
                af[0] = *(const uint32_t*)&sA[row * PAH + kb + 2 * c];
                af[1] = *(const uint32_t*)&sA[(row + 8) * PAH + kb + 2 * c];
                af[2] = *(const uint32_t*)&sA[row * PAH + kb + 2 * c + 8];
                af[3] = *(const uint32_t*)&sA[(row + 8) * PAH + kb + 2 * c + 8];
                #pragma unroll
                for (int nt = 0; nt < 4; nt++)
                    mma_f16(acc[mt][nt], af, bf[nt]);
            }
        }
    }

    // epilogue
    #pragma unroll
    for (int mt = 0; mt < 4; mt++) {
        int r0 = m0 + wm + mt * 16 + g;
        #pragma unroll
        for (int nt = 0; nt < 4; nt++) {
            int cl = n0 + wn + nt * 8 + 2 * c;
            #pragma unroll
            for (int half_i = 0; half_i < 2; half_i++) {
                int rr = r0 + half_i * 8;
                float v0 = acc[mt][nt][half_i * 2 + 0];
                float v1 = acc[mt][nt][half_i * 2 + 1];
                size_t idx = (size_t)rr * NC + cl;
                if (MODE == 0) {
                    *(float2*)((float*)C + idx) = make_float2(v0, v1);
                } else if (MODE == 1) {
                    v0 += Res[idx]; v1 += Res[idx + 1];
                    *(float2*)((float*)C + idx) = make_float2(v0, v1);
                } else {
                    float g0 = Res[idx], g1 = Res[idx + 1];
                    v0 *= g0 / (1.f + expf(-g0));
                    v1 *= g1 / (1.f + expf(-g1));
                    *(__half2*)((__half*)C + idx) = __floats2half2_rn(v0, v1);
                }
            }
        }
    }
}

template<int MODE, typename OT>
__global__ __launch_bounds__(256, 2) void hgemm_kernel(
    const __half* __restrict__ A, const __half* __restrict__ Bt,
    const float* __restrict__ Res, OT* __restrict__ C, int N, int K)
{
    hgemm_tile<MODE, OT>(A, Bt, Res, C, N, K, blockIdx.y * 128, blockIdx.x * 128);
}

// fused QKV: grid.x = 16 (q 0-7, k 8-11, v 12-15)
__global__ __launch_bounds__(256, 2) void qkv_h_kernel(
    const __half* __restrict__ A,
    const __half* __restrict__ Bq, const __half* __restrict__ Bk,
    const __half* __restrict__ Bv,
    float* __restrict__ Cq, float* __restrict__ Ck, float* __restrict__ Cv,
    int K)
{
    int nb = blockIdx.x, m0 = blockIdx.y * 128;
    if (nb < 8)
        hgemm_tile<0, float>(A, Bq, nullptr, Cq, 1024, K, m0, nb * 128);
    else if (nb < 12)
        hgemm_tile<0, float>(A, Bk + (size_t)(nb - 8) * 128 * K, nullptr,
                             Ck + (nb - 8) * 128, 512, K, m0, 0);
    else
        hgemm_tile<0, float>(A, Bv + (size_t)(nb - 12) * 128 * K, nullptr,
                             Cv + (nb - 12) * 128, 512, K, m0, 0);
}

// ---------------- RoPE (+ q prescale, tf32 round) ----------------
__global__ void rope_kernel(float* __restrict__ q, float* __restrict__ k)
{
    int row = blockIdx.x;
    int t = row & (Tt - 1);
    const float qscale = 0.08838834764831845f;
    __shared__ float s_sin[64], s_cos[64];
    if (threadIdx.x < 64) {
        float inv = expf(-logf(10000.0f) * (2.0f * threadIdx.x) / 128.0f);
        float ang = (float)t * inv;
        s_sin[threadIdx.x] = sinf(ang);
        s_cos[threadIdx.x] = cosf(ang);
    }
    __syncthreads();
    for (int p = threadIdx.x; p < 512; p += 256) {
        int head = p >> 6, i = p & 63;
        float* base = q + (size_t)row * 1024 + head * 128;
        float x1 = base[i], x2 = base[i + 64];
        float s = s_sin[i], c = s_cos[i];
        base[i]      = rnd32((x1 * c - x2 * s) * qscale);
        base[i + 64] = rnd32((x2 * c + x1 * s) * qscale);
    }
    for (int p = threadIdx.x; p < 256; p += 256) {
        int head = p >> 6, i = p & 63;
        float* base = k + (size_t)row * 512 + head * 128;
        float x1 = base[i], x2 = base[i + 64];
        float s = s_sin[i], c = s_cos[i];
        base[i]      = rnd32(x1 * c - x2 * s);
        base[i + 64] = rnd32(x2 * c + x1 * s);
    }
}

// ---------------- attention: TF32 MMA flash (R5), fp16 output ----------------
#define ATTN_SMEM (28928 * 4)
__global__ __launch_bounds__(256, 2) void attn_kernel(
    const float* __restrict__ Q, const float* __restrict__ K,
    const float* __restrict__ V, __half* __restrict__ O)
{
    extern __shared__ float sm[];
    float* Qs = sm;
    float* Kt = sm + 8192;
    float* Vs = sm + 16384;
    float* Ps = sm + 24576;
    float* rmax = sm + 28672;
    float* rsum = sm + 28800;

    int qb = blockIdx.x, h = blockIdx.y, b = blockIdx.z;
    int q0 = qb * 64;
    int tid = threadIdx.x, lane = tid & 31, warp = tid >> 5;
    int wq = warp >> 1, wn = warp & 1, g = lane >> 2, c = lane & 3;

    const float* Qg = Q + (size_t)(b * Tt + q0) * 1024 + h * 128;
    #pragma unroll
    for (int p = 0; p < 8; p++) {
        int idx = tid + p * 256;
        int row = idx >> 5, c4 = (idx & 31) * 4;
        float4 v = *(const float4*)(Qg + (size_t)row * 1024 + c4);
        *(float4*)(Qs + row * 128 + (c4 ^ ((row & 7) * 4))) = v;
    }

    int r0 = 16 * wq + g;
    int r1 = r0 + 8;
    float rm0 = -1e30f, rm1 = -1e30f, rl0 = 0.f, rl1 = 0.f;
    float Oacc[8][4];
    #pragma unroll
    for (int i = 0; i < 8; i++)
        #pragma unroll
        for (int j = 0; j < 4; j++) Oacc[i][j] = 0.f;

    int kvh = h & 3;
    const float* Kg = K + (size_t)b * Tt * 512 + kvh * 128;
    const float* Vg = V + (size_t)b * Tt * 512 + kvh * 128;

    int lkey = tid >> 2;
    int ldq  = (tid & 3) * 4;

    int jlo = (qb >= 8) ? qb - 8 : 0;
    for (int jt = jlo; jt <= qb; jt++) {
        int k0 = jt * 64;
        __syncthreads();
        #pragma unroll
        for (int p = 0; p < 8; p++) {
            int d0 = ldq + p * 16;
            float4 kv = *(const float4*)(Kg + (size_t)(k0 + lkey) * 512 + d0);
            Kt[(d0 + 0) * 64 + (lkey ^ 0)]  = kv.x;
            Kt[(d0 + 1) * 64 + (lkey ^ 8)]  = kv.y;
            Kt[(d0 + 2) * 64 + (lkey ^ 16)] = kv.z;
            Kt[(d0 + 3) * 64 + (lkey ^ 24)] = kv.w;
        }
        #pragma unroll
        for (int p = 0; p < 8; p++) {
            int d0 = ldq + p * 16;
            float4 vv = *(const float4*)(Vg + (size_t)(k0 + lkey) * 512 + d0);
            vv.x = rnd32(vv.x); vv.y = rnd32(vv.y);
            vv.z = rnd32(vv.z); vv.w = rnd32(vv.w);
            *(float4*)(Vs + lkey * 128 + (d0 ^ ((lkey & 3) * 8))) = vv;
        }
        __syncthreads();

        float sacc[4][4];
        #pragma unroll
        for (int i = 0; i < 4; i++)
            #pragma unroll
            for (int j = 0; j < 4; j++) sacc[i][j] = 0.f;
        int sa = g * 4;
        #pragma unroll
        for (int ks = 0; ks < 16; ks++) {
            int kk = ks * 8;
            uint32_t af[4];
            af[0] = __float_as_uint(Qs[r0 * 128 + ((kk + c)     ^ sa)]);
            af[1] = __float_as_uint(Qs[r1 * 128 + ((kk + c)     ^ sa)]);
            af[2] = __float_as_uint(Qs[r0 * 128 + ((kk + c + 4) ^ sa)]);
            af[3] = __float_as_uint(Qs[r1 * 128 + ((kk + c + 4) ^ sa)]);
            #pragma unroll
            for (int nt = 0; nt < 4; nt++) {
                int col = wn * 32 + nt * 8 + g;
                uint32_t bf[2];
                bf[0] = __float_as_uint(Kt[(kk + c) * 64     + (col ^ (8 * c))]);
                bf[1] = __float_as_uint(Kt[(kk + c + 4) * 64 + (col ^ (8 * c))]);
                mma_tf32(sacc[nt], af, bf);
            }
        }

        float pm0 = -INFINITY, pm1 = -INFINITY;
        int qt0 = q0 + r0, qt1 = q0 + r1;
        #pragma unroll
        for (int nt = 0; nt < 4; nt++) {
            #pragma unroll
            for (int e = 0; e < 4; e++) {
                int col = wn * 32 + nt * 8 + 2 * c + (e & 1);
                int ktg = k0 + col;
                int qt = (e >> 1) ? qt1 : qt0;
                float sv = softcap50(sacc[nt][e]);
                bool ok = (ktg <= qt) && (qt - ktg < WINs);
                sv = ok ? sv : -INFINITY;
                sacc[nt][e] = sv;
                if (e >> 1) pm1 = fmaxf(pm1, sv); else pm0 = fmaxf(pm0, sv);
            }
        }
        pm0 = fmaxf(pm0, __shfl_xor_sync(0xffffffffu, pm0, 1));
        pm0 = fmaxf(pm0, __shfl_xor_sync(0xffffffffu, pm0, 2));
        pm1 = fmaxf(pm1, __shfl_xor_sync(0xffffffffu, pm1, 1));
        pm1 = fmaxf(pm1, __shfl_xor_sync(0xffffffffu, pm1, 2));
        if (c == 0) { rmax[wn * 64 + r0] = pm0; rmax[wn * 64 + r1] = pm1; }
        __syncthreads();

        float mn0 = fmaxf(rm0, fmaxf(rmax[r0], rmax[64 + r0]));
        float mn1 = fmaxf(rm1, fmaxf(rmax[r1], rmax[64 + r1]));
        float al0 = __expf(rm0 - mn0); rm0 = mn0;
        float al1 = __expf(rm1 - mn1); rm1 = mn1;

        float ps0 = 0.f, ps1 = 0.f;
        #pragma unroll
        for (int nt = 0; nt < 4; nt++) {
            float p00 = rnd32(__expf(sacc[nt][0] - mn0));
            float p01 = rnd32(__expf(sacc[nt][1] - mn0));
            float p10 = rnd32(__expf(sacc[nt][2] - mn1));
            float p11 = rnd32(__expf(sacc[nt][3] - mn1));
            ps0 += p00 + p01;
            ps1 += p10 + p11;
            int colb = wn * 32 + nt * 8 + 2 * c;
            *(float2*)(Ps + r0 * 64 + (colb ^ sa)) = make_float2(p00, p01);
            *(float2*)(Ps + r1 * 64 + (colb ^ sa)) = make_float2(p10, p11);
        }
        ps0 += __shfl_xor_sync(0xffffffffu, ps0, 1);
        ps0 += __shfl_xor_sync(0xffffffffu, ps0, 2);
        ps1 += __shfl_xor_sync(0xffffffffu, ps1, 1);
        ps1 += __shfl_xor_sync(0xffffffffu, ps1, 2);
        if (c == 0) { rsum[wn * 64 + r0] = ps0; rsum[wn * 64 + r1] = ps1; }

        #pragma unroll
        for (int i = 0; i < 8; i++) {
            Oacc[i][0] *= al0; Oacc[i][1] *= al0;
            Oacc[i][2] *= al1; Oacc[i][3] *= al1;
        }
        __syncthreads();
        rl0 = rl0 * al0 + rsum[r0] + rsum[64 + r0];
        rl1 = rl1 * al1 + rsum[r1] + rsum[64 + r1];

        #pragma unroll
        for (int ks = 0; ks < 8; ks++) {
            int kk = ks * 8;
            uint32_t af[4];
            af[0] = __float_as_uint(Ps[r0 * 64 + ((kk + c)     ^ sa)]);
            af[1] = __float_as_uint(Ps[r1 * 64 + ((kk + c)     ^ sa)]);
            af[2] = __float_as_uint(Ps[r0 * 64 + ((kk + c + 4) ^ sa)]);
            af[3] = __float_as_uint(Ps[r1 * 64 + ((kk + c + 4) ^ sa)]);
            #pragma unroll
            for (int nt = 0; nt < 8; nt++) {
                int col = wn * 64 + nt * 8 + g;
                uint32_t bf[2];
                bf[0] = __float_as_uint(Vs[(kk + c) * 128     + (col ^ (8 * c))]);
                bf[1] = __float_as_uint(Vs[(kk + c + 4) * 128 + (col ^ (8 * c))]);
                mma_tf32(Oacc[nt], af, bf);
            }
        }
    }

    float li0 = 1.f / rl0, li1 = 1.f / rl1;
    __half* Og = O + (size_t)(b * Tt + q0) * 1024 + h * 128;
    #pragma unroll
    for (int nt = 0; nt < 8; nt++) {
        int col = wn * 64 + nt * 8 + 2 * c;
        *(__half2*)(Og + (size_t)r0 * 1024 + col) =
            __floats2half2_rn(Oacc[nt][0] * li0, Oacc[nt][1] * li0);
        *(__half2*)(Og + (size_t)r1 * 1024 + col) =
            __floats2half2_rn(Oacc[nt][2] * li1, Oacc[nt][3] * li1);
    }
}

// ---------------- launch ----------------
extern "C" void kernel_launch(void* const* d_in, const int* in_sizes, int n_in,
                              void* d_out, int out_size)
{
    const float* x        = (const float*)d_in[0];
    const float* q_kernel = (const float*)d_in[1];
    const float* k_kernel = (const float*)d_in[2];
    const float* v_kernel = (const float*)d_in[3];
    const float* out_kern = (const float*)d_in[4];
    const float* attn_sc  = (const float*)d_in[5];
    const float* mlp_sc   = (const float*)d_in[6];
    const float* gate_k   = (const float*)d_in[7];
    const float* up_k     = (const float*)d_in[8];
    const float* down_k   = (const float*)d_in[9];
    float* out = (float*)d_out;

    __half *p_h, *p_attnh, *p_act;
    float *p_q, *p_k, *p_v, *p_x2, *p_gate;
    __half *w_q, *w_k, *w_v, *w_o, *w_g, *w_u, *w_d;
    cudaGetSymbolAddress((void**)&p_h,     g_h);
    cudaGetSymbolAddress((void**)&p_q,     g_q);
    cudaGetSymbolAddress((void**)&p_k,     g_k);
    cudaGetSymbolAddress((void**)&p_v,     g_v);
    cudaGetSymbolAddress((void**)&p_attnh, g_attnh);
    cudaGetSymbolAddress((void**)&p_x2,    g_x2);
    cudaGetSymbolAddress((void**)&p_gate,  g_gate);
    cudaGetSymbolAddress((void**)&p_act,   g_act);
    cudaGetSymbolAddress((void**)&w_q,     g_wq);
    cudaGetSymbolAddress((void**)&w_k,     g_wk);
    cudaGetSymbolAddress((void**)&w_v,     g_wv);
    cudaGetSymbolAddress((void**)&w_o,     g_wo);
    cudaGetSymbolAddress((void**)&w_g,     g_wg);
    cudaGetSymbolAddress((void**)&w_u,     g_wu);
    cudaGetSymbolAddress((void**)&w_d,     g_wd);

    cudaFuncSetAttribute(attn_kernel, cudaFuncAttributeMaxDynamicSharedMemorySize, ATTN_SMEM);
    cudaFuncSetAttribute(qkv_h_kernel, cudaFuncAttributeMaxDynamicSharedMemorySize, HGEMM_SMEM);
    cudaFuncSetAttribute((hgemm_kernel<0, float>),  cudaFuncAttributeMaxDynamicSharedMemorySize, HGEMM_SMEM);
    cudaFuncSetAttribute((hgemm_kernel<1, float>),  cudaFuncAttributeMaxDynamicSharedMemorySize, HGEMM_SMEM);
    cudaFuncSetAttribute((hgemm_kernel<2, __half>), cudaFuncAttributeMaxDynamicSharedMemorySize, HGEMM_SMEM);

    // 0) transpose + fp16 weights: [K,N] -> [N,K]
    transpose_cvt_kernel<<<dim3(32, 32),  256>>>(q_kernel, w_q, 1024, 1024);
    transpose_cvt_kernel<<<dim3(16, 32),  256>>>(k_kernel, w_k, 1024, 512);
    transpose_cvt_kernel<<<dim3(16, 32),  256>>>(v_kernel, w_v, 1024, 512);
    transpose_cvt_kernel<<<dim3(32, 32),  256>>>(out_kern, w_o, 1024, 1024);
    transpose_cvt_kernel<<<dim3(128, 32), 256>>>(gate_k,   w_g, 1024, 4096);
    transpose_cvt_kernel<<<dim3(128, 32), 256>>>(up_k,     w_u, 1024, 4096);
    transpose_cvt_kernel<<<dim3(32, 128), 256>>>(down_k,   w_d, 4096, 1024);

    // 1) h = rmsnorm(x, attn_scale) -> fp16
    rmsnorm_h_kernel<<<Mrows, 256>>>(x, attn_sc, p_h);
    // 2) fused q/k/v projections (fp16 mma) -> fp32 outputs
    qkv_h_kernel<<<dim3(16, 32), 256, HGEMM_SMEM>>>(p_h, w_q, w_k, w_v, p_q, p_k, p_v, 1024);
    // 3) rope (+ q prescale, tf32 rounding for attention)
    rope_kernel<<<Mrows, 256>>>(p_q, p_k);
    // 4) attention -> fp16 out
    attn_kernel<<<dim3(Tt / 64, Hh, Bb), 256, ATTN_SMEM>>>(p_q, p_k, p_v, p_attnh);
    // 5) out projection + residual
    hgemm_kernel<1, float><<<dim3(8, 32), 256, HGEMM_SMEM>>>(p_attnh, w_o, x, p_x2, 1024, 1024);
    // 6) h = rmsnorm(x2, mlp_scale) -> fp16
    rmsnorm_h_kernel<<<Mrows, 256>>>(p_x2, mlp_sc, p_h);
    // 7) gate (fp32), then up with fused SwiGLU -> fp16 act
    hgemm_kernel<0, float><<<dim3(32, 32), 256, HGEMM_SMEM>>>(p_h, w_g, nullptr, p_gate, HIDm, 1024);
    hgemm_kernel<2, __half><<<dim3(32, 32), 256, HGEMM_SMEM>>>(p_h, w_u, p_gate, p_act, HIDm, 1024);
    // 8) down + residual -> out
    hgemm_kernel<1, float><<<dim3(8, 32), 256, HGEMM_SMEM>>>(p_act, w_d, p_x2, out, 1024, HIDm);
}

// round 8
// speedup vs baseline: 5.9229x; 1.0586x over previous
#include <cuda_runtime.h>
#include <cuda_fp16.h>
#include <stdint.h>
#include <math.h>

#define Bb   2
#define Tt   2048
#define Cc   1024
#define Hh   8
#define KVh  4
#define Dd   128
#define WINs 512
#define HIDm 4096
#define Mrows (Bb*Tt)   // 4096

// ---------------- scratch ----------------
__device__ __half g_h   [Mrows*Cc];        // rmsnorm out (fp16 A operand)
__device__ float  g_q   [Mrows*Hh*Dd];     // qkv gemm fp32 outputs
__device__ float  g_k   [Mrows*KVh*Dd];
__device__ float  g_v   [Mrows*KVh*Dd];
__device__ __half g_qh  [Mrows*Hh*Dd];     // rope out, prescaled, half
__device__ __half g_kh  [Mrows*KVh*Dd];    // rope out, half
__device__ __half g_attnh[Mrows*Hh*Dd];    // attention out (fp16 A operand)
__device__ float  g_x2  [Mrows*Cc];
__device__ float  g_gate[Mrows*HIDm];      // gate pre-activation (fp32)
__device__ __half g_act [Mrows*HIDm];      // silu(gate)*up (fp16 A operand)
// transposed+converted weights [N][K] fp16
__device__ __half g_wq[1048576];
__device__ __half g_wk[524288];
__device__ __half g_wv[524288];
__device__ __half g_wo[1048576];
__device__ __half g_wg[4194304];
__device__ __half g_wu[4194304];
__device__ __half g_wd[4194304];

// ---------------- helpers ----------------
__device__ __forceinline__ void mma_f16(float* d, const uint32_t* a, const uint32_t* b) {
    asm volatile(
        "mma.sync.aligned.m16n8k16.row.col.f32.f16.f16.f32 "
        "{%0,%1,%2,%3},{%4,%5,%6,%7},{%8,%9},{%0,%1,%2,%3};"
        : "+f"(d[0]), "+f"(d[1]), "+f"(d[2]), "+f"(d[3])
        : "r"(a[0]), "r"(a[1]), "r"(a[2]), "r"(a[3]),
          "r"(b[0]), "r"(b[1]));
}

#define CP16(dst, src) \
    asm volatile("cp.async.cg.shared.global [%0], [%1], 16;" :: "r"(dst), "l"(src))
#define CP_COMMIT() asm volatile("cp.async.commit_group;")

// chunk-of-8-halves XOR swizzle
__device__ __forceinline__ int swz(int x, int row) {
    return (((x >> 3) ^ (row & 7)) << 3) + (x & 7);
}

// softcap: 50*tanh(s/50)
__device__ __forceinline__ float softcap50(float s) {
    float x = s * 0.02f;
    float x2 = x * x;
    float t;
    if (x2 <= 0.09f) {
        t = x * (1.0f + x2 * (-0.333333333f + x2 * (0.133333333f + x2 * (-0.053968254f))));
    } else {
        t = tanhf(x);
    }
    return 50.0f * t;
}

// ---------------- weight transpose + fp16 convert: in[K][N] -> out[N][K] -----
__global__ void transpose_cvt_kernel(const float* __restrict__ in,
                                     __half* __restrict__ out, int K, int N)
{
    __shared__ float t[32][33];
    int n0 = blockIdx.x * 32, k0 = blockIdx.y * 32;
    int tx = threadIdx.x & 31, ty = threadIdx.x >> 5;   // 32 x 8
    #pragma unroll
    for (int i = 0; i < 4; i++) {
        int k = k0 + ty + i * 8;
        t[ty + i * 8][tx] = in[(size_t)k * N + n0 + tx];
    }
    __syncthreads();
    #pragma unroll
    for (int i = 0; i < 4; i++) {
        int n = n0 + ty + i * 8;
        out[(size_t)n * K + k0 + tx] = __float2half_rn(t[tx][ty + i * 8]);
    }
}

// ---------------- rmsnorm -> fp16 ----------------
__global__ void rmsnorm_h_kernel(const float* __restrict__ x,
                                 const float* __restrict__ scale,
                                 __half* __restrict__ y)
{
    int row = blockIdx.x;
    const float4* xr = (const float4*)(x + (size_t)row * Cc);
    float4 v = xr[threadIdx.x];
    float ss = v.x*v.x + v.y*v.y + v.z*v.z + v.w*v.w;
    #pragma unroll
    for (int o = 16; o; o >>= 1) ss += __shfl_xor_sync(0xffffffffu, ss, o);
    __shared__ float wsum[8];
    if ((threadIdx.x & 31) == 0) wsum[threadIdx.x >> 5] = ss;
    __syncthreads();
    if (threadIdx.x < 8) {
        float t = wsum[threadIdx.x];
        #pragma unroll
        for (int o = 4; o; o >>= 1) t += __shfl_xor_sync(0xffu, t, o);
        if (threadIdx.x == 0) wsum[0] = t;
    }
    __syncthreads();
    float inv = rsqrtf(wsum[0] * (1.0f / Cc) + 1e-6f);
    float4 sc = ((const float4*)scale)[threadIdx.x];
    __half2 h0 = __floats2half2_rn(v.x * inv * (1.f + sc.x), v.y * inv * (1.f + sc.y));
    __half2 h1 = __floats2half2_rn(v.z * inv * (1.f + sc.z), v.w * inv * (1.f + sc.w));
    uint2 u = make_uint2(*(uint32_t*)&h0, *(uint32_t*)&h1);
    *(uint2*)(y + (size_t)row * Cc + threadIdx.x * 4) = u;
}

// ---------------- FP16 GEMM (m16n8k16, cp.async 3-stage) ---------------------
#define PAH 40
#define A_HBYTES (128*PAH*2)
#define STAGE_HB (2*A_HBYTES)
#define H_STAGES 3
#define HGEMM_SMEM (H_STAGES*STAGE_HB)

template<int MODE, typename OT>
__device__ __forceinline__ void hgemm_tile(
    const __half* __restrict__ A, const __half* __restrict__ Bt,
    const float* __restrict__ Res, OT* __restrict__ C,
    int NC, int K, int m0, int n0)
{
    extern __shared__ __half smh[];
    uint32_t smb;
    asm("{ .reg .u64 t; cvta.to.shared.u64 t, %1; cvt.u32.u64 %0, t; }"
        : "=r"(smb) : "l"(smh));

    int tid  = threadIdx.x;
    int lane = tid & 31, warp = tid >> 5;
    int wm = (warp & 1) * 64;
    int wn = (warp >> 1) * 32;
    int g = lane >> 2, c = lane & 3;

    const __half* Ag = A  + (size_t)m0 * K;
    const __half* Bg = Bt + (size_t)n0 * K;

    float acc[4][4][4];
    #pragma unroll
    for (int i = 0; i < 4; i++)
        #pragma unroll
        for (int j = 0; j < 4; j++)
            #pragma unroll
            for (int r = 0; r < 4; r++) acc[i][j][r] = 0.f;

    int ntiles = K >> 5;

    int lr = tid >> 2, lc = tid & 3;
    auto load_stage = [&](int s, int kc) {
        uint32_t base = smb + s * STAGE_HB;
        #pragma unroll
        for (int i = 0; i < 2; i++) {
            int r = lr + i * 64;
            CP16(base + r * 80 + lc * 16, Ag + (size_t)r * K + kc * 32 + lc * 8);
        }
        uint32_t bb = base + A_HBYTES;
        #pragma unroll
        for (int i = 0; i < 2; i++) {
            int r = lr + i * 64;
            CP16(bb + r * 80 + lc * 16, Bg + (size_t)r * K + kc * 32 + lc * 8);
        }
    };

    load_stage(0, 0); CP_COMMIT();
    load_stage(1, 1); CP_COMMIT();

    for (int kt = 0; kt < ntiles; kt++) {
        asm volatile("cp.async.wait_group 1;");
        __syncthreads();

        int pf = kt + H_STAGES - 1;
        if (pf < ntiles) load_stage(pf % H_STAGES, pf);
        CP_COMMIT();

        const __half* sA = smh + (size_t)(kt % H_STAGES) * (STAGE_HB / 2);
        const __half* sB = sA + A_HBYTES / 2;
        #pragma unroll
        for (int ks = 0; ks < 2; ks++) {
            int kb = ks * 16;
            uint32_t bf[4][2];
            #pragma unroll
            for (int nt = 0; nt < 4; nt++) {
                int col = wn + nt * 8 + g;
                bf[nt][0] = *(const uint32_t*)&sB[col * PAH + kb + 2 * c];
                bf[nt][1] = *(const uint32_t*)&sB[col * PAH + kb + 2 * c + 8];
            }
            #pragma unroll
            for (int mt = 0; mt < 4; mt++) {
                int row = wm + mt * 16 + g;
                uint32_t af[4];
                af[0] = *(const uint32_t*)&sA[row * PAH + kb + 2 * c];
                af[1] = *(const uint32_t*)&sA[(row + 8) * PAH + kb + 2 * c];
                af[2] = *(const uint32_t*)&sA[row * PAH + kb + 2 * c + 8];
                af[3] = *(const uint32_t*)&sA[(row + 8) * PAH + kb + 2 * c + 8];
                #pragma unroll
                for (int nt = 0; nt < 4; nt++)
                    mma_f16(acc[mt][nt], af, bf[nt]);
            }
        }
    }

    #pragma unroll
    for (int mt = 0; mt < 4; mt++) {
        int r0 = m0 + wm + mt * 16 + g;
        #pragma unroll
        for (int nt = 0; nt < 4; nt++) {
            int cl = n0 + wn + nt * 8 + 2 * c;
            #pragma unroll
            for (int half_i = 0; half_i < 2; half_i++) {
                int rr = r0 + half_i * 8;
                float v0 = acc[mt][nt][half_i * 2 + 0];
                float v1 = acc[mt][nt][half_i * 2 + 1];
                size_t idx = (size_t)rr * NC + cl;
                if (MODE == 0) {
                    *(float2*)((float*)C + idx) = make_float2(v0, v1);
                } else if (MODE == 1) {
                    v0 += Res[idx]; v1 += Res[idx + 1];
                    *(float2*)((float*)C + idx) = make_float2(v0, v1);
                } else {
                    float g0 = Res[idx], g1 = Res[idx + 1];
                    v0 *= g0 / (1.f + expf(-g0));
                    v1 *= g1 / (1.f + expf(-g1));
                    *(__half2*)((__half*)C + idx) = __floats2half2_rn(v0, v1);
                }
            }
        }
    }
}

template<int MODE, typename OT>
__global__ __launch_bounds__(256, 2) void hgemm_kernel(
    const __half* __restrict__ A, const __half* __restrict__ Bt,
    const float* __restrict__ Res, OT* __restrict__ C, int N, int K)
{
    hgemm_tile<MODE, OT>(A, Bt, Res, C, N, K, blockIdx.y * 128, blockIdx.x * 128);
}

// fused QKV: grid.x = 16 (q 0-7, k 8-11, v 12-15)
__global__ __launch_bounds__(256, 2) void qkv_h_kernel(
    const __half* __restrict__ A,
    const __half* __restrict__ Bq, const __half* __restrict__ Bk,
    const __half* __restrict__ Bv,
    float* __restrict__ Cq, float* __restrict__ Ck, float* __restrict__ Cv,
    int K)
{
    int nb = blockIdx.x, m0 = blockIdx.y * 128;
    if (nb < 8)
        hgemm_tile<0, float>(A, Bq, nullptr, Cq, 1024, K, m0, nb * 128);
    else if (nb < 12)
        hgemm_tile<0, float>(A, Bk + (size_t)(nb - 8) * 128 * K, nullptr,
                             Ck + (nb - 8) * 128, 512, K, m0, 0);
    else
        hgemm_tile<0, float>(A, Bv + (size_t)(nb - 12) * 128 * K, nullptr,
                             Cv + (nb - 12) * 128, 512, K, m0, 0);
}

// ---------------- RoPE: fp32 in -> half out (+ q prescale) -------------------
__global__ void rope_kernel(const float* __restrict__ q, const float* __restrict__ k,
                            __half* __restrict__ qh, __half* __restrict__ kh)
{
    int row = blockIdx.x;
    int t = row & (Tt - 1);
    const float qscale = 0.08838834764831845f;
    __shared__ float s_sin[64], s_cos[64];
    if (threadIdx.x < 64) {
        float inv = expf(-logf(10000.0f) * (2.0f * threadIdx.x) / 128.0f);
        float ang = (float)t * inv;
        s_sin[threadIdx.x] = sinf(ang);
        s_cos[threadIdx.x] = cosf(ang);
    }
    __syncthreads();
    for (int p = threadIdx.x; p < 512; p += 256) {
        int head = p >> 6, i = p & 63;
        const float* base = q + (size_t)row * 1024 + head * 128;
        __half* ob = qh + (size_t)row * 1024 + head * 128;
        float x1 = base[i], x2 = base[i + 64];
        float s = s_sin[i], c = s_cos[i];
        ob[i]      = __float2half_rn((x1 * c - x2 * s) * qscale);
        ob[i + 64] = __float2half_rn((x2 * c + x1 * s) * qscale);
    }
    for (int p = threadIdx.x; p < 256; p += 256) {
        int head = p >> 6, i = p & 63;
        const float* base = k + (size_t)row * 512 + head * 128;
        __half* ob = kh + (size_t)row * 512 + head * 128;
        float x1 = base[i], x2 = base[i + 64];
        float s = s_sin[i], c = s_cos[i];
        ob[i]      = __float2half_rn(x1 * c - x2 * s);
        ob[i + 64] = __float2half_rn(x2 * c + x1 * s);
    }
}

// ---------------- attention: FP16 MMA flash ----------------------------------
// smem (halves): Qs[64][128]@0, Ks[64][128]@8192, Vt[128][64]@16384,
//                Ps[64][64]@24576; floats rmax[128]/rsum[128] @ half-off 28672
#define ATTN_SMEM ((28672 + 512) * 2)   // 58368 bytes
__global__ __launch_bounds__(256, 2) void attn_kernel(
    const __half* __restrict__ Q, const __half* __restrict__ K,
    const float* __restrict__ V, __half* __restrict__ O)
{
    extern __shared__ __half sma[];
    __half* Qs = sma;
    __half* Ks = sma + 8192;
    __half* Vt = sma + 16384;
    __half* Ps = sma + 24576;
    float* rmax = (float*)(sma + 28672);
    float* rsum = rmax + 128;

    int qb = blockIdx.x, h = blockIdx.y, b = blockIdx.z;
    int q0 = qb * 64;
    int tid = threadIdx.x, lane = tid & 31, warp = tid >> 5;
    int wq = warp >> 1, wn = warp & 1, g = lane >> 2, c = lane & 3;

    // Q tile: 64 rows x 16 chunks of 8 halves
    const __half* Qg = Q + (size_t)(b * Tt + q0) * 1024 + h * 128;
    #pragma unroll
    for (int p = 0; p < 4; p++) {
        int idx = tid + p * 256;
        int row = idx >> 4, ch = idx & 15;
        uint4 v = *(const uint4*)(Qg + (size_t)row * 1024 + ch * 8);
        *(uint4*)(Qs + row * 128 + ((ch ^ (row & 7)) << 3)) = v;
    }

    int r0 = 16 * wq + g;
    int r1 = r0 + 8;
    float rm0 = -1e30f, rm1 = -1e30f, rl0 = 0.f, rl1 = 0.f;
    float Oacc[8][4];
    #pragma unroll
    for (int i = 0; i < 8; i++)
        #pragma unroll
        for (int j = 0; j < 4; j++) Oacc[i][j] = 0.f;

    int kvh = h & 3;
    const __half* Kg = K + (size_t)b * Tt * 512 + kvh * 128;
    const float*  Vg = V + (size_t)b * Tt * 512 + kvh * 128;

    int lkey = tid >> 2;           // 0..63
    int ldq  = (tid & 3) * 4;      // d base

    int jlo = (qb >= 8) ? qb - 8 : 0;
    for (int jt = jlo; jt <= qb; jt++) {
        int k0 = jt * 64;
        __syncthreads();
        // K tile: rows = keys, natural layout, swizzled chunks
        #pragma unroll
        for (int p = 0; p < 4; p++) {
            int idx = tid + p * 256;
            int row = idx >> 4, ch = idx & 15;
            uint4 v = *(const uint4*)(Kg + (size_t)(k0 + row) * 512 + ch * 8);
            *(uint4*)(Ks + row * 128 + ((ch ^ (row & 7)) << 3)) = v;
        }
        // V tile: fp32 -> half, transposed to Vt[d][key]
        #pragma unroll
        for (int p = 0; p < 8; p++) {
            int d0 = ldq + p * 16;
            float4 vv = *(const float4*)(Vg + (size_t)(k0 + lkey) * 512 + d0);
            Vt[(d0 + 0) * 64 + swz(lkey, d0 + 0)] = __float2half_rn(vv.x);
            Vt[(d0 + 1) * 64 + swz(lkey, d0 + 1)] = __float2half_rn(vv.y);
            Vt[(d0 + 2) * 64 + swz(lkey, d0 + 2)] = __float2half_rn(vv.z);
            Vt[(d0 + 3) * 64 + swz(lkey, d0 + 3)] = __float2half_rn(vv.w);
        }
        __syncthreads();

        // ---- S = Q @ K^T (fp16 m16n8k16) ----
        float sacc[4][4];
        #pragma unroll
        for (int i = 0; i < 4; i++)
            #pragma unroll
            for (int j = 0; j < 4; j++) sacc[i][j] = 0.f;
        #pragma unroll
        for (int ks = 0; ks < 8; ks++) {
            int kb = ks * 16;
            uint32_t af[4];
            af[0] = *(const uint32_t*)&Qs[r0 * 128 + swz(kb + 2 * c, r0)];
            af[1] = *(const uint32_t*)&Qs[r1 * 128 + swz(kb + 2 * c, r1)];
            af[2] = *(const uint32_t*)&Qs[r0 * 128 + swz(kb + 2 * c + 8, r0)];
            af[3] = *(const uint32_t*)&Qs[r1 * 128 + swz(kb + 2 * c + 8, r1)];
            #pragma unroll
            for (int nt = 0; nt < 4; nt++) {
                int col = wn * 32 + nt * 8 + g;
                uint32_t bf[2];
                bf[0] = *(const uint32_t*)&Ks[col * 128 + swz(kb + 2 * c, col)];
                bf[1] = *(const uint32_t*)&Ks[col * 128 + swz(kb + 2 * c + 8, col)];
                mma_f16(sacc[nt], af, bf);
            }
        }

        // ---- softcap + mask ----
        float pm0 = -INFINITY, pm1 = -INFINITY;
        int qt0 = q0 + r0, qt1 = q0 + r1;
        #pragma unroll
        for (int nt = 0; nt < 4; nt++) {
            #pragma unroll
            for (int e = 0; e < 4; e++) {
                int col = wn * 32 + nt * 8 + 2 * c + (e & 1);
                int ktg = k0 + col;
                int qt = (e >> 1) ? qt1 : qt0;
                float sv = softcap50(sacc[nt][e]);
                bool ok = (ktg <= qt) && (qt - ktg < WINs);
                sv = ok ? sv : -INFINITY;
                sacc[nt][e] = sv;
                if (e >> 1) pm1 = fmaxf(pm1, sv); else pm0 = fmaxf(pm0, sv);
            }
        }
        pm0 = fmaxf(pm0, __shfl_xor_sync(0xffffffffu, pm0, 1));
        pm0 = fmaxf(pm0, __shfl_xor_sync(0xffffffffu, pm0, 2));
        pm1 = fmaxf(pm1, __shfl_xor_sync(0xffffffffu, pm1, 1));
        pm1 = fmaxf(pm1, __shfl_xor_sync(0xffffffffu, pm1, 2));
        if (c == 0) { rmax[wn * 64 + r0] = pm0; rmax[wn * 64 + r1] = pm1; }
        __syncthreads();

        float mn0 = fmaxf(rm0, fmaxf(rmax[r0], rmax[64 + r0]));
        float mn1 = fmaxf(rm1, fmaxf(rmax[r1], rmax[64 + r1]));
        float al0 = __expf(rm0 - mn0); rm0 = mn0;
        float al1 = __expf(rm1 - mn1); rm1 = mn1;

        float ps0 = 0.f, ps1 = 0.f;
        #pragma unroll
        for (int nt = 0; nt < 4; nt++) {
            int colb = wn * 32 + nt * 8 + 2 * c;
            __half2 h0 = __floats2half2_rn(__expf(sacc[nt][0] - mn0),
                                           __expf(sacc[nt][1] - mn0));
            __half2 h1 = __floats2half2_rn(__expf(sacc[nt][2] - mn1),
                                           __expf(sacc[nt][3] - mn1));
            // sum the rounded values (matches PV numerator)
            float2 f0 = __half22float2(h0), f1 = __half22float2(h1);
            ps0 += f0.x + f0.y;
            ps1 += f1.x + f1.y;
            *(__half2*)&Ps[r0 * 64 + swz(colb, r0)] = h0;
            *(__half2*)&Ps[r1 * 64 + swz(colb, r1)] = h1;
        }
        ps0 += __shfl_xor_sync(0xffffffffu, ps0, 1);
        ps0 += __shfl_xor_sync(0xffffffffu, ps0, 2);
        ps1 += __shfl_xor_sync(0xffffffffu, ps1, 1);
        ps1 += __shfl_xor_sync(0xffffffffu, ps1, 2);
        if (c == 0) { rsum[wn * 64 + r0] = ps0; rsum[wn * 64 + r1] = ps1; }

        #pragma unroll
        for (int i = 0; i < 8; i++) {
            Oacc[i][0] *= al0; Oacc[i][1] *= al0;
            Oacc[i][2] *= al1; Oacc[i][3] *= al1;
        }
        __syncthreads();
        rl0 = rl0 * al0 + rsum[r0] + rsum[64 + r0];
        rl1 = rl1 * al1 + rsum[r1] + rsum[64 + r1];

        // ---- O += P @ V (fp16 m16n8k16) ----
        #pragma unroll
        for (int ks = 0; ks < 4; ks++) {
            int kb = ks * 16;
            uint32_t af[4];
            af[0] = *(const uint32_t*)&Ps[r0 * 64 + swz(kb + 2 * c, r0)];
            af[1] = *(const uint32_t*)&Ps[r1 * 64 + swz(kb + 2 * c, r1)];
            af[2] = *(const uint32_t*)&Ps[r0 * 64 + swz(kb + 2 * c + 8, r0)];
            af[3] = *(const uint32_t*)&Ps[r1 * 64 + swz(kb + 2 * c + 8, r1)];
            #pragma unroll
            for (int nt = 0; nt < 8; nt++) {
                int col = wn * 64 + nt * 8 + g;
                uint32_t bf[2];
                bf[0] = *(const uint32_t*)&Vt[col * 64 + swz(kb + 2 * c, col)];
                bf[1] = *(const uint32_t*)&Vt[col * 64 + swz(kb + 2 * c + 8, col)];
                mma_f16(Oacc[nt], af, bf);
            }
        }
    }

    float li0 = 1.f / rl0, li1 = 1.f / rl1;
    __half* Og = O + (size_t)(b * Tt + q0) * 1024 + h * 128;
    #pragma unroll
    for (int nt = 0; nt < 8; nt++) {
        int col = wn * 64 + nt * 8 + 2 * c;
        *(__half2*)(Og + (size_t)r0 * 1024 + col) =
            __floats2half2_rn(Oacc[nt][0] * li0, Oacc[nt][1] * li0);
        *(__half2*)(Og + (size_t)r1 * 1024 + col) =
            __floats2half2_rn(Oacc[nt][2] * li1, Oacc[nt][3] * li1);
    }
}

// ---------------- launch ----------------
extern "C" void kernel_launch(void* const* d_in, const int* in_sizes, int n_in,
                              void* d_out, int out_size)
{
    const float* x        = (const float*)d_in[0];
    const float* q_kernel = (const float*)d_in[1];
    const float* k_kernel = (const float*)d_in[2];
    const float* v_kernel = (const float*)d_in[3];
    const float* out_kern = (const float*)d_in[4];
    const float* attn_sc  = (const float*)d_in[5];
    const float* mlp_sc   = (const float*)d_in[6];
    const float* gate_k   = (const float*)d_in[7];
    const float* up_k     = (const float*)d_in[8];
    const float* down_k   = (const float*)d_in[9];
    float* out = (float*)d_out;

    __half *p_h, *p_attnh, *p_act, *p_qh, *p_kh;
    float *p_q, *p_k, *p_v, *p_x2, *p_gate;
    __half *w_q, *w_k, *w_v, *w_o, *w_g, *w_u, *w_d;
    cudaGetSymbolAddress((void**)&p_h,     g_h);
    cudaGetSymbolAddress((void**)&p_q,     g_q);
    cudaGetSymbolAddress((void**)&p_k,     g_k);
    cudaGetSymbolAddress((void**)&p_v,     g_v);
    cudaGetSymbolAddress((void**)&p_qh,    g_qh);
    cudaGetSymbolAddress((void**)&p_kh,    g_kh);
    cudaGetSymbolAddress((void**)&p_attnh, g_attnh);
    cudaGetSymbolAddress((void**)&p_x2,    g_x2);
    cudaGetSymbolAddress((void**)&p_gate,  g_gate);
    cudaGetSymbolAddress((void**)&p_act,   g_act);
    cudaGetSymbolAddress((void**)&w_q,     g_wq);
    cudaGetSymbolAddress((void**)&w_k,     g_wk);
    cudaGetSymbolAddress((void**)&w_v,     g_wv);
    cudaGetSymbolAddress((void**)&w_o,     g_wo);
    cudaGetSymbolAddress((void**)&w_g,     g_wg);
    cudaGetSymbolAddress((void**)&w_u,     g_wu);
    cudaGetSymbolAddress((void**)&w_d,     g_wd);

    cudaFuncSetAttribute(attn_kernel, cudaFuncAttributeMaxDynamicSharedMemorySize, ATTN_SMEM);
    cudaFuncSetAttribute(qkv_h_kernel, cudaFuncAttributeMaxDynamicSharedMemorySize, HGEMM_SMEM);
    cudaFuncSetAttribute((hgemm_kernel<0, float>),  cudaFuncAttributeMaxDynamicSharedMemorySize, HGEMM_SMEM);
    cudaFuncSetAttribute((hgemm_kernel<1, float>),  cudaFuncAttributeMaxDynamicSharedMemorySize, HGEMM_SMEM);
    cudaFuncSetAttribute((hgemm_kernel<2, __half>), cudaFuncAttributeMaxDynamicSharedMemorySize, HGEMM_SMEM);

    // 0) transpose + fp16 weights: [K,N] -> [N,K]
    transpose_cvt_kernel<<<dim3(32, 32),  256>>>(q_kernel, w_q, 1024, 1024);
    transpose_cvt_kernel<<<dim3(16, 32),  256>>>(k_kernel, w_k, 1024, 512);
    transpose_cvt_kernel<<<dim3(16, 32),  256>>>(v_kernel, w_v, 1024, 512);
    transpose_cvt_kernel<<<dim3(32, 32),  256>>>(out_kern, w_o, 1024, 1024);
    transpose_cvt_kernel<<<dim3(128, 32), 256>>>(gate_k,   w_g, 1024, 4096);
    transpose_cvt_kernel<<<dim3(128, 32), 256>>>(up_k,     w_u, 1024, 4096);
    transpose_cvt_kernel<<<dim3(32, 128), 256>>>(down_k,   w_d, 4096, 1024);

    // 1) h = rmsnorm(x, attn_scale) -> fp16
    rmsnorm_h_kernel<<<Mrows, 256>>>(x, attn_sc, p_h);
    // 2) fused q/k/v projections (fp16 mma) -> fp32
    qkv_h_kernel<<<dim3(16, 32), 256, HGEMM_SMEM>>>(p_h, w_q, w_k, w_v, p_q, p_k, p_v, 1024);
    // 3) rope -> half q (prescaled), half k
    rope_kernel<<<Mrows, 256>>>(p_q, p_k, p_qh, p_kh);
    // 4) attention (fp16 MMA) -> fp16 out
    attn_kernel<<<dim3(Tt / 64, Hh, Bb), 256, ATTN_SMEM>>>(p_qh, p_kh, p_v, p_attnh);
    // 5) out projection + residual
    hgemm_kernel<1, float><<<dim3(8, 32), 256, HGEMM_SMEM>>>(p_attnh, w_o, x, p_x2, 1024, 1024);
    // 6) h = rmsnorm(x2, mlp_scale) -> fp16
    rmsnorm_h_kernel<<<Mrows, 256>>>(p_x2, mlp_sc, p_h);
    // 7) gate (fp32), then up with fused SwiGLU -> fp16 act
    hgemm_kernel<0, float><<<dim3(32, 32), 256, HGEMM_SMEM>>>(p_h, w_g, nullptr, p_gate, HIDm, 1024);
    hgemm_kernel<2, __half><<<dim3(32, 32), 256, HGEMM_SMEM>>>(p_h, w_u, p_gate, p_act, HIDm, 1024);
    // 8) down + residual -> out
    hgemm_kernel<1, float><<<dim3(8, 32), 256, HGEMM_SMEM>>>(p_act, w_d, p_x2, out, 1024, HIDm);
}

// round 9
// speedup vs baseline: 6.0675x; 1.0244x over previous
#include <cuda_runtime.h>
#include <cuda_fp16.h>
#include <stdint.h>
#include <math.h>

#define Bb   2
#define Tt   2048
#define Cc   1024
#define Hh   8
#define KVh  4
#define Dd   128
#define WINs 512
#define HIDm 4096
#define Mrows (Bb*Tt)   // 4096

// ---------------- scratch ----------------
__device__ __half g_h   [Mrows*Cc];
__device__ float  g_q   [Mrows*Hh*Dd];
__device__ float  g_k   [Mrows*KVh*Dd];
__device__ float  g_v   [Mrows*KVh*Dd];
__device__ __half g_qh  [Mrows*Hh*Dd];
__device__ __half g_kh  [Mrows*KVh*Dd];
__device__ __half g_attnh[Mrows*Hh*Dd];
__device__ float  g_x2  [Mrows*Cc];
__device__ float  g_gate[Mrows*HIDm];
__device__ __half g_act [Mrows*HIDm];
// transposed+converted weights [N][K] fp16
__device__ __half g_wq[1048576];
__device__ __half g_wk[524288];
__device__ __half g_wv[524288];
__device__ __half g_wo[1048576];
__device__ __half g_wg[4194304];
__device__ __half g_wu[4194304];
__device__ __half g_wd[4194304];

// ---------------- helpers ----------------
__device__ __forceinline__ void mma_f16(float* d, const uint32_t* a, const uint32_t* b) {
    asm volatile(
        "mma.sync.aligned.m16n8k16.row.col.f32.f16.f16.f32 "
        "{%0,%1,%2,%3},{%4,%5,%6,%7},{%8,%9},{%0,%1,%2,%3};"
        : "+f"(d[0]), "+f"(d[1]), "+f"(d[2]), "+f"(d[3])
        : "r"(a[0]), "r"(a[1]), "r"(a[2]), "r"(a[3]),
          "r"(b[0]), "r"(b[1]));
}
__device__ __forceinline__ void ldm_x4(uint32_t* r, uint32_t addr) {
    asm volatile("ldmatrix.sync.aligned.m8n8.x4.shared.b16 {%0,%1,%2,%3}, [%4];"
        : "=r"(r[0]), "=r"(r[1]), "=r"(r[2]), "=r"(r[3]) : "r"(addr));
}

#define CP16(dst, src) \
    asm volatile("cp.async.cg.shared.global [%0], [%1], 16;" :: "r"(dst), "l"(src))
#define CP_COMMIT() asm volatile("cp.async.commit_group;")

// chunk-of-8-halves XOR swizzle (half-index)
__device__ __forceinline__ int swz(int x, int row) {
    return (((x >> 3) ^ (row & 7)) << 3) + (x & 7);
}

// softcap: 50*tanh(s/50)
__device__ __forceinline__ float softcap50(float s) {
    float x = s * 0.02f;
    float x2 = x * x;
    float t;
    if (x2 <= 0.09f) {
        t = x * (1.0f + x2 * (-0.333333333f + x2 * (0.133333333f + x2 * (-0.053968254f))));
    } else {
        t = tanhf(x);
    }
    return 50.0f * t;
}

// ---------------- weight transpose + fp16 convert: in[K][N] -> out[N][K] -----
__global__ void transpose_cvt_kernel(const float* __restrict__ in,
                                     __half* __restrict__ out, int K, int N)
{
    __shared__ float t[32][33];
    int n0 = blockIdx.x * 32, k0 = blockIdx.y * 32;
    int tx = threadIdx.x & 31, ty = threadIdx.x >> 5;
    #pragma unroll
    for (int i = 0; i < 4; i++) {
        int k = k0 + ty + i * 8;
        t[ty + i * 8][tx] = in[(size_t)k * N + n0 + tx];
    }
    __syncthreads();
    #pragma unroll
    for (int i = 0; i < 4; i++) {
        int n = n0 + ty + i * 8;
        out[(size_t)n * K + k0 + tx] = __float2half_rn(t[tx][ty + i * 8]);
    }
}

// ---------------- rmsnorm -> fp16 ----------------
__global__ void rmsnorm_h_kernel(const float* __restrict__ x,
                                 const float* __restrict__ scale,
                                 __half* __restrict__ y)
{
    int row = blockIdx.x;
    const float4* xr = (const float4*)(x + (size_t)row * Cc);
    float4 v = xr[threadIdx.x];
    float ss = v.x*v.x + v.y*v.y + v.z*v.z + v.w*v.w;
    #pragma unroll
    for (int o = 16; o; o >>= 1) ss += __shfl_xor_sync(0xffffffffu, ss, o);
    __shared__ float wsum[8];
    if ((threadIdx.x & 31) == 0) wsum[threadIdx.x >> 5] = ss;
    __syncthreads();
    if (threadIdx.x < 8) {
        float t = wsum[threadIdx.x];
        #pragma unroll
        for (int o = 4; o; o >>= 1) t += __shfl_xor_sync(0xffu, t, o);
        if (threadIdx.x == 0) wsum[0] = t;
    }
    __syncthreads();
    float inv = rsqrtf(wsum[0] * (1.0f / Cc) + 1e-6f);
    float4 sc = ((const float4*)scale)[threadIdx.x];
    __half2 h0 = __floats2half2_rn(v.x * inv * (1.f + sc.x), v.y * inv * (1.f + sc.y));
    __half2 h1 = __floats2half2_rn(v.z * inv * (1.f + sc.z), v.w * inv * (1.f + sc.w));
    uint2 u = make_uint2(*(uint32_t*)&h0, *(uint32_t*)&h1);
    *(uint2*)(y + (size_t)row * Cc + threadIdx.x * 4) = u;
}

// ---------------- FP16 GEMM (m16n8k16, cp.async 3-stage, ldmatrix) -----------
#define PAH 40
#define A_HBYTES (128*PAH*2)
#define STAGE_HB (2*A_HBYTES)
#define H_STAGES 3
#define HGEMM_SMEM (H_STAGES*STAGE_HB)

template<int MODE, typename OT>
__device__ __forceinline__ void hgemm_tile(
    const __half* __restrict__ A, const __half* __restrict__ Bt,
    const float* __restrict__ Res, OT* __restrict__ C,
    int NC, int K, int m0, int n0)
{
    extern __shared__ __half smh[];
    uint32_t smb;
    asm("{ .reg .u64 t; cvta.to.shared.u64 t, %1; cvt.u32.u64 %0, t; }"
        : "=r"(smb) : "l"(smh));

    int tid  = threadIdx.x;
    int lane = tid & 31, warp = tid >> 5;
    int wm = (warp & 1) * 64;
    int wn = (warp >> 1) * 32;
    int g = lane >> 2, c = lane & 3;
    int lane16 = lane & 15;
    int lhi = (lane & 16) >> 1;        // +8 halves if lane>=16

    // per-lane ldmatrix byte offsets (within a stage)
    uint32_t offA[4][2], offB[2][2];
    #pragma unroll
    for (int mt = 0; mt < 4; mt++)
        #pragma unroll
        for (int ks = 0; ks < 2; ks++) {
            int row = wm + mt * 16 + lane16;
            int kx = ks * 16 + lhi;
            offA[mt][ks] = (uint32_t)(row * PAH + kx) * 2u;
        }
    #pragma unroll
    for (int bi = 0; bi < 2; bi++)
        #pragma unroll
        for (int ks = 0; ks < 2; ks++) {
            int col = wn + bi * 16 + lane16;
            int kx = ks * 16 + lhi;
            offB[bi][ks] = (uint32_t)A_HBYTES + (uint32_t)(col * PAH + kx) * 2u;
        }

    const __half* Ag = A  + (size_t)m0 * K;
    const __half* Bg = Bt + (size_t)n0 * K;

    float acc[4][4][4];
    #pragma unroll
    for (int i = 0; i < 4; i++)
        #pragma unroll
        for (int j = 0; j < 4; j++)
            #pragma unroll
            for (int r = 0; r < 4; r++) acc[i][j][r] = 0.f;

    int ntiles = K >> 5;

    int lr = tid >> 2, lc = tid & 3;
    auto load_stage = [&](int s, int kc) {
        uint32_t base = smb + s * STAGE_HB;
        #pragma unroll
        for (int i = 0; i < 2; i++) {
            int r = lr + i * 64;
            CP16(base + r * 80 + lc * 16, Ag + (size_t)r * K + kc * 32 + lc * 8);
        }
        uint32_t bb = base + A_HBYTES;
        #pragma unroll
        for (int i = 0; i < 2; i++) {
            int r = lr + i * 64;
            CP16(bb + r * 80 + lc * 16, Bg + (size_t)r * K + kc * 32 + lc * 8);
        }
    };

    load_stage(0, 0); CP_COMMIT();
    load_stage(1, 1); CP_COMMIT();

    for (int kt = 0; kt < ntiles; kt++) {
        asm volatile("cp.async.wait_group 1;");
        __syncthreads();

        int pf = kt + H_STAGES - 1;
        if (pf < ntiles) load_stage(pf % H_STAGES, pf);
        CP_COMMIT();

        uint32_t sbase = smb + (kt % H_STAGES) * STAGE_HB;
        #pragma unroll
        for (int ks = 0; ks < 2; ks++) {
            uint32_t bf[4][2];
            #pragma unroll
            for (int bi = 0; bi < 2; bi++) {
                uint32_t r[4];
                ldm_x4(r, sbase + offB[bi][ks]);
                bf[2 * bi][0] = r[0]; bf[2 * bi + 1][0] = r[1];
                bf[2 * bi][1] = r[2]; bf[2 * bi + 1][1] = r[3];
            }
            #pragma unroll
            for (int mt = 0; mt < 4; mt++) {
                uint32_t af[4];
                ldm_x4(af, sbase + offA[mt][ks]);
                #pragma unroll
                for (int nt = 0; nt < 4; nt++)
                    mma_f16(acc[mt][nt], af, bf[nt]);
            }
        }
    }

    #pragma unroll
    for (int mt = 0; mt < 4; mt++) {
        int r0 = m0 + wm + mt * 16 + g;
        #pragma unroll
        for (int nt = 0; nt < 4; nt++) {
            int cl = n0 + wn + nt * 8 + 2 * c;
            #pragma unroll
            for (int half_i = 0; half_i < 2; half_i++) {
                int rr = r0 + half_i * 8;
                float v0 = acc[mt][nt][half_i * 2 + 0];
                float v1 = acc[mt][nt][half_i * 2 + 1];
                size_t idx = (size_t)rr * NC + cl;
                if (MODE == 0) {
                    *(float2*)((float*)C + idx) = make_float2(v0, v1);
                } else if (MODE == 1) {
                    v0 += Res[idx]; v1 += Res[idx + 1];
                    *(float2*)((float*)C + idx) = make_float2(v0, v1);
                } else {
                    float g0 = Res[idx], g1 = Res[idx + 1];
                    v0 *= g0 / (1.f + expf(-g0));
                    v1 *= g1 / (1.f + expf(-g1));
                    *(__half2*)((__half*)C + idx) = __floats2half2_rn(v0, v1);
                }
            }
        }
    }
}

template<int MODE, typename OT>
__global__ __launch_bounds__(256, 2) void hgemm_kernel(
    const __half* __restrict__ A, const __half* __restrict__ Bt,
    const float* __restrict__ Res, OT* __restrict__ C, int N, int K)
{
    hgemm_tile<MODE, OT>(A, Bt, Res, C, N, K, blockIdx.y * 128, blockIdx.x * 128);
}

__global__ __launch_bounds__(256, 2) void qkv_h_kernel(
    const __half* __restrict__ A,
    const __half* __restrict__ Bq, const __half* __restrict__ Bk,
    const __half* __restrict__ Bv,
    float* __restrict__ Cq, float* __restrict__ Ck, float* __restrict__ Cv,
    int K)
{
    int nb = blockIdx.x, m0 = blockIdx.y * 128;
    if (nb < 8)
        hgemm_tile<0, float>(A, Bq, nullptr, Cq, 1024, K, m0, nb * 128);
    else if (nb < 12)
        hgemm_tile<0, float>(A, Bk + (size_t)(nb - 8) * 128 * K, nullptr,
                             Ck + (nb - 8) * 128, 512, K, m0, 0);
    else
        hgemm_tile<0, float>(A, Bv + (size_t)(nb - 12) * 128 * K, nullptr,
                             Cv + (nb - 12) * 128, 512, K, m0, 0);
}

// ---------------- RoPE: fp32 in -> half out (+ q prescale) -------------------
__global__ void rope_kernel(const float* __restrict__ q, const float* __restrict__ k,
                            __half* __restrict__ qh, __half* __restrict__ kh)
{
    int row = blockIdx.x;
    int t = row & (Tt - 1);
    const float qscale = 0.08838834764831845f;
    __shared__ float s_sin[64], s_cos[64];
    if (threadIdx.x < 64) {
        float inv = expf(-logf(10000.0f) * (2.0f * threadIdx.x) / 128.0f);
        float ang = (float)t * inv;
        s_sin[threadIdx.x] = sinf(ang);
        s_cos[threadIdx.x] = cosf(ang);
    }
    __syncthreads();
    for (int p = threadIdx.x; p < 512; p += 256) {
        int head = p >> 6, i = p & 63;
        const float* base = q + (size_t)row * 1024 + head * 128;
        __half* ob = qh + (size_t)row * 1024 + head * 128;
        float x1 = base[i], x2 = base[i + 64];
        float s = s_sin[i], c = s_cos[i];
        ob[i]      = __float2half_rn((x1 * c - x2 * s) * qscale);
        ob[i + 64] = __float2half_rn((x2 * c + x1 * s) * qscale);
    }
    for (int p = threadIdx.x; p < 256; p += 256) {
        int head = p >> 6, i = p & 63;
        const float* base = k + (size_t)row * 512 + head * 128;
        __half* ob = kh + (size_t)row * 512 + head * 128;
        float x1 = base[i], x2 = base[i + 64];
        float s = s_sin[i], c = s_cos[i];
        ob[i]      = __float2half_rn(x1 * c - x2 * s);
        ob[i + 64] = __float2half_rn(x2 * c + x1 * s);
    }
}

// ---------------- attention: FP16 MMA flash + ldmatrix -----------------------
// smem (halves): Qs[64][128]@0, Ks[64][128]@8192, Vt[128][64]@16384,
//                Ps[64][64]@24576; floats rmax[128]/rsum[128] @ half-off 28672
#define ATTN_SMEM ((28672 + 512) * 2)
#define QS_B 0
#define KS_B (8192*2)
#define VT_B (16384*2)
#define PS_B (24576*2)
__global__ __launch_bounds__(256, 2) void attn_kernel(
    const __half* __restrict__ Q, const __half* __restrict__ K,
    const float* __restrict__ V, __half* __restrict__ O)
{
    extern __shared__ __half sma[];
    __half* Qs = sma;
    __half* Ks = sma + 8192;
    __half* Vt = sma + 16384;
    __half* Ps = sma + 24576;
    float* rmax = (float*)(sma + 28672);
    float* rsum = rmax + 128;
    uint32_t smb;
    asm("{ .reg .u64 t; cvta.to.shared.u64 t, %1; cvt.u32.u64 %0, t; }"
        : "=r"(smb) : "l"(sma));

    int qb = blockIdx.x, h = blockIdx.y, b = blockIdx.z;
    int q0 = qb * 64;
    int tid = threadIdx.x, lane = tid & 31, warp = tid >> 5;
    int wq = warp >> 1, wn = warp & 1, g = lane >> 2, c = lane & 3;
    int lane16 = lane & 15;
    int hb = (lane & 16) >> 4;     // +1 chunk if lane>=16

    // per-lane ldmatrix row bases (byte offsets; chunk XOR applied per call)
    int rowQ = 16 * wq + lane16;   int rq7 = rowQ & 7;
    uint32_t qrow_b = QS_B + (uint32_t)rowQ * 256u;           // pitch 128 halves
    uint32_t prow_b = PS_B + (uint32_t)rowQ * 128u;           // pitch 64 halves
    int colK0 = wn * 32 + lane16, colK1 = colK0 + 16;
    uint32_t krow_b0 = KS_B + (uint32_t)colK0 * 256u; int k07 = colK0 & 7;
    uint32_t krow_b1 = KS_B + (uint32_t)colK1 * 256u; int k17 = colK1 & 7;
    uint32_t vrow_b[4]; int v7[4];
    #pragma unroll
    for (int bi = 0; bi < 4; bi++) {
        int colV = wn * 64 + bi * 16 + lane16;
        vrow_b[bi] = VT_B + (uint32_t)colV * 128u;
        v7[bi] = colV & 7;
    }

    // Q tile
    const __half* Qg = Q + (size_t)(b * Tt + q0) * 1024 + h * 128;
    #pragma unroll
    for (int p = 0; p < 4; p++) {
        int idx = tid + p * 256;
        int row = idx >> 4, ch = idx & 15;
        uint4 v = *(const uint4*)(Qg + (size_t)row * 1024 + ch * 8);
        *(uint4*)(Qs + row * 128 + ((ch ^ (row & 7)) << 3)) = v;
    }

    int r0 = 16 * wq + g;
    int r1 = r0 + 8;
    float rm0 = -1e30f, rm1 = -1e30f, rl0 = 0.f, rl1 = 0.f;
    float Oacc[8][4];
    #pragma unroll
    for (int i = 0; i < 8; i++)
        #pragma unroll
        for (int j = 0; j < 4; j++) Oacc[i][j] = 0.f;

    int kvh = h & 3;
    const __half* Kg = K + (size_t)b * Tt * 512 + kvh * 128;
    const float*  Vg = V + (size_t)b * Tt * 512 + kvh * 128;

    int lkey = tid >> 2;
    int ldq  = (tid & 3) * 4;

    int jlo = (qb >= 8) ? qb - 8 : 0;
    for (int jt = jlo; jt <= qb; jt++) {
        int k0 = jt * 64;
        __syncthreads();
        #pragma unroll
        for (int p = 0; p < 4; p++) {
            int idx = tid + p * 256;
            int row = idx >> 4, ch = idx & 15;
            uint4 v = *(const uint4*)(Kg + (size_t)(k0 + row) * 512 + ch * 8);
            *(uint4*)(Ks + row * 128 + ((ch ^ (row & 7)) << 3)) = v;
        }
        #pragma unroll
        for (int p = 0; p < 8; p++) {
            int d0 = ldq + p * 16;
            float4 vv = *(const float4*)(Vg + (size_t)(k0 + lkey) * 512 + d0);
            Vt[(d0 + 0) * 64 + swz(lkey, d0 + 0)] = __float2half_rn(vv.x);
            Vt[(d0 + 1) * 64 + swz(lkey, d0 + 1)] = __float2half_rn(vv.y);
            Vt[(d0 + 2) * 64 + swz(lkey, d0 + 2)] = __float2half_rn(vv.z);
            Vt[(d0 + 3) * 64 + swz(lkey, d0 + 3)] = __float2half_rn(vv.w);
        }
        __syncthreads();

        // ---- S = Q @ K^T ----
        float sacc[4][4];
        #pragma unroll
        for (int i = 0; i < 4; i++)
            #pragma unroll
            for (int j = 0; j < 4; j++) sacc[i][j] = 0.f;
        #pragma unroll
        for (int ks = 0; ks < 8; ks++) {
            int chunk = ks * 2 + hb;
            uint32_t af[4];
            ldm_x4(af, smb + qrow_b + (uint32_t)((chunk ^ rq7) << 4));
            uint32_t bf[4][2];
            {
                uint32_t r[4];
                ldm_x4(r, smb + krow_b0 + (uint32_t)((chunk ^ k07) << 4));
                bf[0][0] = r[0]; bf[1][0] = r[1]; bf[0][1] = r[2]; bf[1][1] = r[3];
                ldm_x4(r, smb + krow_b1 + (uint32_t)((chunk ^ k17) << 4));
                bf[2][0] = r[0]; bf[3][0] = r[1]; bf[2][1] = r[2]; bf[3][1] = r[3];
            }
            #pragma unroll
            for (int nt = 0; nt < 4; nt++)
                mma_f16(sacc[nt], af, bf[nt]);
        }

        // ---- softcap + mask ----
        float pm0 = -INFINITY, pm1 = -INFINITY;
        int qt0 = q0 + r0, qt1 = q0 + r1;
        #pragma unroll
        for (int nt = 0; nt < 4; nt++) {
            #pragma unroll
            for (int e = 0; e < 4; e++) {
                int col = wn * 32 + nt * 8 + 2 * c + (e & 1);
                int ktg = k0 + col;
                int qt = (e >> 1) ? qt1 : qt0;
                float sv = softcap50(sacc[nt][e]);
                bool ok = (ktg <= qt) && (qt - ktg < WINs);
                sv = ok ? sv : -INFINITY;
                sacc[nt][e] = sv;
                if (e >> 1) pm1 = fmaxf(pm1, sv); else pm0 = fmaxf(pm0, sv);
            }
        }
        pm0 = fmaxf(pm0, __shfl_xor_sync(0xffffffffu, pm0, 1));
        pm0 = fmaxf(pm0, __shfl_xor_sync(0xffffffffu, pm0, 2));
        pm1 = fmaxf(pm1, __shfl_xor_sync(0xffffffffu, pm1, 1));
        pm1 = fmaxf(pm1, __shfl_xor_sync(0xffffffffu, pm1, 2));
        if (c == 0) { rmax[wn * 64 + r0] = pm0; rmax[wn * 64 + r1] = pm1; }
        __syncthreads();

        float mn0 = fmaxf(rm0, fmaxf(rmax[r0], rmax[64 + r0]));
        float mn1 = fmaxf(rm1, fmaxf(rmax[r1], rmax[64 + r1]));
        float al0 = __expf(rm0 - mn0); rm0 = mn0;
        float al1 = __expf(rm1 - mn1); rm1 = mn1;

        float ps0 = 0.f, ps1 = 0.f;
        #pragma unroll
        for (int nt = 0; nt < 4; nt++) {
            int colb = wn * 32 + nt * 8 + 2 * c;
            __half2 h0 = __floats2half2_rn(__expf(sacc[nt][0] - mn0),
                                           __expf(sacc[nt][1] - mn0));
            __half2 h1 = __floats2half2_rn(__expf(sacc[nt][2] - mn1),
                                           __expf(sacc[nt][3] - mn1));
            float2 f0 = __half22float2(h0), f1 = __half22float2(h1);
            ps0 += f0.x + f0.y;
            ps1 += f1.x + f1.y;
            *(__half2*)&Ps[r0 * 64 + swz(colb, r0)] = h0;
            *(__half2*)&Ps[r1 * 64 + swz(colb, r1)] = h1;
        }
        ps0 += __shfl_xor_sync(0xffffffffu, ps0, 1);
        ps0 += __shfl_xor_sync(0xffffffffu, ps0, 2);
        ps1 += __shfl_xor_sync(0xffffffffu, ps1, 1);
        ps1 += __shfl_xor_sync(0xffffffffu, ps1, 2);
        if (c == 0) { rsum[wn * 64 + r0] = ps0; rsum[wn * 64 + r1] = ps1; }

        #pragma unroll
        for (int i = 0; i < 8; i++) {
            Oacc[i][0] *= al0; Oacc[i][1] *= al0;
            Oacc[i][2] *= al1; Oacc[i][3] *= al1;
        }
        __syncthreads();
        rl0 = rl0 * al0 + rsum[r0] + rsum[64 + r0];
        rl1 = rl1 * al1 + rsum[r1] + rsum[64 + r1];

        // ---- O += P @ V ----
        #pragma unroll
        for (int ks = 0; ks < 4; ks++) {
            int chunk = ks * 2 + hb;
            uint32_t af[4];
            ldm_x4(af, smb + prow_b + (uint32_t)((chunk ^ rq7) << 4));
            uint32_t vb[8][2];
            #pragma unroll
            for (int bi = 0; bi < 4; bi++) {
                uint32_t r[4];
                ldm_x4(r, smb + vrow_b[bi] + (uint32_t)((chunk ^ v7[bi]) << 4));
                vb[2 * bi][0] = r[0]; vb[2 * bi + 1][0] = r[1];
                vb[2 * bi][1] = r[2]; vb[2 * bi + 1][1] = r[3];
            }
            #pragma unroll
            for (int nt = 0; nt < 8; nt++)
                mma_f16(Oacc[nt], af, vb[nt]);
        }
    }

    float li0 = 1.f / rl0, li1 = 1.f / rl1;
    __half* Og = O + (size_t)(b * Tt + q0) * 1024 + h * 128;
    #pragma unroll
    for (int nt = 0; nt < 8; nt++) {
        int col = wn * 64 + nt * 8 + 2 * c;
        *(__half2*)(Og + (size_t)r0 * 1024 + col) =
            __floats2half2_rn(Oacc[nt][0] * li0, Oacc[nt][1] * li0);
        *(__half2*)(Og + (size_t)r1 * 1024 + col) =
            __floats2half2_rn(Oacc[nt][2] * li1, Oacc[nt][3] * li1);
    }
}

// ---------------- launch ----------------
extern "C" void kernel_launch(void* const* d_in, const int* in_sizes, int n_in,
                              void* d_out, int out_size)
{
    const float* x        = (const float*)d_in[0];
    const float* q_kernel = (const float*)d_in[1];
    const float* k_kernel = (const float*)d_in[2];
    const float* v_kernel = (const float*)d_in[3];
    const float* out_kern = (const float*)d_in[4];
    const float* attn_sc  = (const float*)d_in[5];
    const float* mlp_sc   = (const float*)d_in[6];
    const float* gate_k   = (const float*)d_in[7];
    const float* up_k     = (const float*)d_in[8];
    const float* down_k   = (const float*)d_in[9];
    float* out = (float*)d_out;

    __half *p_h, *p_attnh, *p_act, *p_qh, *p_kh;
    float *p_q, *p_k, *p_v, *p_x2, *p_gate;
    __half *w_q, *w_k, *w_v, *w_o, *w_g, *w_u, *w_d;
    cudaGetSymbolAddress((void**)&p_h,     g_h);
    cudaGetSymbolAddress((void**)&p_q,     g_q);
    cudaGetSymbolAddress((void**)&p_k,     g_k);
    cudaGetSymbolAddress((void**)&p_v,     g_v);
    cudaGetSymbolAddress((void**)&p_qh,    g_qh);
    cudaGetSymbolAddress((void**)&p_kh,    g_kh);
    cudaGetSymbolAddress((void**)&p_attnh, g_attnh);
    cudaGetSymbolAddress((void**)&p_x2,    g_x2);
    cudaGetSymbolAddress((void**)&p_gate,  g_gate);
    cudaGetSymbolAddress((void**)&p_act,   g_act);
    cudaGetSymbolAddress((void**)&w_q,     g_wq);
    cudaGetSymbolAddress((void**)&w_k,     g_wk);
    cudaGetSymbolAddress((void**)&w_v,     g_wv);
    cudaGetSymbolAddress((void**)&w_o,     g_wo);
    cudaGetSymbolAddress((void**)&w_g,     g_wg);
    cudaGetSymbolAddress((void**)&w_u,     g_wu);
    cudaGetSymbolAddress((void**)&w_d,     g_wd);

    cudaFuncSetAttribute(attn_kernel, cudaFuncAttributeMaxDynamicSharedMemorySize, ATTN_SMEM);
    cudaFuncSetAttribute(qkv_h_kernel, cudaFuncAttributeMaxDynamicSharedMemorySize, HGEMM_SMEM);
    cudaFuncSetAttribute((hgemm_kernel<0, float>),  cudaFuncAttributeMaxDynamicSharedMemorySize, HGEMM_SMEM);
    cudaFuncSetAttribute((hgemm_kernel<1, float>),  cudaFuncAttributeMaxDynamicSharedMemorySize, HGEMM_SMEM);
    cudaFuncSetAttribute((hgemm_kernel<2, __half>), cudaFuncAttributeMaxDynamicSharedMemorySize, HGEMM_SMEM);

    // 0) transpose + fp16 weights: [K,N] -> [N,K]
    transpose_cvt_kernel<<<dim3(32, 32),  256>>>(q_kernel, w_q, 1024, 1024);
    transpose_cvt_kernel<<<dim3(16, 32),  256>>>(k_kernel, w_k, 1024, 512);
    transpose_cvt_kernel<<<dim3(16, 32),  256>>>(v_kernel, w_v, 1024, 512);
    transpose_cvt_kernel<<<dim3(32, 32),  256>>>(out_kern, w_o, 1024, 1024);
    transpose_cvt_kernel<<<dim3(128, 32), 256>>>(gate_k,   w_g, 1024, 4096);
    transpose_cvt_kernel<<<dim3(128, 32), 256>>>(up_k,     w_u, 1024, 4096);
    transpose_cvt_kernel<<<dim3(32, 128), 256>>>(down_k,   w_d, 4096, 1024);

    // 1) h = rmsnorm(x, attn_scale) -> fp16
    rmsnorm_h_kernel<<<Mrows, 256>>>(x, attn_sc, p_h);
    // 2) fused q/k/v projections
    qkv_h_kernel<<<dim3(16, 32), 256, HGEMM_SMEM>>>(p_h, w_q, w_k, w_v, p_q, p_k, p_v, 1024);
    // 3) rope -> half q (prescaled), half k
    rope_kernel<<<Mrows, 256>>>(p_q, p_k, p_qh, p_kh);
    // 4) attention
    attn_kernel<<<dim3(Tt / 64, Hh, Bb), 256, ATTN_SMEM>>>(p_qh, p_kh, p_v, p_attnh);
    // 5) out projection + residual
    hgemm_kernel<1, float><<<dim3(8, 32), 256, HGEMM_SMEM>>>(p_attnh, w_o, x, p_x2, 1024, 1024);
    // 6) h = rmsnorm(x2, mlp_scale) -> fp16
    rmsnorm_h_kernel<<<Mrows, 256>>>(p_x2, mlp_sc, p_h);
    // 7) gate, then up with fused SwiGLU -> fp16 act
    hgemm_kernel<0, float><<<dim3(32, 32), 256, HGEMM_SMEM>>>(p_h, w_g, nullptr, p_gate, HIDm, 1024);
    hgemm_kernel<2, __half><<<dim3(32, 32), 256, HGEMM_SMEM>>>(p_h, w_u, p_gate, p_act, HIDm, 1024);
    // 8) down + residual -> out
    hgemm_kernel<1, float><<<dim3(8, 32), 256, HGEMM_SMEM>>>(p_act, w_d, p_x2, out, 1024, HIDm);
}

// round 11
// speedup vs baseline: 6.2466x; 1.0295x over previous
#include <cuda_runtime.h>
#include <cuda_fp16.h>
#include <stdint.h>
#include <math.h>

#define Bb   2
#define Tt   2048
#define Cc   1024
#define Hh   8
#define KVh  4
#define Dd   128
#define WINs 512
#define HIDm 4096
#define Mrows (Bb*Tt)   // 4096

// ---------------- scratch ----------------
__device__ __half g_h   [Mrows*Cc];
__device__ float  g_q   [Mrows*Hh*Dd];
__device__ float  g_k   [Mrows*KVh*Dd];
__device__ float  g_v   [Mrows*KVh*Dd];
__device__ __half g_qh  [Mrows*Hh*Dd];
__device__ __half g_kh  [Mrows*KVh*Dd];
__device__ __half g_vt  [Bb*KVh*Dd*Tt];   // V transposed: [b][kvh][d][t] fp16
__device__ __half g_attnh[Mrows*Hh*Dd];
__device__ float  g_x2  [Mrows*Cc];
__device__ __half g_gateh[Mrows*HIDm];    // silu(gate) fp16
__device__ __half g_act [Mrows*HIDm];
// transposed+converted weights [N][K] fp16
__device__ __half g_wq[1048576];
__device__ __half g_wk[524288];
__device__ __half g_wv[524288];
__device__ __half g_wo[1048576];
__device__ __half g_wg[4194304];
__device__ __half g_wu[4194304];
__device__ __half g_wd[4194304];

// ---------------- helpers ----------------
__device__ __forceinline__ void mma_f16(float* d, const uint32_t* a, const uint32_t* b) {
    asm volatile(
        "mma.sync.aligned.m16n8k16.row.col.f32.f16.f16.f32 "
        "{%0,%1,%2,%3},{%4,%5,%6,%7},{%8,%9},{%0,%1,%2,%3};"
        : "+f"(d[0]), "+f"(d[1]), "+f"(d[2]), "+f"(d[3])
        : "r"(a[0]), "r"(a[1]), "r"(a[2]), "r"(a[3]),
          "r"(b[0]), "r"(b[1]));
}
__device__ __forceinline__ void ldm_x4(uint32_t* r, uint32_t addr) {
    asm volatile("ldmatrix.sync.aligned.m8n8.x4.shared.b16 {%0,%1,%2,%3}, [%4];"
        : "=r"(r[0]), "=r"(r[1]), "=r"(r[2]), "=r"(r[3]) : "r"(addr));
}

#define CP16(dst, src) \
    asm volatile("cp.async.cg.shared.global [%0], [%1], 16;" :: "r"(dst), "l"(src))
#define CP_COMMIT() asm volatile("cp.async.commit_group;")

// softcap: 50*tanh(s/50)
__device__ __forceinline__ float softcap50(float s) {
    float x = s * 0.02f;
    float x2 = x * x;
    float t;
    if (x2 <= 0.09f) {
        t = x * (1.0f + x2 * (-0.333333333f + x2 * (0.133333333f + x2 * (-0.053968254f))));
    } else {
        t = tanhf(x);
    }
    return 50.0f * t;
}

// ---------------- weight transpose + fp16 convert: in[K][N] -> out[N][K] -----
__global__ void transpose_cvt_kernel(const float* __restrict__ in,
                                     __half* __restrict__ out, int K, int N)
{
    __shared__ float t[32][33];
    int n0 = blockIdx.x * 32, k0 = blockIdx.y * 32;
    int tx = threadIdx.x & 31, ty = threadIdx.x >> 5;
    #pragma unroll
    for (int i = 0; i < 4; i++) {
        int k = k0 + ty + i * 8;
        t[ty + i * 8][tx] = in[(size_t)k * N + n0 + tx];
    }
    __syncthreads();
    #pragma unroll
    for (int i = 0; i < 4; i++) {
        int n = n0 + ty + i * 8;
        out[(size_t)n * K + k0 + tx] = __float2half_rn(t[tx][ty + i * 8]);
    }
}

// ---------------- V transpose: fp32 [t][kvh*128+d] -> fp16 [b][kvh][d][T] ----
__global__ void vtrans_kernel(const float* __restrict__ V, __half* __restrict__ Vt)
{
    __shared__ float t[32][33];
    int t0 = blockIdx.x * 32, d0 = blockIdx.y * 32, bk = blockIdx.z;
    int b = bk >> 2, kvh = bk & 3;
    int tx = threadIdx.x & 31, ty = threadIdx.x >> 5;
    #pragma unroll
    for (int i = 0; i < 4; i++) {
        int tt = t0 + ty + i * 8;
        t[ty + i * 8][tx] = V[((size_t)(b * Tt + tt)) * 512 + kvh * 128 + d0 + tx];
    }
    __syncthreads();
    #pragma unroll
    for (int i = 0; i < 4; i++) {
        int d = d0 + ty + i * 8;
        Vt[((size_t)(bk * 128 + d)) * Tt + t0 + tx] = __float2half_rn(t[tx][ty + i * 8]);
    }
}

// ---------------- rmsnorm -> fp16 ----------------
__global__ void rmsnorm_h_kernel(const float* __restrict__ x,
                                 const float* __restrict__ scale,
                                 __half* __restrict__ y)
{
    int row = blockIdx.x;
    const float4* xr = (const float4*)(x + (size_t)row * Cc);
    float4 v = xr[threadIdx.x];
    float ss = v.x*v.x + v.y*v.y + v.z*v.z + v.w*v.w;
    #pragma unroll
    for (int o = 16; o; o >>= 1) ss += __shfl_xor_sync(0xffffffffu, ss, o);
    __shared__ float wsum[8];
    if ((threadIdx.x & 31) == 0) wsum[threadIdx.x >> 5] = ss;
    __syncthreads();
    if (threadIdx.x < 8) {
        float t = wsum[threadIdx.x];
        #pragma unroll
        for (int o = 4; o; o >>= 1) t += __shfl_xor_sync(0xffu, t, o);
        if (threadIdx.x == 0) wsum[0] = t;
    }
    __syncthreads();
    float inv = rsqrtf(wsum[0] * (1.0f / Cc) + 1e-6f);
    float4 sc = ((const float4*)scale)[threadIdx.x];
    __half2 h0 = __floats2half2_rn(v.x * inv * (1.f + sc.x), v.y * inv * (1.f + sc.y));
    __half2 h1 = __floats2half2_rn(v.z * inv * (1.f + sc.z), v.w * inv * (1.f + sc.w));
    uint2 u = make_uint2(*(uint32_t*)&h0, *(uint32_t*)&h1);
    *(uint2*)(y + (size_t)row * Cc + threadIdx.x * 4) = u;
}

// ---------------- FP16 GEMM (m16n8k16, cp.async 3-stage, ldmatrix) -----------
// MODE 0: C=acc (float)      MODE 1: C=acc+Res (float)
// MODE 3: C=silu(acc) (half) MODE 4: C=acc*Res (Res half, C half)
#define PAH 40
#define A_HBYTES (128*PAH*2)
#define STAGE_HB (2*A_HBYTES)
#define H_STAGES 3
#define HGEMM_SMEM (H_STAGES*STAGE_HB)

template<int MODE, typename OT, typename RT>
__device__ __forceinline__ void hgemm_tile(
    const __half* __restrict__ A, const __half* __restrict__ Bt,
    const RT* __restrict__ Res, OT* __restrict__ C,
    int NC, int K, int m0, int n0)
{
    extern __shared__ __half smh[];
    uint32_t smb;
    asm("{ .reg .u64 t; cvta.to.shared.u64 t, %1; cvt.u32.u64 %0, t; }"
        : "=r"(smb) : "l"(smh));

    int tid  = threadIdx.x;
    int lane = tid & 31, warp = tid >> 5;
    int wm = (warp & 1) * 64;
    int wn = (warp >> 1) * 32;
    int g = lane >> 2, c = lane & 3;
    int lane16 = lane & 15;
    int lhi = (lane & 16) >> 1;

    uint32_t offA[4][2], offB[2][2];
    #pragma unroll
    for (int mt = 0; mt < 4; mt++)
        #pragma unroll
        for (int ks = 0; ks < 2; ks++) {
            int row = wm + mt * 16 + lane16;
            int kx = ks * 16 + lhi;
            offA[mt][ks] = (uint32_t)(row * PAH + kx) * 2u;
        }
    #pragma unroll
    for (int bi = 0; bi < 2; bi++)
        #pragma unroll
        for (int ks = 0; ks < 2; ks++) {
            int col = wn + bi * 16 + lane16;
            int kx = ks * 16 + lhi;
            offB[bi][ks] = (uint32_t)A_HBYTES + (uint32_t)(col * PAH + kx) * 2u;
        }

    const __half* Ag = A  + (size_t)m0 * K;
    const __half* Bg = Bt + (size_t)n0 * K;

    float acc[4][4][4];
    #pragma unroll
    for (int i = 0; i < 4; i++)
        #pragma unroll
        for (int j = 0; j < 4; j++)
            #pragma unroll
            for (int r = 0; r < 4; r++) acc[i][j][r] = 0.f;

    int ntiles = K >> 5;

    int lr = tid >> 2, lc = tid & 3;
    auto load_stage = [&](int s, int kc) {
        uint32_t base = smb + s * STAGE_HB;
        #pragma unroll
        for (int i = 0; i < 2; i++) {
            int r = lr + i * 64;
            CP16(base + r * 80 + lc * 16, Ag + (size_t)r * K + kc * 32 + lc * 8);
        }
        uint32_t bb = base + A_HBYTES;
        #pragma unroll
        for (int i = 0; i < 2; i++) {
            int r = lr + i * 64;
            CP16(bb + r * 80 + lc * 16, Bg + (size_t)r * K + kc * 32 + lc * 8);
        }
    };

    load_stage(0, 0); CP_COMMIT();
    load_stage(1, 1); CP_COMMIT();

    for (int kt = 0; kt < ntiles; kt++) {
        asm volatile("cp.async.wait_group 1;");
        __syncthreads();

        int pf = kt + H_STAGES - 1;
        if (pf < ntiles) load_stage(pf % H_STAGES, pf);
        CP_COMMIT();

        uint32_t sbase = smb + (kt % H_STAGES) * STAGE_HB;
        #pragma unroll
        for (int ks = 0; ks < 2; ks++) {
            uint32_t bf[4][2];
            #pragma unroll
            for (int bi = 0; bi < 2; bi++) {
                uint32_t r[4];
                ldm_x4(r, sbase + offB[bi][ks]);
                bf[2 * bi][0] = r[0]; bf[2 * bi + 1][0] = r[1];
                bf[2 * bi][1] = r[2]; bf[2 * bi + 1][1] = r[3];
            }
            #pragma unroll
            for (int mt = 0; mt < 4; mt++) {
                uint32_t af[4];
                ldm_x4(af, sbase + offA[mt][ks]);
                #pragma unroll
                for (int nt = 0; nt < 4; nt++)
                    mma_f16(acc[mt][nt], af, bf[nt]);
            }
        }
    }

    #pragma unroll
    for (int mt = 0; mt < 4; mt++) {
        int r0 = m0 + wm + mt * 16 + g;
        #pragma unroll
        for (int nt = 0; nt < 4; nt++) {
            int cl = n0 + wn + nt * 8 + 2 * c;
            #pragma unroll
            for (int half_i = 0; half_i < 2; half_i++) {
                int rr = r0 + half_i * 8;
                float v0 = acc[mt][nt][half_i * 2 + 0];
                float v1 = acc[mt][nt][half_i * 2 + 1];
                size_t idx = (size_t)rr * NC + cl;
                if (MODE == 0) {
                    *(float2*)((float*)C + idx) = make_float2(v0, v1);
                } else if (MODE == 1) {
                    v0 += ((const float*)Res)[idx];
                    v1 += ((const float*)Res)[idx + 1];
                    *(float2*)((float*)C + idx) = make_float2(v0, v1);
                } else if (MODE == 3) {
                    v0 = v0 / (1.f + expf(-v0));
                    v1 = v1 / (1.f + expf(-v1));
                    *(__half2*)((__half*)C + idx) = __floats2half2_rn(v0, v1);
                } else if (MODE == 4) {
                    __half2 gh = *(const __half2*)((const __half*)Res + idx);
                    float2 gf = __half22float2(gh);
                    v0 *= gf.x; v1 *= gf.y;
                    *(__half2*)((__half*)C + idx) = __floats2half2_rn(v0, v1);
                }
            }
        }
    }
}

template<int MODE, typename OT, typename RT>
__global__ __launch_bounds__(256, 2) void hgemm_kernel(
    const __half* __restrict__ A, const __half* __restrict__ Bt,
    const RT* __restrict__ Res, OT* __restrict__ C, int N, int K)
{
    hgemm_tile<MODE, OT, RT>(A, Bt, Res, C, N, K, blockIdx.y * 128, blockIdx.x * 128);
}

__global__ __launch_bounds__(256, 2) void qkv_h_kernel(
    const __half* __restrict__ A,
    const __half* __restrict__ Bq, const __half* __restrict__ Bk,
    const __half* __restrict__ Bv,
    float* __restrict__ Cq, float* __restrict__ Ck, float* __restrict__ Cv,
    int K)
{
    int nb = blockIdx.x, m0 = blockIdx.y * 128;
    if (nb < 8)
        hgemm_tile<0, float, float>(A, Bq, (const float*)nullptr, Cq, 1024, K, m0, nb * 128);
    else if (nb < 12)
        hgemm_tile<0, float, float>(A, Bk + (size_t)(nb - 8) * 128 * K, (const float*)nullptr,
                                    Ck + (nb - 8) * 128, 512, K, m0, 0);
    else
        hgemm_tile<0, float, float>(A, Bv + (size_t)(nb - 12) * 128 * K, (const float*)nullptr,
                                    Cv + (nb - 12) * 128, 512, K, m0, 0);
}

// ---------------- RoPE: fp32 in -> half out (+ q prescale) -------------------
__global__ void rope_kernel(const float* __restrict__ q, const float* __restrict__ k,
                            __half* __restrict__ qh, __half* __restrict__ kh)
{
    int row = blockIdx.x;
    int t = row & (Tt - 1);
    const float qscale = 0.08838834764831845f;
    __shared__ float s_sin[64], s_cos[64];
    if (threadIdx.x < 64) {
        float inv = expf(-logf(10000.0f) * (2.0f * threadIdx.x) / 128.0f);
        float ang = (float)t * inv;
        s_sin[threadIdx.x] = sinf(ang);
        s_cos[threadIdx.x] = cosf(ang);
    }
    __syncthreads();
    for (int p = threadIdx.x; p < 512; p += 256) {
        int head = p >> 6, i = p & 63;
        const float* base = q + (size_t)row * 1024 + head * 128;
        __half* ob = qh + (size_t)row * 1024 + head * 128;
        float x1 = base[i], x2 = base[i + 64];
        float s = s_sin[i], c = s_cos[i];
        ob[i]      = __float2half_rn((x1 * c - x2 * s) * qscale);
        ob[i + 64] = __float2half_rn((x2 * c + x1 * s) * qscale);
    }
    for (int p = threadIdx.x; p < 256; p += 256) {
        int head = p >> 6, i = p & 63;
        const float* base = k + (size_t)row * 512 + head * 128;
        __half* ob = kh + (size_t)row * 512 + head * 128;
        float x1 = base[i], x2 = base[i + 64];
        float s = s_sin[i], c = s_cos[i];
        ob[i]      = __float2half_rn(x1 * c - x2 * s);
        ob[i + 64] = __float2half_rn(x2 * c + x1 * s);
    }
}

// ---------------- attention: 128-q tile, register Q/P, dbl-buf K/Vt ----------
// smem halves: Ks[2][64*128] @ 0,8192; Vts[2][128*64] @ 16384,24576
#define ATTN_SMEM (32768 * 2)   // 65536 B
__global__ __launch_bounds__(256, 1) void attn_kernel(
    const __half* __restrict__ Q, const __half* __restrict__ K,
    const __half* __restrict__ Vt, __half* __restrict__ O)
{
    extern __shared__ __half sma[];
    uint32_t smb;
    asm("{ .reg .u64 t; cvta.to.shared.u64 t, %1; cvt.u32.u64 %0, t; }"
        : "=r"(smb) : "l"(sma));

    int qb = blockIdx.x, h = blockIdx.y, b = blockIdx.z;
    int q0 = qb * 128;
    int tid = threadIdx.x, lane = tid & 31, warp = tid >> 5;
    int g = lane >> 2, c = lane & 3;
    int lane16 = lane & 15;
    int hb = (lane & 16) >> 4;

    // ---- Q fragments (register resident) ----
    const __half* Qg = Q + (size_t)(b * Tt + q0 + 16 * warp) * 1024 + h * 128;
    uint32_t qf[8][4];
    #pragma unroll
    for (int ks = 0; ks < 8; ks++) {
        int kx = 16 * ks + 2 * c;
        qf[ks][0] = *(const uint32_t*)(Qg + (size_t)g * 1024 + kx);
        qf[ks][1] = *(const uint32_t*)(Qg + (size_t)(g + 8) * 1024 + kx);
        qf[ks][2] = *(const uint32_t*)(Qg + (size_t)g * 1024 + kx + 8);
        qf[ks][3] = *(const uint32_t*)(Qg + (size_t)(g + 8) * 1024 + kx + 8);
    }

    float Oacc[16][4];
    #pragma unroll
    for (int i = 0; i < 16; i++)
        #pragma unroll
        for (int j = 0; j < 4; j++) Oacc[i][j] = 0.f;
    float rm0 = -1e30f, rm1 = -1e30f, rl0 = 0.f, rl1 = 0.f;

    int kvh = h & 3;
    const __half* Kg  = K  + (size_t)b * Tt * 512 + kvh * 128;
    const __half* Vtg = Vt + (size_t)(b * KVh + kvh) * 128 * Tt;

    // window coverage: lowest key = q0-511 -> tile floor((128qb-511)/64) = 2qb-8
    int jlo = (2 * qb - 8 > 0) ? 2 * qb - 8 : 0;
    int jhi = 2 * qb + 1;

    auto load_kv = [&](int s, int k0) {
        #pragma unroll
        for (int p = 0; p < 4; p++) {
            int idx = tid + p * 256;
            int row = idx >> 4, ch = idx & 15;
            CP16(smb + (uint32_t)(s * 8192 + row * 128 + ((ch ^ (row & 7)) << 3)) * 2u,
                 Kg + (size_t)(k0 + row) * 512 + ch * 8);
        }
        #pragma unroll
        for (int p = 0; p < 4; p++) {
            int idx = tid + p * 256;
            int row = idx >> 3, ch = idx & 7;
            CP16(smb + (uint32_t)(16384 + s * 8192 + row * 64 + ((ch ^ (row & 7)) << 3)) * 2u,
                 Vtg + (size_t)row * Tt + k0 + ch * 8);
        }
    };

    load_kv(0, jlo * 64); CP_COMMIT();

    int qt0 = q0 + 16 * warp + g;
    int qt1 = qt0 + 8;

    for (int jt = jlo; jt <= jhi; jt++) {
        int s = (jt - jlo) & 1;
        int k0 = jt * 64;

        asm volatile("cp.async.wait_group 0;");
        __syncthreads();
        if (jt < jhi) { load_kv(s ^ 1, k0 + 64); }
        CP_COMMIT();

        // ---- S = Q @ K^T ----
        float sacc[8][4];
        #pragma unroll
        for (int i = 0; i < 8; i++)
            #pragma unroll
            for (int j = 0; j < 4; j++) sacc[i][j] = 0.f;
        #pragma unroll
        for (int ks = 0; ks < 8; ks++) {
            int chunk = 2 * ks + hb;
            uint32_t bf[8][2];
            #pragma unroll
            for (int bi = 0; bi < 4; bi++) {
                int colK = bi * 16 + lane16;
                uint32_t r[4];
                ldm_x4(r, smb + (uint32_t)(s * 8192 + colK * 128 +
                                           ((chunk ^ (colK & 7)) << 3)) * 2u);
                bf[2 * bi][0] = r[0]; bf[2 * bi + 1][0] = r[1];
                bf[2 * bi][1] = r[2]; bf[2 * bi + 1][1] = r[3];
            }
            #pragma unroll
            for (int nt = 0; nt < 8; nt++)
                mma_f16(sacc[nt], qf[ks], bf[nt]);
        }

        // ---- softcap + mask + in-warp online softmax ----
        float pm0 = -INFINITY, pm1 = -INFINITY;
        #pragma unroll
        for (int nt = 0; nt < 8; nt++) {
            #pragma unroll
            for (int e = 0; e < 4; e++) {
                int ktg = k0 + nt * 8 + 2 * c + (e & 1);
                int qt = (e >> 1) ? qt1 : qt0;
                float sv = softcap50(sacc[nt][e]);
                bool ok = (ktg <= qt) && (qt - ktg < WINs);
                sv = ok ? sv : -INFINITY;
                sacc[nt][e] = sv;
                if (e >> 1) pm1 = fmaxf(pm1, sv); else pm0 = fmaxf(pm0, sv);
            }
        }
        pm0 = fmaxf(pm0, __shfl_xor_sync(0xffffffffu, pm0, 1));
        pm0 = fmaxf(pm0, __shfl_xor_sync(0xffffffffu, pm0, 2));
        pm1 = fmaxf(pm1, __shfl_xor_sync(0xffffffffu, pm1, 1));
        pm1 = fmaxf(pm1, __shfl_xor_sync(0xffffffffu, pm1, 2));

        float mn0 = fmaxf(rm0, pm0);
        float mn1 = fmaxf(rm1, pm1);
        float al0 = __expf(rm0 - mn0); rm0 = mn0;
        float al1 = __expf(rm1 - mn1); rm1 = mn1;

        uint32_t ph0[8], ph1[8];
        float ps0 = 0.f, ps1 = 0.f;
        #pragma unroll
        for (int nt = 0; nt < 8; nt++) {
            __half2 h0 = __floats2half2_rn(__expf(sacc[nt][0] - mn0),
                                           __expf(sacc[nt][1] - mn0));
            __half2 h1 = __floats2half2_rn(__expf(sacc[nt][2] - mn1),
                                           __expf(sacc[nt][3] - mn1));
            float2 f0 = __half22float2(h0), f1 = __half22float2(h1);
            ps0 += f0.x + f0.y;
            ps1 += f1.x + f1.y;
            ph0[nt] = *(uint32_t*)&h0;
            ph1[nt] = *(uint32_t*)&h1;
        }
        ps0 += __shfl_xor_sync(0xffffffffu, ps0, 1);
        ps0 += __shfl_xor_sync(0xffffffffu, ps0, 2);
        ps1 += __shfl_xor_sync(0xffffffffu, ps1, 1);
        ps1 += __shfl_xor_sync(0xffffffffu, ps1, 2);
        rl0 = rl0 * al0 + ps0;
        rl1 = rl1 * al1 + ps1;

        #pragma unroll
        for (int i = 0; i < 16; i++) {
            Oacc[i][0] *= al0; Oacc[i][1] *= al0;
            Oacc[i][2] *= al1; Oacc[i][3] *= al1;
        }

        // ---- O += P @ V (P from registers) ----
        #pragma unroll
        for (int ks = 0; ks < 4; ks++) {
            uint32_t af[4] = { ph0[2 * ks], ph1[2 * ks], ph0[2 * ks + 1], ph1[2 * ks + 1] };
            int chunk = 2 * ks + hb;
            uint32_t vb[16][2];
            #pragma unroll
            for (int bi = 0; bi < 8; bi++) {
                int d = bi * 16 + lane16;
                uint32_t r[4];
                ldm_x4(r, smb + (uint32_t)(16384 + s * 8192 + d * 64 +
                                           ((chunk ^ (d & 7)) << 3)) * 2u);
                vb[2 * bi][0] = r[0]; vb[2 * bi + 1][0] = r[1];
                vb[2 * bi][1] = r[2]; vb[2 * bi + 1][1] = r[3];
            }
            #pragma unroll
            for (int nt = 0; nt < 16; nt++)
                mma_f16(Oacc[nt], af, vb[nt]);
        }
    }

    float li0 = 1.f / rl0, li1 = 1.f / rl1;
    __half* Og = O + (size_t)(b * Tt + q0 + 16 * warp) * 1024 + h * 128;
    #pragma unroll
    for (int nt = 0; nt < 16; nt++) {
        int col = nt * 8 + 2 * c;
        *(__half2*)(Og + (size_t)g * 1024 + col) =
            __floats2half2_rn(Oacc[nt][0] * li0, Oacc[nt][1] * li0);
        *(__half2*)(Og + (size_t)(g + 8) * 1024 + col) =
            __floats2half2_rn(Oacc[nt][2] * li1, Oacc[nt][3] * li1);
    }
}

// ---------------- launch ----------------
extern "C" void kernel_launch(void* const* d_in, const int* in_sizes, int n_in,
                              void* d_out, int out_size)
{
    const float* x        = (const float*)d_in[0];
    const float* q_kernel = (const float*)d_in[1];
    const float* k_kernel = (const float*)d_in[2];
    const float* v_kernel = (const float*)d_in[3];
    const float* out_kern = (const float*)d_in[4];
    const float* attn_sc  = (const float*)d_in[5];
    const float* mlp_sc   = (const float*)d_in[6];
    const float* gate_k   = (const float*)d_in[7];
    const float* up_k     = (const float*)d_in[8];
    const float* down_k   = (const float*)d_in[9];
    float* out = (float*)d_out;

    __half *p_h, *p_attnh, *p_act, *p_qh, *p_kh, *p_vt, *p_gateh;
    float *p_q, *p_k, *p_v, *p_x2;
    __half *w_q, *w_k, *w_v, *w_o, *w_g, *w_u, *w_d;
    cudaGetSymbolAddress((void**)&p_h,     g_h);
    cudaGetSymbolAddress((void**)&p_q,     g_q);
    cudaGetSymbolAddress((void**)&p_k,     g_k);
    cudaGetSymbolAddress((void**)&p_v,     g_v);
    cudaGetSymbolAddress((void**)&p_qh,    g_qh);
    cudaGetSymbolAddress((void**)&p_kh,    g_kh);
    cudaGetSymbolAddress((void**)&p_vt,    g_vt);
    cudaGetSymbolAddress((void**)&p_attnh, g_attnh);
    cudaGetSymbolAddress((void**)&p_x2,    g_x2);
    cudaGetSymbolAddress((void**)&p_gateh, g_gateh);
    cudaGetSymbolAddress((void**)&p_act,   g_act);
    cudaGetSymbolAddress((void**)&w_q,     g_wq);
    cudaGetSymbolAddress((void**)&w_k,     g_wk);
    cudaGetSymbolAddress((void**)&w_v,     g_wv);
    cudaGetSymbolAddress((void**)&w_o,     g_wo);
    cudaGetSymbolAddress((void**)&w_g,     g_wg);
    cudaGetSymbolAddress((void**)&w_u,     g_wu);
    cudaGetSymbolAddress((void**)&w_d,     g_wd);

    cudaFuncSetAttribute(attn_kernel, cudaFuncAttributeMaxDynamicSharedMemorySize, ATTN_SMEM);
    cudaFuncSetAttribute(qkv_h_kernel, cudaFuncAttributeMaxDynamicSharedMemorySize, HGEMM_SMEM);
    cudaFuncSetAttribute((hgemm_kernel<0, float, float>),   cudaFuncAttributeMaxDynamicSharedMemorySize, HGEMM_SMEM);
    cudaFuncSetAttribute((hgemm_kernel<1, float, float>),   cudaFuncAttributeMaxDynamicSharedMemorySize, HGEMM_SMEM);
    cudaFuncSetAttribute((hgemm_kernel<3, __half, float>),  cudaFuncAttributeMaxDynamicSharedMemorySize, HGEMM_SMEM);
    cudaFuncSetAttribute((hgemm_kernel<4, __half, __half>), cudaFuncAttributeMaxDynamicSharedMemorySize, HGEMM_SMEM);

    // 0) weight transpose + fp16
    transpose_cvt_kernel<<<dim3(32, 32),  256>>>(q_kernel, w_q, 1024, 1024);
    transpose_cvt_kernel<<<dim3(16, 32),  256>>>(k_kernel, w_k, 1024, 512);
    transpose_cvt_kernel<<<dim3(16, 32),  256>>>(v_kernel, w_v, 1024, 512);
    transpose_cvt_kernel<<<dim3(32, 32),  256>>>(out_kern, w_o, 1024, 1024);
    transpose_cvt_kernel<<<dim3(128, 32), 256>>>(gate_k,   w_g, 1024, 4096);
    transpose_cvt_kernel<<<dim3(128, 32), 256>>>(up_k,     w_u, 1024, 4096);
    transpose_cvt_kernel<<<dim3(32, 128), 256>>>(down_k,   w_d, 4096, 1024);

    // 1) h = rmsnorm(x, attn_scale) -> fp16
    rmsnorm_h_kernel<<<Mrows, 256>>>(x, attn_sc, p_h);
    // 2) fused q/k/v projections
    qkv_h_kernel<<<dim3(16, 32), 256, HGEMM_SMEM>>>(p_h, w_q, w_k, w_v, p_q, p_k, p_v, 1024);
    // 3) rope -> half q (prescaled), half k ; V -> fp16 transposed
    rope_kernel<<<Mrows, 256>>>(p_q, p_k, p_qh, p_kh);
    vtrans_kernel<<<dim3(Tt / 32, 4, Bb * KVh), 256>>>(p_v, p_vt);
    // 4) attention
    attn_kernel<<<dim3(Tt / 128, Hh, Bb), 256, ATTN_SMEM>>>(p_qh, p_kh, p_vt, p_attnh);
    // 5) out projection + residual
    hgemm_kernel<1, float, float><<<dim3(8, 32), 256, HGEMM_SMEM>>>(p_attnh, w_o, x, p_x2, 1024, 1024);
    // 6) h = rmsnorm(x2, mlp_scale) -> fp16
    rmsnorm_h_kernel<<<Mrows, 256>>>(p_x2, mlp_sc, p_h);
    // 7) gate (silu, fp16), then up * gate -> fp16 act
    hgemm_kernel<3, __half, float><<<dim3(32, 32), 256, HGEMM_SMEM>>>(p_h, w_g, (const float*)nullptr, p_gateh, HIDm, 1024);
    hgemm_kernel<4, __half, __half><<<dim3(32, 32), 256, HGEMM_SMEM>>>(p_h, w_u, p_gateh, p_act, HIDm, 1024);
    // 8) down + residual -> out
    hgemm_kernel<1, float, float><<<dim3(8, 32), 256, HGEMM_SMEM>>>(p_act, w_d, p_x2, out, 1024, HIDm);
}

// round 12
// speedup vs baseline: 6.5425x; 1.0474x over previous
#include <cuda_runtime.h>
#include <cuda_fp16.h>
#include <stdint.h>
#include <math.h>

#define Bb   2
#define Tt   2048
#define Cc   1024
#define Hh   8
#define KVh  4
#define Dd   128
#define WINs 512
#define HIDm 4096
#define Mrows (Bb*Tt)   // 4096

// ---------------- scratch ----------------
__device__ __half g_h   [Mrows*Cc];
__device__ __half g_qh  [Mrows*Hh*Dd];
__device__ __half g_kh  [Mrows*KVh*Dd];
__device__ __half g_vh  [Mrows*KVh*Dd];
__device__ __half g_attnh[Mrows*Hh*Dd];
__device__ float  g_x2  [Mrows*Cc];
__device__ __half g_gateh[Mrows*HIDm];
__device__ __half g_act [Mrows*HIDm];
// fp16 weights in NATIVE [K][N] layout (no transpose)
__device__ __half g_wq[1048576];
__device__ __half g_wk[524288];
__device__ __half g_wv[524288];
__device__ __half g_wo[1048576];
__device__ __half g_wg[4194304];
__device__ __half g_wu[4194304];
__device__ __half g_wd[4194304];

// ---------------- helpers ----------------
__device__ __forceinline__ void mma_f16(float* d, const uint32_t* a, const uint32_t* b) {
    asm volatile(
        "mma.sync.aligned.m16n8k16.row.col.f32.f16.f16.f32 "
        "{%0,%1,%2,%3},{%4,%5,%6,%7},{%8,%9},{%0,%1,%2,%3};"
        : "+f"(d[0]), "+f"(d[1]), "+f"(d[2]), "+f"(d[3])
        : "r"(a[0]), "r"(a[1]), "r"(a[2]), "r"(a[3]),
          "r"(b[0]), "r"(b[1]));
}
__device__ __forceinline__ void ldm_x4(uint32_t* r, uint32_t addr) {
    asm volatile("ldmatrix.sync.aligned.m8n8.x4.shared.b16 {%0,%1,%2,%3}, [%4];"
        : "=r"(r[0]), "=r"(r[1]), "=r"(r[2]), "=r"(r[3]) : "r"(addr));
}
__device__ __forceinline__ void ldm_x4_t(uint32_t* r, uint32_t addr) {
    asm volatile("ldmatrix.sync.aligned.m8n8.x4.trans.shared.b16 {%0,%1,%2,%3}, [%4];"
        : "=r"(r[0]), "=r"(r[1]), "=r"(r[2]), "=r"(r[3]) : "r"(addr));
}

#define CP16(dst, src) \
    asm volatile("cp.async.cg.shared.global [%0], [%1], 16;" :: "r"(dst), "l"(src))
#define CP_COMMIT() asm volatile("cp.async.commit_group;")

// softcap: 50*tanh(s/50)
__device__ __forceinline__ float softcap50(float s) {
    float x = s * 0.02f;
    float x2 = x * x;
    float t;
    if (x2 <= 0.09f) {
        t = x * (1.0f + x2 * (-0.333333333f + x2 * (0.133333333f + x2 * (-0.053968254f))));
    } else {
        t = tanhf(x);
    }
    return 50.0f * t;
}

// ---------------- fp32 -> fp16 streaming convert ----------------
__global__ void cvt_kernel(const float4* __restrict__ in, __half* __restrict__ out, int n4)
{
    int i = blockIdx.x * blockDim.x + threadIdx.x;
    if (i < n4) {
        float4 v = in[i];
        __half2 h0 = __floats2half2_rn(v.x, v.y);
        __half2 h1 = __floats2half2_rn(v.z, v.w);
        *(uint2*)(out + (size_t)i * 4) = make_uint2(*(uint32_t*)&h0, *(uint32_t*)&h1);
    }
}

// ---------------- rmsnorm -> fp16 ----------------
__global__ void rmsnorm_h_kernel(const float* __restrict__ x,
                                 const float* __restrict__ scale,
                                 __half* __restrict__ y)
{
    int row = blockIdx.x;
    const float4* xr = (const float4*)(x + (size_t)row * Cc);
    float4 v = xr[threadIdx.x];
    float ss = v.x*v.x + v.y*v.y + v.z*v.z + v.w*v.w;
    #pragma unroll
    for (int o = 16; o; o >>= 1) ss += __shfl_xor_sync(0xffffffffu, ss, o);
    __shared__ float wsum[8];
    if ((threadIdx.x & 31) == 0) wsum[threadIdx.x >> 5] = ss;
    __syncthreads();
    if (threadIdx.x < 8) {
        float t = wsum[threadIdx.x];
        #pragma unroll
        for (int o = 4; o; o >>= 1) t += __shfl_xor_sync(0xffu, t, o);
        if (threadIdx.x == 0) wsum[0] = t;
    }
    __syncthreads();
    float inv = rsqrtf(wsum[0] * (1.0f / Cc) + 1e-6f);
    float4 sc = ((const float4*)scale)[threadIdx.x];
    __half2 h0 = __floats2half2_rn(v.x * inv * (1.f + sc.x), v.y * inv * (1.f + sc.y));
    __half2 h1 = __floats2half2_rn(v.z * inv * (1.f + sc.z), v.w * inv * (1.f + sc.w));
    uint2 u = make_uint2(*(uint32_t*)&h0, *(uint32_t*)&h1);
    *(uint2*)(y + (size_t)row * Cc + threadIdx.x * 4) = u;
}

// ---------------- FP16 GEMM: A[M,K]@B[K,N], B native layout, trans-ldmatrix --
// MODE 0: C=acc (float)       MODE 1: C=acc+Res (float)
// MODE 3: C=silu(acc) (half)  MODE 4: C=acc*Res (half,half)  MODE 5: C=acc (half)
#define PAH 40
#define A_HBYTES (128*PAH*2)       // 10240
#define B_HBYTES (32*128*2)        // 8192
#define STAGE_HB (A_HBYTES + B_HBYTES)   // 18432
#define H_STAGES 3
#define HGEMM_SMEM (H_STAGES*STAGE_HB)   // 55296

template<int MODE, typename OT, typename RT>
__device__ __forceinline__ void hgemm_tile(
    const __half* __restrict__ A, const __half* __restrict__ Bkn,
    const RT* __restrict__ Res, OT* __restrict__ C,
    int NB, int NC, int K, int m0, int n0)
{
    extern __shared__ __half smh[];
    uint32_t smb;
    asm("{ .reg .u64 t; cvta.to.shared.u64 t, %1; cvt.u32.u64 %0, t; }"
        : "=r"(smb) : "l"(smh));

    int tid  = threadIdx.x;
    int lane = tid & 31, warp = tid >> 5;
    int wm = (warp & 1) * 64;
    int wn = (warp >> 1) * 32;
    int g = lane >> 2, c = lane & 3;
    int lane16 = lane & 15;
    int lhi = (lane & 16) >> 1;
    int m_ = lane >> 3, r_ = lane & 7;
    int tb = (m_ >> 1) * 8 + r_;       // k-row within 16-block for trans B

    // A fragment offsets (non-trans, [m][k] pitch PAH)
    uint32_t offA[4][2];
    #pragma unroll
    for (int mt = 0; mt < 4; mt++)
        #pragma unroll
        for (int ks = 0; ks < 2; ks++) {
            int row = wm + mt * 16 + lane16;
            int kx = ks * 16 + lhi;
            offA[mt][ks] = (uint32_t)(row * PAH + kx) * 2u;
        }
    // B fragment offsets (trans, smem [k 32][n 128] rows of 256B)
    uint32_t offB[2][2];
    #pragma unroll
    for (int bi = 0; bi < 2; bi++)
        #pragma unroll
        for (int ks = 0; ks < 2; ks++) {
            int k = ks * 16 + tb;
            int nch = (wn >> 3) + bi * 2 + (m_ & 1);
            offB[bi][ks] = (uint32_t)A_HBYTES + (uint32_t)(k * 256 + (((nch) ^ r_) << 4));
        }

    const __half* Ag = A + (size_t)m0 * K;

    float acc[4][4][4];
    #pragma unroll
    for (int i = 0; i < 4; i++)
        #pragma unroll
        for (int j = 0; j < 4; j++)
            #pragma unroll
            for (int r = 0; r < 4; r++) acc[i][j][r] = 0.f;

    int ntiles = K >> 5;

    int lra = tid >> 2, lca = tid & 3;         // A loader
    int lrb = tid >> 3, lcb = (tid & 7) * 2;   // B loader (2 chunks)
    auto load_stage = [&](int s, int kc) {
        uint32_t base = smb + s * STAGE_HB;
        #pragma unroll
        for (int i = 0; i < 2; i++) {
            int r = lra + i * 64;
            CP16(base + r * 80 + lca * 16, Ag + (size_t)r * K + kc * 32 + lca * 8);
        }
        uint32_t bb = base + A_HBYTES;
        const __half* Bs = Bkn + (size_t)(kc * 32 + lrb) * NB + n0;
        #pragma unroll
        for (int i = 0; i < 2; i++) {
            int ch = lcb + i;
            CP16(bb + lrb * 256 + ((ch ^ (lrb & 7)) << 4), Bs + ch * 8);
        }
    };

    load_stage(0, 0); CP_COMMIT();
    load_stage(1, 1); CP_COMMIT();

    for (int kt = 0; kt < ntiles; kt++) {
        asm volatile("cp.async.wait_group 1;");
        __syncthreads();

        int pf = kt + H_STAGES - 1;
        if (pf < ntiles) load_stage(pf % H_STAGES, pf);
        CP_COMMIT();

        uint32_t sbase = smb + (kt % H_STAGES) * STAGE_HB;
        #pragma unroll
        for (int ks = 0; ks < 2; ks++) {
            uint32_t bf[4][2];
            #pragma unroll
            for (int bi = 0; bi < 2; bi++) {
                uint32_t r[4];
                ldm_x4_t(r, sbase + offB[bi][ks]);
                bf[2 * bi][0] = r[0]; bf[2 * bi + 1][0] = r[1];
                bf[2 * bi][1] = r[2]; bf[2 * bi + 1][1] = r[3];
            }
            #pragma unroll
            for (int mt = 0; mt < 4; mt++) {
                uint32_t af[4];
                ldm_x4(af, sbase + offA[mt][ks]);
                #pragma unroll
                for (int nt = 0; nt < 4; nt++)
                    mma_f16(acc[mt][nt], af, bf[nt]);
            }
        }
    }

    #pragma unroll
    for (int mt = 0; mt < 4; mt++) {
        int r0 = m0 + wm + mt * 16 + g;
        #pragma unroll
        for (int nt = 0; nt < 4; nt++) {
            int cl = n0 + wn + nt * 8 + 2 * c;
            #pragma unroll
            for (int half_i = 0; half_i < 2; half_i++) {
                int rr = r0 + half_i * 8;
                float v0 = acc[mt][nt][half_i * 2 + 0];
                float v1 = acc[mt][nt][half_i * 2 + 1];
                size_t idx = (size_t)rr * NC + cl;
                if (MODE == 0) {
                    *(float2*)((float*)C + idx) = make_float2(v0, v1);
                } else if (MODE == 1) {
                    v0 += ((const float*)Res)[idx];
                    v1 += ((const float*)Res)[idx + 1];
                    *(float2*)((float*)C + idx) = make_float2(v0, v1);
                } else if (MODE == 3) {
                    v0 = v0 / (1.f + expf(-v0));
                    v1 = v1 / (1.f + expf(-v1));
                    *(__half2*)((__half*)C + idx) = __floats2half2_rn(v0, v1);
                } else if (MODE == 4) {
                    __half2 gh = *(const __half2*)((const __half*)Res + idx);
                    float2 gf = __half22float2(gh);
                    v0 *= gf.x; v1 *= gf.y;
                    *(__half2*)((__half*)C + idx) = __floats2half2_rn(v0, v1);
                } else if (MODE == 5) {
                    *(__half2*)((__half*)C + idx) = __floats2half2_rn(v0, v1);
                }
            }
        }
    }
}

template<int MODE, typename OT, typename RT>
__global__ __launch_bounds__(256, 2) void hgemm_kernel(
    const __half* __restrict__ A, const __half* __restrict__ Bkn,
    const RT* __restrict__ Res, OT* __restrict__ C, int N, int K)
{
    hgemm_tile<MODE, OT, RT>(A, Bkn, Res, C, N, N, K, blockIdx.y * 128, blockIdx.x * 128);
}

__global__ __launch_bounds__(256, 2) void qkv_h_kernel(
    const __half* __restrict__ A,
    const __half* __restrict__ Bq, const __half* __restrict__ Bk,
    const __half* __restrict__ Bv,
    __half* __restrict__ Cq, __half* __restrict__ Ck, __half* __restrict__ Cv,
    int K)
{
    int nb = blockIdx.x, m0 = blockIdx.y * 128;
    if (nb < 8)
        hgemm_tile<5, __half, float>(A, Bq, (const float*)nullptr, Cq, 1024, 1024, K, m0, nb * 128);
    else if (nb < 12)
        hgemm_tile<5, __half, float>(A, Bk, (const float*)nullptr, Ck, 512, 512, K, m0, (nb - 8) * 128);
    else
        hgemm_tile<5, __half, float>(A, Bv, (const float*)nullptr, Cv, 512, 512, K, m0, (nb - 12) * 128);
}

// ---------------- RoPE: fp16 in-place (+ q prescale) -------------------------
__global__ void rope_kernel(__half* __restrict__ q, __half* __restrict__ k)
{
    int row = blockIdx.x;
    int t = row & (Tt - 1);
    const float qscale = 0.08838834764831845f;
    __shared__ float s_sin[64], s_cos[64];
    if (threadIdx.x < 64) {
        float inv = expf(-logf(10000.0f) * (2.0f * threadIdx.x) / 128.0f);
        float ang = (float)t * inv;
        s_sin[threadIdx.x] = sinf(ang);
        s_cos[threadIdx.x] = cosf(ang);
    }
    __syncthreads();
    for (int p = threadIdx.x; p < 512; p += 256) {
        int head = p >> 6, i = p & 63;
        __half* base = q + (size_t)row * 1024 + head * 128;
        float x1 = __half2float(base[i]), x2 = __half2float(base[i + 64]);
        float s = s_sin[i], c = s_cos[i];
        base[i]      = __float2half_rn((x1 * c - x2 * s) * qscale);
        base[i + 64] = __float2half_rn((x2 * c + x1 * s) * qscale);
    }
    for (int p = threadIdx.x; p < 256; p += 256) {
        int head = p >> 6, i = p & 63;
        __half* base = k + (size_t)row * 512 + head * 128;
        float x1 = __half2float(base[i]), x2 = __half2float(base[i + 64]);
        float s = s_sin[i], c = s_cos[i];
        base[i]      = __float2half_rn(x1 * c - x2 * s);
        base[i + 64] = __float2half_rn(x2 * c + x1 * s);
    }
}

// ---------------- attention: 128-q tile, register Q/P, V via trans-ldmatrix --
// smem halves: Ks[2][64*128] @ 0,8192; Vs[2][64*128] @ 16384,24576
#define ATTN_SMEM (32768 * 2)   // 65536 B
__global__ __launch_bounds__(256, 1) void attn_kernel(
    const __half* __restrict__ Q, const __half* __restrict__ K,
    const __half* __restrict__ V, __half* __restrict__ O)
{
    extern __shared__ __half sma[];
    uint32_t smb;
    asm("{ .reg .u64 t; cvta.to.shared.u64 t, %1; cvt.u32.u64 %0, t; }"
        : "=r"(smb) : "l"(sma));

    int qb = blockIdx.x, h = blockIdx.y, b = blockIdx.z;
    int q0 = qb * 128;
    int tid = threadIdx.x, lane = tid & 31, warp = tid >> 5;
    int g = lane >> 2, c = lane & 3;
    int lane16 = lane & 15;
    int hb = (lane & 16) >> 4;
    int m_ = lane >> 3, r_ = lane & 7;
    int tb = (m_ >> 1) * 8 + r_;     // k-row-in-16 for trans V

    // ---- Q fragments (register resident) ----
    const __half* Qg = Q + (size_t)(b * Tt + q0 + 16 * warp) * 1024 + h * 128;
    uint32_t qf[8][4];
    #pragma unroll
    for (int ks = 0; ks < 8; ks++) {
        int kx = 16 * ks + 2 * c;
        qf[ks][0] = *(const uint32_t*)(Qg + (size_t)g * 1024 + kx);
        qf[ks][1] = *(const uint32_t*)(Qg + (size_t)(g + 8) * 1024 + kx);
        qf[ks][2] = *(const uint32_t*)(Qg + (size_t)g * 1024 + kx + 8);
        qf[ks][3] = *(const uint32_t*)(Qg + (size_t)(g + 8) * 1024 + kx + 8);
    }

    float Oacc[16][4];
    #pragma unroll
    for (int i = 0; i < 16; i++)
        #pragma unroll
        for (int j = 0; j < 4; j++) Oacc[i][j] = 0.f;
    float rm0 = -1e30f, rm1 = -1e30f, rl0 = 0.f, rl1 = 0.f;

    int kvh = h & 3;
    const __half* Kg = K + (size_t)b * Tt * 512 + kvh * 128;
    const __half* Vg = V + (size_t)b * Tt * 512 + kvh * 128;

    // V trans-ldmatrix per-lane offsets: d-chunk per bi
    uint32_t voff[8];
    #pragma unroll
    for (int bi = 0; bi < 8; bi++) {
        int dch = bi * 2 + (m_ & 1);
        voff[bi] = (uint32_t)(tb * 128 + ((dch ^ r_) << 3)) * 2u;
    }

    int jlo = (2 * qb - 8 > 0) ? 2 * qb - 8 : 0;
    int jhi = 2 * qb + 1;

    auto load_kv = [&](int s, int k0) {
        #pragma unroll
        for (int p = 0; p < 4; p++) {
            int idx = tid + p * 256;
            int row = idx >> 4, ch = idx & 15;
            CP16(smb + (uint32_t)(s * 8192 + row * 128 + ((ch ^ (row & 7)) << 3)) * 2u,
                 Kg + (size_t)(k0 + row) * 512 + ch * 8);
        }
        #pragma unroll
        for (int p = 0; p < 4; p++) {
            int idx = tid + p * 256;
            int row = idx >> 4, ch = idx & 15;
            CP16(smb + (uint32_t)(16384 + s * 8192 + row * 128 + ((ch ^ (row & 7)) << 3)) * 2u,
                 Vg + (size_t)(k0 + row) * 512 + ch * 8);
        }
    };

    load_kv(0, jlo * 64); CP_COMMIT();

    int qt0 = q0 + 16 * warp + g;
    int qt1 = qt0 + 8;

    for (int jt = jlo; jt <= jhi; jt++) {
        int s = (jt - jlo) & 1;
        int k0 = jt * 64;

        asm volatile("cp.async.wait_group 0;");
        __syncthreads();
        if (jt < jhi) { load_kv(s ^ 1, k0 + 64); }
        CP_COMMIT();

        // ---- S = Q @ K^T ----
        float sacc[8][4];
        #pragma unroll
        for (int i = 0; i < 8; i++)
            #pragma unroll
            for (int j = 0; j < 4; j++) sacc[i][j] = 0.f;
        #pragma unroll
        for (int ks = 0; ks < 8; ks++) {
            int chunk = 2 * ks + hb;
            uint32_t bf[8][2];
            #pragma unroll
            for (int bi = 0; bi < 4; bi++) {
                int colK = bi * 16 + lane16;
                uint32_t r[4];
                ldm_x4(r, smb + (uint32_t)(s * 8192 + colK * 128 +
                                           ((chunk ^ (colK & 7)) << 3)) * 2u);
                bf[2 * bi][0] = r[0]; bf[2 * bi + 1][0] = r[1];
                bf[2 * bi][1] = r[2]; bf[2 * bi + 1][1] = r[3];
            }
            #pragma unroll
            for (int nt = 0; nt < 8; nt++)
                mma_f16(sacc[nt], qf[ks], bf[nt]);
        }

        // ---- softcap + mask + in-warp online softmax ----
        float pm0 = -INFINITY, pm1 = -INFINITY;
        #pragma unroll
        for (int nt = 0; nt < 8; nt++) {
            #pragma unroll
            for (int e = 0; e < 4; e++) {
                int ktg = k0 + nt * 8 + 2 * c + (e & 1);
                int qt = (e >> 1) ? qt1 : qt0;
                float sv = softcap50(sacc[nt][e]);
                bool ok = (ktg <= qt) && (qt - ktg < WINs);
                sv = ok ? sv : -INFINITY;
                sacc[nt][e] = sv;
                if (e >> 1) pm1 = fmaxf(pm1, sv); else pm0 = fmaxf(pm0, sv);
            }
        }
        pm0 = fmaxf(pm0, __shfl_xor_sync(0xffffffffu, pm0, 1));
        pm0 = fmaxf(pm0, __shfl_xor_sync(0xffffffffu, pm0, 2));
        pm1 = fmaxf(pm1, __shfl_xor_sync(0xffffffffu, pm1, 1));
        pm1 = fmaxf(pm1, __shfl_xor_sync(0xffffffffu, pm1, 2));

        float mn0 = fmaxf(rm0, pm0);
        float mn1 = fmaxf(rm1, pm1);
        float al0 = __expf(rm0 - mn0); rm0 = mn0;
        float al1 = __expf(rm1 - mn1); rm1 = mn1;

        uint32_t ph0[8], ph1[8];
        float ps0 = 0.f, ps1 = 0.f;
        #pragma unroll
        for (int nt = 0; nt < 8; nt++) {
            __half2 h0 = __floats2half2_rn(__expf(sacc[nt][0] - mn0),
                                           __expf(sacc[nt][1] - mn0));
            __half2 h1 = __floats2half2_rn(__expf(sacc[nt][2] - mn1),
                                           __expf(sacc[nt][3] - mn1));
            float2 f0 = __half22float2(h0), f1 = __half22float2(h1);
            ps0 += f0.x + f0.y;
            ps1 += f1.x + f1.y;
            ph0[nt] = *(uint32_t*)&h0;
            ph1[nt] = *(uint32_t*)&h1;
        }
        ps0 += __shfl_xor_sync(0xffffffffu, ps0, 1);
        ps0 += __shfl_xor_sync(0xffffffffu, ps0, 2);
        ps1 += __shfl_xor_sync(0xffffffffu, ps1, 1);
        ps1 += __shfl_xor_sync(0xffffffffu, ps1, 2);
        rl0 = rl0 * al0 + ps0;
        rl1 = rl1 * al1 + ps1;

        #pragma unroll
        for (int i = 0; i < 16; i++) {
            Oacc[i][0] *= al0; Oacc[i][1] *= al0;
            Oacc[i][2] *= al1; Oacc[i][3] *= al1;
        }

        // ---- O += P @ V (P from regs, V via trans-ldmatrix from [t][d]) ----
        uint32_t vstage = smb + (uint32_t)(16384 + s * 8192) * 2u;
        #pragma unroll
        for (int ks = 0; ks < 4; ks++) {
            uint32_t af[4] = { ph0[2 * ks], ph1[2 * ks], ph0[2 * ks + 1], ph1[2 * ks + 1] };
            uint32_t krow = (uint32_t)(ks * 16 * 128) * 2u;
            uint32_t vb[16][2];
            #pragma unroll
            for (int bi = 0; bi < 8; bi++) {
                uint32_t r[4];
                ldm_x4_t(r, vstage + krow + voff[bi]);
                vb[2 * bi][0] = r[0]; vb[2 * bi + 1][0] = r[1];
                vb[2 * bi][1] = r[2]; vb[2 * bi + 1][1] = r[3];
            }
            #pragma unroll
            for (int nt = 0; nt < 16; nt++)
                mma_f16(Oacc[nt], af, vb[nt]);
        }
    }

    float li0 = 1.f / rl0, li1 = 1.f / rl1;
    __half* Og = O + (size_t)(b * Tt + q0 + 16 * warp) * 1024 + h * 128;
    #pragma unroll
    for (int nt = 0; nt < 16; nt++) {
        int col = nt * 8 + 2 * c;
        *(__half2*)(Og + (size_t)g * 1024 + col) =
            __floats2half2_rn(Oacc[nt][0] * li0, Oacc[nt][1] * li0);
        *(__half2*)(Og + (size_t)(g + 8) * 1024 + col) =
            __floats2half2_rn(Oacc[nt][2] * li1, Oacc[nt][3] * li1);
    }
}

// ---------------- launch ----------------
extern "C" void kernel_launch(void* const* d_in, const int* in_sizes, int n_in,
                              void* d_out, int out_size)
{
    const float* x        = (const float*)d_in[0];
    const float* q_kernel = (const float*)d_in[1];
    const float* k_kernel = (const float*)d_in[2];
    const float* v_kernel = (const float*)d_in[3];
    const float* out_kern = (const float*)d_in[4];
    const float* attn_sc  = (const float*)d_in[5];
    const float* mlp_sc   = (const float*)d_in[6];
    const float* gate_k   = (const float*)d_in[7];
    const float* up_k     = (const float*)d_in[8];
    const float* down_k   = (const float*)d_in[9];
    float* out = (float*)d_out;

    __half *p_h, *p_attnh, *p_act, *p_qh, *p_kh, *p_vh, *p_gateh;
    float *p_x2;
    __half *w_q, *w_k, *w_v, *w_o, *w_g, *w_u, *w_d;
    cudaGetSymbolAddress((void**)&p_h,     g_h);
    cudaGetSymbolAddress((void**)&p_qh,    g_qh);
    cudaGetSymbolAddress((void**)&p_kh,    g_kh);
    cudaGetSymbolAddress((void**)&p_vh,    g_vh);
    cudaGetSymbolAddress((void**)&p_attnh, g_attnh);
    cudaGetSymbolAddress((void**)&p_x2,    g_x2);
    cudaGetSymbolAddress((void**)&p_gateh, g_gateh);
    cudaGetSymbolAddress((void**)&p_act,   g_act);
    cudaGetSymbolAddress((void**)&w_q,     g_wq);
    cudaGetSymbolAddress((void**)&w_k,     g_wk);
    cudaGetSymbolAddress((void**)&w_v,     g_wv);
    cudaGetSymbolAddress((void**)&w_o,     g_wo);
    cudaGetSymbolAddress((void**)&w_g,     g_wg);
    cudaGetSymbolAddress((void**)&w_u,     g_wu);
    cudaGetSymbolAddress((void**)&w_d,     g_wd);

    cudaFuncSetAttribute(attn_kernel, cudaFuncAttributeMaxDynamicSharedMemorySize, ATTN_SMEM);
    cudaFuncSetAttribute(qkv_h_kernel, cudaFuncAttributeMaxDynamicSharedMemorySize, HGEMM_SMEM);
    cudaFuncSetAttribute((hgemm_kernel<1, float, float>),   cudaFuncAttributeMaxDynamicSharedMemorySize, HGEMM_SMEM);
    cudaFuncSetAttribute((hgemm_kernel<3, __half, float>),  cudaFuncAttributeMaxDynamicSharedMemorySize, HGEMM_SMEM);
    cudaFuncSetAttribute((hgemm_kernel<4, __half, __half>), cudaFuncAttributeMaxDynamicSharedMemorySize, HGEMM_SMEM);

    // 0) weights: streaming fp32 -> fp16, native [K][N] layout
    cvt_kernel<<<1024, 256>>>((const float4*)q_kernel, w_q, 262144);
    cvt_kernel<<<512,  256>>>((const float4*)k_kernel, w_k, 131072);
    cvt_kernel<<<512,  256>>>((const float4*)v_kernel, w_v, 131072);
    cvt_kernel<<<1024, 256>>>((const float4*)out_kern, w_o, 262144);
    cvt_kernel<<<4096, 256>>>((const float4*)gate_k,   w_g, 1048576);
    cvt_kernel<<<4096, 256>>>((const float4*)up_k,     w_u, 1048576);
    cvt_kernel<<<4096, 256>>>((const float4*)down_k,   w_d, 1048576);

    // 1) h = rmsnorm(x, attn_scale) -> fp16
    rmsnorm_h_kernel<<<Mrows, 256>>>(x, attn_sc, p_h);
    // 2) fused q/k/v projections -> fp16
    qkv_h_kernel<<<dim3(16, 32), 256, HGEMM_SMEM>>>(p_h, w_q, w_k, w_v, p_qh, p_kh, p_vh, 1024);
    // 3) rope in-place on fp16 q (prescaled) and k
    rope_kernel<<<Mrows, 256>>>(p_qh, p_kh);
    // 4) attention
    attn_kernel<<<dim3(Tt / 128, Hh, Bb), 256, ATTN_SMEM>>>(p_qh, p_kh, p_vh, p_attnh);
    // 5) out projection + residual
    hgemm_kernel<1, float, float><<<dim3(8, 32), 256, HGEMM_SMEM>>>(p_attnh, w_o, x, p_x2, 1024, 1024);
    // 6) h = rmsnorm(x2, mlp_scale) -> fp16
    rmsnorm_h_kernel<<<Mrows, 256>>>(p_x2, mlp_sc, p_h);
    // 7) gate (silu, fp16), then up * gate -> fp16 act
    hgemm_kernel<3, __half, float><<<dim3(32, 32), 256, HGEMM_SMEM>>>(p_h, w_g, (const float*)nullptr, p_gateh, HIDm, 1024);
    hgemm_kernel<4, __half, __half><<<dim3(32, 32), 256, HGEMM_SMEM>>>(p_h, w_u, p_gateh, p_act, HIDm, 1024);
    // 8) down + residual -> out
    hgemm_kernel<1, float, float><<<dim3(8, 32), 256, HGEMM_SMEM>>>(p_act, w_d, p_x2, out, 1024, HIDm);
}